// round 2
// baseline (speedup 1.0000x reference)
#include <cuda_runtime.h>
#include <math.h>

#define BATCH 4
#define NQ 2048
#define NK 2048
#define DM 1024
#define NH 16
#define HD 64

// Scratch (static __device__ arrays are the allowed scratch mechanism)
__device__ float g_Q[BATCH * NQ * DM];
__device__ float g_K[BATCH * NK * DM];
__device__ float g_V[BATCH * NK * DM];
__device__ float g_O[BATCH * NQ * DM];

// ---------------------------------------------------------------------------
// SGEMM: C[M,N] = A[M,K] @ B[K,N] (+ bias broadcast over rows, optional)
// BM=BN=128, BK=16, 256 threads, 8x8 per thread.
// ---------------------------------------------------------------------------
#define BM 128
#define BN 128
#define BK 16
#define TM 8
#define TN 8

__global__ __launch_bounds__(256) void gemm_kernel(
    const float* __restrict__ A, const float* __restrict__ Bm,
    const float* __restrict__ bias, float* __restrict__ C,
    int M, int N, int K)
{
    __shared__ float As[BK][BM];      // transposed A tile
    __shared__ float Bs[BK][BN];

    const int tid = threadIdx.x;
    const int bm = blockIdx.y * BM;
    const int bn = blockIdx.x * BN;

    const int tcol = tid % (BN / TN);   // 0..15
    const int trow = tid / (BN / TN);   // 0..15

    float acc[TM][TN];
#pragma unroll
    for (int i = 0; i < TM; i++)
#pragma unroll
        for (int j = 0; j < TN; j++) acc[i][j] = 0.0f;

    for (int k0 = 0; k0 < K; k0 += BK) {
        // Load A tile: BM x BK = 2048 floats = 512 float4, 2 per thread
#pragma unroll
        for (int i = 0; i < 2; i++) {
            int idx = tid + i * 256;
            int r = idx / (BK / 4);        // 0..127
            int c4 = idx % (BK / 4);       // 0..3
            float4 v = *(const float4*)&A[(size_t)(bm + r) * K + k0 + c4 * 4];
            As[c4 * 4 + 0][r] = v.x;
            As[c4 * 4 + 1][r] = v.y;
            As[c4 * 4 + 2][r] = v.z;
            As[c4 * 4 + 3][r] = v.w;
        }
        // Load B tile: BK x BN = 2048 floats = 512 float4, 2 per thread
#pragma unroll
        for (int i = 0; i < 2; i++) {
            int idx = tid + i * 256;
            int r = idx / (BN / 4);        // 0..15
            int c4 = idx % (BN / 4);       // 0..31
            *(float4*)&Bs[r][c4 * 4] =
                *(const float4*)&Bm[(size_t)(k0 + r) * N + bn + c4 * 4];
        }
        __syncthreads();

#pragma unroll
        for (int k = 0; k < BK; k++) {
            float ra[TM], rb[TN];
#pragma unroll
            for (int i = 0; i < TM; i += 4) {
                float4 v = *(const float4*)&As[k][trow * TM + i];
                ra[i] = v.x; ra[i + 1] = v.y; ra[i + 2] = v.z; ra[i + 3] = v.w;
            }
#pragma unroll
            for (int j = 0; j < TN; j += 4) {
                float4 v = *(const float4*)&Bs[k][tcol * TN + j];
                rb[j] = v.x; rb[j + 1] = v.y; rb[j + 2] = v.z; rb[j + 3] = v.w;
            }
#pragma unroll
            for (int i = 0; i < TM; i++)
#pragma unroll
                for (int j = 0; j < TN; j++)
                    acc[i][j] += ra[i] * rb[j];
        }
        __syncthreads();
    }

    // Epilogue
#pragma unroll
    for (int i = 0; i < TM; i++) {
        int r = bm + trow * TM + i;
#pragma unroll
        for (int j = 0; j < TN; j += 4) {
            int c = bn + tcol * TN + j;
            float4 v;
            v.x = acc[i][j + 0];
            v.y = acc[i][j + 1];
            v.z = acc[i][j + 2];
            v.w = acc[i][j + 3];
            if (bias) {
                v.x += bias[c + 0];
                v.y += bias[c + 1];
                v.z += bias[c + 2];
                v.w += bias[c + 3];
            }
            *(float4*)&C[(size_t)r * N + c] = v;
        }
    }
}

// ---------------------------------------------------------------------------
// Flash attention: one CTA per (q-tile of 64, head, batch).
// Br = Bc = 64, hd = 64. 256 threads in 16x16 layout, 4x4 per thread.
// ---------------------------------------------------------------------------
#define SQ_STRIDE 68
#define SKT_STRIDE 68
#define SP_STRIDE 68
#define SV_STRIDE 64

#define SMEM_ATTN ((64 * SQ_STRIDE + 64 * SKT_STRIDE + 64 * SV_STRIDE + 64 * SP_STRIDE) * 4)

__global__ __launch_bounds__(256) void attn_kernel(
    const float* __restrict__ Qp, const float* __restrict__ Kp,
    const float* __restrict__ Vp, float* __restrict__ Op)
{
    extern __shared__ float sm[];
    float* sQ  = sm;                              // [64][68]  (row, d)  pre-scaled
    float* sKT = sQ + 64 * SQ_STRIDE;             // [64][68]  (d, key)
    float* sV  = sKT + 64 * SKT_STRIDE;           // [64][64]  (key, d)
    float* sP  = sV + 64 * SV_STRIDE;             // [64][68]  (row, key)

    const int tid = threadIdx.x;
    const int tx = tid % 16;
    const int ty = tid / 16;
    const int qt = blockIdx.x;
    const int h  = blockIdx.y;
    const int b  = blockIdx.z;
    const float scale = 0.03125f;  // 1/sqrt(1024)

    const float* Qbase = Qp + ((size_t)b * NQ + qt * 64) * DM + h * HD;

    // Load Q tile (scaled): 64 rows x 16 float4
    for (int i = tid; i < 64 * 16; i += 256) {
        int r = i / 16, c4 = i % 16;
        float4 v = *(const float4*)&Qbase[(size_t)r * DM + c4 * 4];
        float* d = &sQ[r * SQ_STRIDE + c4 * 4];
        d[0] = v.x * scale; d[1] = v.y * scale; d[2] = v.z * scale; d[3] = v.w * scale;
    }

    float m[4], l[4], acc[4][4];
#pragma unroll
    for (int i = 0; i < 4; i++) {
        m[i] = -1e30f; l[i] = 0.0f;
#pragma unroll
        for (int j = 0; j < 4; j++) acc[i][j] = 0.0f;
    }

    for (int kt = 0; kt < NK / 64; kt++) {
        const float* Kbase = Kp + ((size_t)b * NK + kt * 64) * DM + h * HD;
        const float* Vbase = Vp + ((size_t)b * NK + kt * 64) * DM + h * HD;

        __syncthreads();  // previous iteration's reads of sKT/sV/sP done

        // Load K tile transposed, V tile row-major
        for (int i = tid; i < 64 * 16; i += 256) {
            int r = i / 16, c4 = i % 16;
            float4 v = *(const float4*)&Kbase[(size_t)r * DM + c4 * 4];
            sKT[(c4 * 4 + 0) * SKT_STRIDE + r] = v.x;
            sKT[(c4 * 4 + 1) * SKT_STRIDE + r] = v.y;
            sKT[(c4 * 4 + 2) * SKT_STRIDE + r] = v.z;
            sKT[(c4 * 4 + 3) * SKT_STRIDE + r] = v.w;
            float4 w = *(const float4*)&Vbase[(size_t)r * DM + c4 * 4];
            *(float4*)&sV[r * SV_STRIDE + c4 * 4] = w;
        }
        __syncthreads();

        // S = Q @ K^T  (4x4 per thread)
        float s[4][4];
#pragma unroll
        for (int i = 0; i < 4; i++)
#pragma unroll
            for (int j = 0; j < 4; j++) s[i][j] = 0.0f;

#pragma unroll 4
        for (int kk = 0; kk < 64; kk++) {
            float4 rb = *(const float4*)&sKT[kk * SKT_STRIDE + tx * 4];
            float ra0 = sQ[(ty * 4 + 0) * SQ_STRIDE + kk];
            float ra1 = sQ[(ty * 4 + 1) * SQ_STRIDE + kk];
            float ra2 = sQ[(ty * 4 + 2) * SQ_STRIDE + kk];
            float ra3 = sQ[(ty * 4 + 3) * SQ_STRIDE + kk];
            s[0][0] += ra0 * rb.x; s[0][1] += ra0 * rb.y; s[0][2] += ra0 * rb.z; s[0][3] += ra0 * rb.w;
            s[1][0] += ra1 * rb.x; s[1][1] += ra1 * rb.y; s[1][2] += ra1 * rb.z; s[1][3] += ra1 * rb.w;
            s[2][0] += ra2 * rb.x; s[2][1] += ra2 * rb.y; s[2][2] += ra2 * rb.z; s[2][3] += ra2 * rb.w;
            s[3][0] += ra3 * rb.x; s[3][1] += ra3 * rb.y; s[3][2] += ra3 * rb.z; s[3][3] += ra3 * rb.w;
        }

        // Online softmax update (row reductions over the 16 tx lanes)
#pragma unroll
        for (int i = 0; i < 4; i++) {
            float mt = fmaxf(fmaxf(s[i][0], s[i][1]), fmaxf(s[i][2], s[i][3]));
#pragma unroll
            for (int o = 8; o >= 1; o >>= 1)
                mt = fmaxf(mt, __shfl_xor_sync(0xffffffffu, mt, o));
            float mn = fmaxf(m[i], mt);
            float alpha = __expf(m[i] - mn);
            float p0 = __expf(s[i][0] - mn);
            float p1 = __expf(s[i][1] - mn);
            float p2 = __expf(s[i][2] - mn);
            float p3 = __expf(s[i][3] - mn);
            float rs = p0 + p1 + p2 + p3;
#pragma unroll
            for (int o = 8; o >= 1; o >>= 1)
                rs += __shfl_xor_sync(0xffffffffu, rs, o);
            l[i] = l[i] * alpha + rs;
            m[i] = mn;
#pragma unroll
            for (int j = 0; j < 4; j++) acc[i][j] *= alpha;
            float4 pv; pv.x = p0; pv.y = p1; pv.z = p2; pv.w = p3;
            *(float4*)&sP[(ty * 4 + i) * SP_STRIDE + tx * 4] = pv;
        }
        __syncthreads();

        // acc += P @ V  (4 rows x 4 d-cols per thread)
#pragma unroll 4
        for (int kk = 0; kk < 64; kk++) {
            float4 rb = *(const float4*)&sV[kk * SV_STRIDE + tx * 4];
            float ra0 = sP[(ty * 4 + 0) * SP_STRIDE + kk];
            float ra1 = sP[(ty * 4 + 1) * SP_STRIDE + kk];
            float ra2 = sP[(ty * 4 + 2) * SP_STRIDE + kk];
            float ra3 = sP[(ty * 4 + 3) * SP_STRIDE + kk];
            acc[0][0] += ra0 * rb.x; acc[0][1] += ra0 * rb.y; acc[0][2] += ra0 * rb.z; acc[0][3] += ra0 * rb.w;
            acc[1][0] += ra1 * rb.x; acc[1][1] += ra1 * rb.y; acc[1][2] += ra1 * rb.z; acc[1][3] += ra1 * rb.w;
            acc[2][0] += ra2 * rb.x; acc[2][1] += ra2 * rb.y; acc[2][2] += ra2 * rb.z; acc[2][3] += ra2 * rb.w;
            acc[3][0] += ra3 * rb.x; acc[3][1] += ra3 * rb.y; acc[3][2] += ra3 * rb.z; acc[3][3] += ra3 * rb.w;
        }
    }

    // Epilogue: O = acc / l, write directly to [b, n, h*64 + d] layout
#pragma unroll
    for (int i = 0; i < 4; i++) {
        float inv = 1.0f / l[i];
        int row = qt * 64 + ty * 4 + i;
        float4 o;
        o.x = acc[i][0] * inv;
        o.y = acc[i][1] * inv;
        o.z = acc[i][2] * inv;
        o.w = acc[i][3] * inv;
        *(float4*)&Op[((size_t)b * NQ + row) * DM + h * HD + tx * 4] = o;
    }
}

// ---------------------------------------------------------------------------
// Launch
// ---------------------------------------------------------------------------
extern "C" void kernel_launch(void* const* d_in, const int* in_sizes, int n_in,
                              void* d_out, int out_size)
{
    const float* queries = (const float*)d_in[0];
    const float* keys    = (const float*)d_in[1];
    const float* values  = (const float*)d_in[2];
    const float* Wq      = (const float*)d_in[3];
    const float* Wk      = (const float*)d_in[4];
    const float* Wv      = (const float*)d_in[5];
    const float* Wo      = (const float*)d_in[6];
    const float* bo      = (const float*)d_in[7];
    float* out           = (float*)d_out;

    float *Qp, *Kp, *Vp, *Op;
    cudaGetSymbolAddress((void**)&Qp, g_Q);
    cudaGetSymbolAddress((void**)&Kp, g_K);
    cudaGetSymbolAddress((void**)&Vp, g_V);
    cudaGetSymbolAddress((void**)&Op, g_O);

    static bool attr_set = false;
    if (!attr_set) {
        cudaFuncSetAttribute(attn_kernel,
                             cudaFuncAttributeMaxDynamicSharedMemorySize, SMEM_ATTN);
        attr_set = true;
    }

    const int M = BATCH * NQ;  // 8192

    dim3 ggrid(DM / BN, M / BM);  // (8, 64)
    gemm_kernel<<<ggrid, 256>>>(queries, Wq, nullptr, Qp, M, DM, DM);
    gemm_kernel<<<ggrid, 256>>>(keys,    Wk, nullptr, Kp, M, DM, DM);
    gemm_kernel<<<ggrid, 256>>>(values,  Wv, nullptr, Vp, M, DM, DM);

    dim3 agrid(NQ / 64, NH, BATCH);  // (32, 16, 4)
    attn_kernel<<<agrid, 256, SMEM_ATTN>>>(Qp, Kp, Vp, Op);

    gemm_kernel<<<ggrid, 256>>>(Op, Wo, bo, out, M, DM, DM);
}

// round 4
// speedup vs baseline: 1.4441x; 1.4441x over previous
#include <cuda_runtime.h>
#include <math.h>
#include <stdint.h>

#define BATCH 4
#define NQ 2048
#define NK 2048
#define DM 1024
#define NH 16
#define HD 64

// Scratch
__device__ float g_Q[BATCH * NQ * DM];
__device__ float g_K[BATCH * NK * DM];
__device__ float g_V[BATCH * NK * DM];
__device__ float g_O[BATCH * NQ * DM];
__device__ float g_WT[4 * DM * DM];   // transposed + tf32(RNA)-rounded weights

__device__ __forceinline__ float to_tf32(float x) {
    float r;
    asm("cvt.rna.tf32.f32 %0, %1;" : "=f"(r) : "f"(x));
    return r;
}

__device__ __forceinline__ void mma_tf32(float* c, const uint32_t* a, const uint32_t* b) {
    asm volatile(
        "mma.sync.aligned.m16n8k8.row.col.f32.tf32.tf32.f32 "
        "{%0,%1,%2,%3}, {%4,%5,%6,%7}, {%8,%9}, {%0,%1,%2,%3};"
        : "+f"(c[0]), "+f"(c[1]), "+f"(c[2]), "+f"(c[3])
        : "r"(a[0]), "r"(a[1]), "r"(a[2]), "r"(a[3]), "r"(b[0]), "r"(b[1]));
}

// ---------------------------------------------------------------------------
// Weight transpose (+ tf32 RNA rounding): W[K][N] (1024x1024) -> WT[N][K]
// ---------------------------------------------------------------------------
__global__ void transpose_tf32(const float* __restrict__ W, float* __restrict__ WT) {
    __shared__ float t[32][33];
    int bx = blockIdx.x * 32, by = blockIdx.y * 32;
    for (int j = threadIdx.y; j < 32; j += 8)
        t[j][threadIdx.x] = W[(size_t)(by + j) * DM + bx + threadIdx.x];
    __syncthreads();
    for (int j = threadIdx.y; j < 32; j += 8)
        WT[(size_t)(bx + j) * DM + by + threadIdx.x] = to_tf32(t[threadIdx.x][j]);
}

// ---------------------------------------------------------------------------
// TF32 tensor-core GEMM via mma.sync: C[M,N] = A[M,K] @ BT^T (+bias)
// A row-major fp32 (RNA-rounded while staging), BT row-major [N][K] pre-rounded.
// CTA tile 128x128, BK=32, 8 warps; warp tile 64(m) x 32(n).
// ---------------------------------------------------------------------------
#define GBM 128
#define GBN 128
#define GBK 32
#define SSTRIDE 36   // padded floats per row: bank = (4*row + col) % 32, conflict-free

__global__ __launch_bounds__(256) void gemm_mma(
    const float* __restrict__ A, const float* __restrict__ BT,
    const float* __restrict__ bias, float* __restrict__ C,
    int M, int N, int K)
{
    __shared__ float sA[GBM * SSTRIDE];
    __shared__ float sB[GBN * SSTRIDE];

    const int tid = threadIdx.x;
    const int wid = tid >> 5;
    const int lane = tid & 31;
    const int gID = lane >> 2;    // 0..7
    const int ig  = lane & 3;     // 0..3

    const int warp_m = wid >> 2;  // 0..1  (64 rows each)
    const int warp_n = wid & 3;   // 0..3  (32 cols each)

    const int bm = blockIdx.y * GBM;
    const int bn = blockIdx.x * GBN;

    float acc[4][4][4];           // [mt][nt][4]
#pragma unroll
    for (int i = 0; i < 4; i++)
#pragma unroll
        for (int j = 0; j < 4; j++)
#pragma unroll
            for (int v = 0; v < 4; v++) acc[i][j][v] = 0.0f;

    for (int k0 = 0; k0 < K; k0 += GBK) {
        // Stage A and B tiles: 128 rows x 32 floats each = 1024 float4 per tile
#pragma unroll
        for (int i = 0; i < 4; i++) {
            int idx = tid + i * 256;
            int r = idx >> 3;            // 0..127
            int c4 = idx & 7;            // 0..7
            float4 va = *(const float4*)&A[(size_t)(bm + r) * K + k0 + c4 * 4];
            va.x = to_tf32(va.x); va.y = to_tf32(va.y);
            va.z = to_tf32(va.z); va.w = to_tf32(va.w);
            *(float4*)&sA[r * SSTRIDE + c4 * 4] = va;
            float4 vb = *(const float4*)&BT[(size_t)(bn + r) * K + k0 + c4 * 4];
            *(float4*)&sB[r * SSTRIDE + c4 * 4] = vb;
        }
        __syncthreads();

#pragma unroll
        for (int kk = 0; kk < GBK; kk += 8) {
            uint32_t afrag[4][4];
#pragma unroll
            for (int mt = 0; mt < 4; mt++) {
                int r0 = warp_m * 64 + mt * 16 + gID;
                afrag[mt][0] = __float_as_uint(sA[r0 * SSTRIDE + kk + ig]);
                afrag[mt][1] = __float_as_uint(sA[(r0 + 8) * SSTRIDE + kk + ig]);
                afrag[mt][2] = __float_as_uint(sA[r0 * SSTRIDE + kk + ig + 4]);
                afrag[mt][3] = __float_as_uint(sA[(r0 + 8) * SSTRIDE + kk + ig + 4]);
            }
            uint32_t bfrag[4][2];
#pragma unroll
            for (int nt = 0; nt < 4; nt++) {
                int n0 = warp_n * 32 + nt * 8 + gID;
                bfrag[nt][0] = __float_as_uint(sB[n0 * SSTRIDE + kk + ig]);
                bfrag[nt][1] = __float_as_uint(sB[n0 * SSTRIDE + kk + ig + 4]);
            }
#pragma unroll
            for (int mt = 0; mt < 4; mt++)
#pragma unroll
                for (int nt = 0; nt < 4; nt++)
                    mma_tf32(acc[mt][nt], afrag[mt], bfrag[nt]);
        }
        __syncthreads();
    }

    // Epilogue: accumulator layout m16n8 -> gmem
#pragma unroll
    for (int mt = 0; mt < 4; mt++) {
#pragma unroll
        for (int nt = 0; nt < 4; nt++) {
            int row = bm + warp_m * 64 + mt * 16 + gID;
            int col = bn + warp_n * 32 + nt * 8 + ig * 2;
            float2 v0, v1;
            v0.x = acc[mt][nt][0]; v0.y = acc[mt][nt][1];
            v1.x = acc[mt][nt][2]; v1.y = acc[mt][nt][3];
            if (bias) {
                float b0 = bias[col], b1 = bias[col + 1];
                v0.x += b0; v0.y += b1;
                v1.x += b0; v1.y += b1;
            }
            *(float2*)&C[(size_t)row * N + col] = v0;
            *(float2*)&C[(size_t)(row + 8) * N + col] = v1;
        }
    }
}

// ---------------------------------------------------------------------------
// Flash attention (SIMT fp32): one CTA per (q-tile 64, head, batch)
// ---------------------------------------------------------------------------
#define SQ_STRIDE 68
#define SKT_STRIDE 68
#define SP_STRIDE 68
#define SV_STRIDE 64
#define SMEM_ATTN ((64 * SQ_STRIDE + 64 * SKT_STRIDE + 64 * SV_STRIDE + 64 * SP_STRIDE) * 4)

__global__ __launch_bounds__(256) void attn_kernel(
    const float* __restrict__ Qp, const float* __restrict__ Kp,
    const float* __restrict__ Vp, float* __restrict__ Op)
{
    extern __shared__ float sm[];
    float* sQ  = sm;
    float* sKT = sQ + 64 * SQ_STRIDE;
    float* sV  = sKT + 64 * SKT_STRIDE;
    float* sP  = sV + 64 * SV_STRIDE;

    const int tid = threadIdx.x;
    const int tx = tid % 16;
    const int ty = tid / 16;
    const int qt = blockIdx.x;
    const int h  = blockIdx.y;
    const int b  = blockIdx.z;
    const float scale = 0.03125f;

    const float* Qbase = Qp + ((size_t)b * NQ + qt * 64) * DM + h * HD;

    for (int i = tid; i < 64 * 16; i += 256) {
        int r = i / 16, c4 = i % 16;
        float4 v = *(const float4*)&Qbase[(size_t)r * DM + c4 * 4];
        float* d = &sQ[r * SQ_STRIDE + c4 * 4];
        d[0] = v.x * scale; d[1] = v.y * scale; d[2] = v.z * scale; d[3] = v.w * scale;
    }

    float m[4], l[4], acc[4][4];
#pragma unroll
    for (int i = 0; i < 4; i++) {
        m[i] = -1e30f; l[i] = 0.0f;
#pragma unroll
        for (int j = 0; j < 4; j++) acc[i][j] = 0.0f;
    }

    for (int kt = 0; kt < NK / 64; kt++) {
        const float* Kbase = Kp + ((size_t)b * NK + kt * 64) * DM + h * HD;
        const float* Vbase = Vp + ((size_t)b * NK + kt * 64) * DM + h * HD;

        __syncthreads();
        for (int i = tid; i < 64 * 16; i += 256) {
            int r = i / 16, c4 = i % 16;
            float4 v = *(const float4*)&Kbase[(size_t)r * DM + c4 * 4];
            sKT[(c4 * 4 + 0) * SKT_STRIDE + r] = v.x;
            sKT[(c4 * 4 + 1) * SKT_STRIDE + r] = v.y;
            sKT[(c4 * 4 + 2) * SKT_STRIDE + r] = v.z;
            sKT[(c4 * 4 + 3) * SKT_STRIDE + r] = v.w;
            float4 w = *(const float4*)&Vbase[(size_t)r * DM + c4 * 4];
            *(float4*)&sV[r * SV_STRIDE + c4 * 4] = w;
        }
        __syncthreads();

        float s[4][4];
#pragma unroll
        for (int i = 0; i < 4; i++)
#pragma unroll
            for (int j = 0; j < 4; j++) s[i][j] = 0.0f;

#pragma unroll 4
        for (int kk = 0; kk < 64; kk++) {
            float4 rb = *(const float4*)&sKT[kk * SKT_STRIDE + tx * 4];
            float ra0 = sQ[(ty * 4 + 0) * SQ_STRIDE + kk];
            float ra1 = sQ[(ty * 4 + 1) * SQ_STRIDE + kk];
            float ra2 = sQ[(ty * 4 + 2) * SQ_STRIDE + kk];
            float ra3 = sQ[(ty * 4 + 3) * SQ_STRIDE + kk];
            s[0][0] += ra0 * rb.x; s[0][1] += ra0 * rb.y; s[0][2] += ra0 * rb.z; s[0][3] += ra0 * rb.w;
            s[1][0] += ra1 * rb.x; s[1][1] += ra1 * rb.y; s[1][2] += ra1 * rb.z; s[1][3] += ra1 * rb.w;
            s[2][0] += ra2 * rb.x; s[2][1] += ra2 * rb.y; s[2][2] += ra2 * rb.z; s[2][3] += ra2 * rb.w;
            s[3][0] += ra3 * rb.x; s[3][1] += ra3 * rb.y; s[3][2] += ra3 * rb.z; s[3][3] += ra3 * rb.w;
        }

#pragma unroll
        for (int i = 0; i < 4; i++) {
            float mt = fmaxf(fmaxf(s[i][0], s[i][1]), fmaxf(s[i][2], s[i][3]));
#pragma unroll
            for (int o = 8; o >= 1; o >>= 1)
                mt = fmaxf(mt, __shfl_xor_sync(0xffffffffu, mt, o));
            float mn = fmaxf(m[i], mt);
            float alpha = __expf(m[i] - mn);
            float p0 = __expf(s[i][0] - mn);
            float p1 = __expf(s[i][1] - mn);
            float p2 = __expf(s[i][2] - mn);
            float p3 = __expf(s[i][3] - mn);
            float rs = p0 + p1 + p2 + p3;
#pragma unroll
            for (int o = 8; o >= 1; o >>= 1)
                rs += __shfl_xor_sync(0xffffffffu, rs, o);
            l[i] = l[i] * alpha + rs;
            m[i] = mn;
#pragma unroll
            for (int j = 0; j < 4; j++) acc[i][j] *= alpha;
            float4 pv; pv.x = p0; pv.y = p1; pv.z = p2; pv.w = p3;
            *(float4*)&sP[(ty * 4 + i) * SP_STRIDE + tx * 4] = pv;
        }
        __syncthreads();

#pragma unroll 4
        for (int kk = 0; kk < 64; kk++) {
            float4 rb = *(const float4*)&sV[kk * SV_STRIDE + tx * 4];
            float ra0 = sP[(ty * 4 + 0) * SP_STRIDE + kk];
            float ra1 = sP[(ty * 4 + 1) * SP_STRIDE + kk];
            float ra2 = sP[(ty * 4 + 2) * SP_STRIDE + kk];
            float ra3 = sP[(ty * 4 + 3) * SP_STRIDE + kk];
            acc[0][0] += ra0 * rb.x; acc[0][1] += ra0 * rb.y; acc[0][2] += ra0 * rb.z; acc[0][3] += ra0 * rb.w;
            acc[1][0] += ra1 * rb.x; acc[1][1] += ra1 * rb.y; acc[1][2] += ra1 * rb.z; acc[1][3] += ra1 * rb.w;
            acc[2][0] += ra2 * rb.x; acc[2][1] += ra2 * rb.y; acc[2][2] += ra2 * rb.z; acc[2][3] += ra2 * rb.w;
            acc[3][0] += ra3 * rb.x; acc[3][1] += ra3 * rb.y; acc[3][2] += ra3 * rb.z; acc[3][3] += ra3 * rb.w;
        }
    }

#pragma unroll
    for (int i = 0; i < 4; i++) {
        float inv = 1.0f / l[i];
        int row = qt * 64 + ty * 4 + i;
        float4 o;
        o.x = acc[i][0] * inv;
        o.y = acc[i][1] * inv;
        o.z = acc[i][2] * inv;
        o.w = acc[i][3] * inv;
        *(float4*)&Op[((size_t)b * NQ + row) * DM + h * HD + tx * 4] = o;
    }
}

// ---------------------------------------------------------------------------
// Launch
// ---------------------------------------------------------------------------
extern "C" void kernel_launch(void* const* d_in, const int* in_sizes, int n_in,
                              void* d_out, int out_size)
{
    const float* queries = (const float*)d_in[0];
    const float* keys    = (const float*)d_in[1];
    const float* values  = (const float*)d_in[2];
    const float* Wq      = (const float*)d_in[3];
    const float* Wk      = (const float*)d_in[4];
    const float* Wv      = (const float*)d_in[5];
    const float* Wo      = (const float*)d_in[6];
    const float* bo      = (const float*)d_in[7];
    float* out           = (float*)d_out;

    float *Qp, *Kp, *Vp, *Op, *WT;
    cudaGetSymbolAddress((void**)&Qp, g_Q);
    cudaGetSymbolAddress((void**)&Kp, g_K);
    cudaGetSymbolAddress((void**)&Vp, g_V);
    cudaGetSymbolAddress((void**)&Op, g_O);
    cudaGetSymbolAddress((void**)&WT, g_WT);

    static bool attr_set = false;
    if (!attr_set) {
        cudaFuncSetAttribute(attn_kernel,
                             cudaFuncAttributeMaxDynamicSharedMemorySize, SMEM_ATTN);
        attr_set = true;
    }

    const int M = BATCH * NQ;  // 8192
    const size_t WSZ = (size_t)DM * DM;

    dim3 tgrid(DM / 32, DM / 32), tblk(32, 8);
    transpose_tf32<<<tgrid, tblk>>>(Wq, WT + 0 * WSZ);
    transpose_tf32<<<tgrid, tblk>>>(Wk, WT + 1 * WSZ);
    transpose_tf32<<<tgrid, tblk>>>(Wv, WT + 2 * WSZ);
    transpose_tf32<<<tgrid, tblk>>>(Wo, WT + 3 * WSZ);

    dim3 ggrid(DM / GBN, M / GBM);  // (8, 64)
    gemm_mma<<<ggrid, 256>>>(queries, WT + 0 * WSZ, nullptr, Qp, M, DM, DM);
    gemm_mma<<<ggrid, 256>>>(keys,    WT + 1 * WSZ, nullptr, Kp, M, DM, DM);
    gemm_mma<<<ggrid, 256>>>(values,  WT + 2 * WSZ, nullptr, Vp, M, DM, DM);

    dim3 agrid(NQ / 64, NH, BATCH);  // (32, 16, 4)
    attn_kernel<<<agrid, 256, SMEM_ATTN>>>(Qp, Kp, Vp, Op);

    gemm_mma<<<ggrid, 256>>>(Op, WT + 3 * WSZ, bo, out, M, DM, DM);
}

// round 5
// speedup vs baseline: 3.0061x; 2.0817x over previous
#include <cuda_runtime.h>
#include <math.h>
#include <stdint.h>

#define BATCH 4
#define NQ 2048
#define NK 2048
#define DM 1024
#define NH 16
#define HD 64

// Scratch
__device__ float g_Q[BATCH * NQ * DM];
__device__ float g_K[BATCH * NK * DM];
__device__ float g_V[BATCH * NK * DM];
__device__ float g_O[BATCH * NQ * DM];
__device__ float g_WT[4 * DM * DM];   // transposed + tf32(RNA)-rounded weights

__device__ __forceinline__ float to_tf32(float x) {
    float r;
    asm("cvt.rna.tf32.f32 %0, %1;" : "=f"(r) : "f"(x));
    return r;
}

__device__ __forceinline__ float ex2(float x) {
    float r;
    asm("ex2.approx.ftz.f32 %0, %1;" : "=f"(r) : "f"(x));
    return r;
}

__device__ __forceinline__ void mma_tf32(float* c, const uint32_t* a, const uint32_t* b) {
    asm volatile(
        "mma.sync.aligned.m16n8k8.row.col.f32.tf32.tf32.f32 "
        "{%0,%1,%2,%3}, {%4,%5,%6,%7}, {%8,%9}, {%0,%1,%2,%3};"
        : "+f"(c[0]), "+f"(c[1]), "+f"(c[2]), "+f"(c[3])
        : "r"(a[0]), "r"(a[1]), "r"(a[2]), "r"(a[3]), "r"(b[0]), "r"(b[1]));
}

// ---------------------------------------------------------------------------
// Weight transpose (+ tf32 RNA rounding): W[K][N] (1024x1024) -> WT[N][K]
// ---------------------------------------------------------------------------
__global__ void transpose_tf32(const float* __restrict__ W, float* __restrict__ WT) {
    __shared__ float t[32][33];
    int bx = blockIdx.x * 32, by = blockIdx.y * 32;
    for (int j = threadIdx.y; j < 32; j += 8)
        t[j][threadIdx.x] = W[(size_t)(by + j) * DM + bx + threadIdx.x];
    __syncthreads();
    for (int j = threadIdx.y; j < 32; j += 8)
        WT[(size_t)(bx + j) * DM + by + threadIdx.x] = to_tf32(t[threadIdx.x][j]);
}

// ---------------------------------------------------------------------------
// TF32 tensor-core GEMM via mma.sync (as R4): tile 128x128, BK=32, 8 warps.
// ---------------------------------------------------------------------------
#define GBM 128
#define GBN 128
#define GBK 32
#define SSTRIDE 36

__global__ __launch_bounds__(256) void gemm_mma(
    const float* __restrict__ A, const float* __restrict__ BT,
    const float* __restrict__ bias, float* __restrict__ C,
    int M, int N, int K)
{
    __shared__ float sA[GBM * SSTRIDE];
    __shared__ float sB[GBN * SSTRIDE];

    const int tid = threadIdx.x;
    const int wid = tid >> 5;
    const int lane = tid & 31;
    const int gID = lane >> 2;
    const int ig  = lane & 3;

    const int warp_m = wid >> 2;
    const int warp_n = wid & 3;

    const int bm = blockIdx.y * GBM;
    const int bn = blockIdx.x * GBN;

    float acc[4][4][4];
#pragma unroll
    for (int i = 0; i < 4; i++)
#pragma unroll
        for (int j = 0; j < 4; j++)
#pragma unroll
            for (int v = 0; v < 4; v++) acc[i][j][v] = 0.0f;

    for (int k0 = 0; k0 < K; k0 += GBK) {
#pragma unroll
        for (int i = 0; i < 4; i++) {
            int idx = tid + i * 256;
            int r = idx >> 3;
            int c4 = idx & 7;
            float4 va = *(const float4*)&A[(size_t)(bm + r) * K + k0 + c4 * 4];
            va.x = to_tf32(va.x); va.y = to_tf32(va.y);
            va.z = to_tf32(va.z); va.w = to_tf32(va.w);
            *(float4*)&sA[r * SSTRIDE + c4 * 4] = va;
            float4 vb = *(const float4*)&BT[(size_t)(bn + r) * K + k0 + c4 * 4];
            *(float4*)&sB[r * SSTRIDE + c4 * 4] = vb;
        }
        __syncthreads();

#pragma unroll
        for (int kk = 0; kk < GBK; kk += 8) {
            uint32_t afrag[4][4];
#pragma unroll
            for (int mt = 0; mt < 4; mt++) {
                int r0 = warp_m * 64 + mt * 16 + gID;
                afrag[mt][0] = __float_as_uint(sA[r0 * SSTRIDE + kk + ig]);
                afrag[mt][1] = __float_as_uint(sA[(r0 + 8) * SSTRIDE + kk + ig]);
                afrag[mt][2] = __float_as_uint(sA[r0 * SSTRIDE + kk + ig + 4]);
                afrag[mt][3] = __float_as_uint(sA[(r0 + 8) * SSTRIDE + kk + ig + 4]);
            }
            uint32_t bfrag[4][2];
#pragma unroll
            for (int nt = 0; nt < 4; nt++) {
                int n0 = warp_n * 32 + nt * 8 + gID;
                bfrag[nt][0] = __float_as_uint(sB[n0 * SSTRIDE + kk + ig]);
                bfrag[nt][1] = __float_as_uint(sB[n0 * SSTRIDE + kk + ig + 4]);
            }
#pragma unroll
            for (int mt = 0; mt < 4; mt++)
#pragma unroll
                for (int nt = 0; nt < 4; nt++)
                    mma_tf32(acc[mt][nt], afrag[mt], bfrag[nt]);
        }
        __syncthreads();
    }

#pragma unroll
    for (int mt = 0; mt < 4; mt++) {
#pragma unroll
        for (int nt = 0; nt < 4; nt++) {
            int row = bm + warp_m * 64 + mt * 16 + gID;
            int col = bn + warp_n * 32 + nt * 8 + ig * 2;
            float2 v0, v1;
            v0.x = acc[mt][nt][0]; v0.y = acc[mt][nt][1];
            v1.x = acc[mt][nt][2]; v1.y = acc[mt][nt][3];
            if (bias) {
                float b0 = bias[col], b1 = bias[col + 1];
                v0.x += b0; v0.y += b1;
                v1.x += b0; v1.y += b1;
            }
            *(float2*)&C[(size_t)row * N + col] = v0;
            *(float2*)&C[(size_t)(row + 8) * N + col] = v1;
        }
    }
}

// ---------------------------------------------------------------------------
// Tensor-core flash attention. CTA = (128 q-rows, head, batch), 8 warps.
// Warp owns 16 q-rows. Online softmax in accumulator layout (quad-uniform m/l).
// ---------------------------------------------------------------------------
#define AST 68   // padded smem stride (floats); frag bank = (4r + c) % 32, conflict-free

#define SMEM_ATT ((128 * AST + 64 * AST + 64 * AST + 128 * AST) * 4)

__global__ __launch_bounds__(256) void attn_mma(
    const float* __restrict__ Qp, const float* __restrict__ Kp,
    const float* __restrict__ Vp, float* __restrict__ Op)
{
    extern __shared__ float sm[];
    float* sQ  = sm;                      // [128][AST] scaled (1/32 * log2e), tf32
    float* sK  = sQ + 128 * AST;          // [64][AST]  tf32
    float* sVT = sK + 64 * AST;           // [64(hd)][AST(key)] tf32
    float* sP  = sVT + 64 * AST;          // [128][AST] tf32

    const int tid = threadIdx.x;
    const int wid = tid >> 5;
    const int lane = tid & 31;
    const int gID = lane >> 2;
    const int ig  = lane & 3;
    const int qt = blockIdx.x;
    const int h  = blockIdx.y;
    const int b  = blockIdx.z;

    const float scale = 0.03125f * 1.4426950408889634f;  // 1/sqrt(1024) * log2(e)
    const int r0 = wid * 16 + gID;   // this thread's first q-row (in tile)

    // Stage Q once: 128 rows x 16 float4
    const float* Qbase = Qp + ((size_t)b * NQ + qt * 128) * DM + h * HD;
    for (int i = tid; i < 128 * 16; i += 256) {
        int r = i >> 4, c4 = i & 15;
        float4 v = *(const float4*)&Qbase[(size_t)r * DM + c4 * 4];
        v.x = to_tf32(v.x * scale); v.y = to_tf32(v.y * scale);
        v.z = to_tf32(v.z * scale); v.w = to_tf32(v.w * scale);
        *(float4*)&sQ[r * AST + c4 * 4] = v;
    }

    float m0 = -1e30f, m1 = -1e30f, l0 = 0.0f, l1 = 0.0f;
    float oacc[8][4];
#pragma unroll
    for (int nt = 0; nt < 8; nt++)
#pragma unroll
        for (int v = 0; v < 4; v++) oacc[nt][v] = 0.0f;

    for (int kt = 0; kt < NK / 64; kt++) {
        const float* Kbase = Kp + ((size_t)b * NK + kt * 64) * DM + h * HD;
        const float* Vbase = Vp + ((size_t)b * NK + kt * 64) * DM + h * HD;

        __syncthreads();   // previous iteration's mma reads of sK/sVT done
        for (int i = tid; i < 64 * 16; i += 256) {
            int r = i >> 4, c4 = i & 15;
            float4 kv = *(const float4*)&Kbase[(size_t)r * DM + c4 * 4];
            kv.x = to_tf32(kv.x); kv.y = to_tf32(kv.y);
            kv.z = to_tf32(kv.z); kv.w = to_tf32(kv.w);
            *(float4*)&sK[r * AST + c4 * 4] = kv;
            float4 vv = *(const float4*)&Vbase[(size_t)r * DM + c4 * 4];
            sVT[(c4 * 4 + 0) * AST + r] = to_tf32(vv.x);
            sVT[(c4 * 4 + 1) * AST + r] = to_tf32(vv.y);
            sVT[(c4 * 4 + 2) * AST + r] = to_tf32(vv.z);
            sVT[(c4 * 4 + 3) * AST + r] = to_tf32(vv.w);
        }
        __syncthreads();

        // ---- S = Q @ K^T (warp's 16 rows x 64 keys), log2-domain scaled ----
        float s[8][4];
#pragma unroll
        for (int nt = 0; nt < 8; nt++)
#pragma unroll
            for (int v = 0; v < 4; v++) s[nt][v] = 0.0f;

#pragma unroll
        for (int kk = 0; kk < 64; kk += 8) {
            uint32_t af[4];
            af[0] = __float_as_uint(sQ[r0 * AST + kk + ig]);
            af[1] = __float_as_uint(sQ[(r0 + 8) * AST + kk + ig]);
            af[2] = __float_as_uint(sQ[r0 * AST + kk + ig + 4]);
            af[3] = __float_as_uint(sQ[(r0 + 8) * AST + kk + ig + 4]);
#pragma unroll
            for (int nt = 0; nt < 8; nt++) {
                int n0 = nt * 8 + gID;
                uint32_t bf[2];
                bf[0] = __float_as_uint(sK[n0 * AST + kk + ig]);
                bf[1] = __float_as_uint(sK[n0 * AST + kk + ig + 4]);
                mma_tf32(s[nt], af, bf);
            }
        }

        // ---- Online softmax (rows r0, r0+8; quad-local reductions) ----
        float mt0 = -1e30f, mt1 = -1e30f;
#pragma unroll
        for (int nt = 0; nt < 8; nt++) {
            mt0 = fmaxf(mt0, fmaxf(s[nt][0], s[nt][1]));
            mt1 = fmaxf(mt1, fmaxf(s[nt][2], s[nt][3]));
        }
        mt0 = fmaxf(mt0, __shfl_xor_sync(0xffffffffu, mt0, 1));
        mt0 = fmaxf(mt0, __shfl_xor_sync(0xffffffffu, mt0, 2));
        mt1 = fmaxf(mt1, __shfl_xor_sync(0xffffffffu, mt1, 1));
        mt1 = fmaxf(mt1, __shfl_xor_sync(0xffffffffu, mt1, 2));

        float mn0 = fmaxf(m0, mt0), mn1 = fmaxf(m1, mt1);
        float a0 = ex2(m0 - mn0), a1 = ex2(m1 - mn1);
        m0 = mn0; m1 = mn1;

        float rs0 = 0.0f, rs1 = 0.0f;
#pragma unroll
        for (int nt = 0; nt < 8; nt++) {
            float p00 = ex2(s[nt][0] - mn0);
            float p01 = ex2(s[nt][1] - mn0);
            float p10 = ex2(s[nt][2] - mn1);
            float p11 = ex2(s[nt][3] - mn1);
            rs0 += p00 + p01;
            rs1 += p10 + p11;
            int c = nt * 8 + ig * 2;
            float2 q0; q0.x = to_tf32(p00); q0.y = to_tf32(p01);
            *(float2*)&sP[r0 * AST + c] = q0;
            float2 q1; q1.x = to_tf32(p10); q1.y = to_tf32(p11);
            *(float2*)&sP[(r0 + 8) * AST + c] = q1;
        }
        rs0 += __shfl_xor_sync(0xffffffffu, rs0, 1);
        rs0 += __shfl_xor_sync(0xffffffffu, rs0, 2);
        rs1 += __shfl_xor_sync(0xffffffffu, rs1, 1);
        rs1 += __shfl_xor_sync(0xffffffffu, rs1, 2);
        l0 = l0 * a0 + rs0;
        l1 = l1 * a1 + rs1;

#pragma unroll
        for (int nt = 0; nt < 8; nt++) {
            oacc[nt][0] *= a0; oacc[nt][1] *= a0;
            oacc[nt][2] *= a1; oacc[nt][3] *= a1;
        }
        __syncwarp();   // sP slab written by own warp's lanes, read cross-lane below

        // ---- oacc += P @ V (A from sP rows of this warp, B from sVT) ----
#pragma unroll
        for (int kk = 0; kk < 64; kk += 8) {
            uint32_t af[4];
            af[0] = __float_as_uint(sP[r0 * AST + kk + ig]);
            af[1] = __float_as_uint(sP[(r0 + 8) * AST + kk + ig]);
            af[2] = __float_as_uint(sP[r0 * AST + kk + ig + 4]);
            af[3] = __float_as_uint(sP[(r0 + 8) * AST + kk + ig + 4]);
#pragma unroll
            for (int nt = 0; nt < 8; nt++) {
                int n0 = nt * 8 + gID;
                uint32_t bf[2];
                bf[0] = __float_as_uint(sVT[n0 * AST + kk + ig]);
                bf[1] = __float_as_uint(sVT[n0 * AST + kk + ig + 4]);
                mma_tf32(oacc[nt], af, bf);
            }
        }
    }

    // ---- Epilogue: normalize, write to [b, n, h*64 + d] ----
    float inv0 = 1.0f / l0, inv1 = 1.0f / l1;
    const int grow = qt * 128 + r0;
#pragma unroll
    for (int nt = 0; nt < 8; nt++) {
        int col = h * HD + nt * 8 + ig * 2;
        float2 o0; o0.x = oacc[nt][0] * inv0; o0.y = oacc[nt][1] * inv0;
        *(float2*)&Op[((size_t)b * NQ + grow) * DM + col] = o0;
        float2 o1; o1.x = oacc[nt][2] * inv1; o1.y = oacc[nt][3] * inv1;
        *(float2*)&Op[((size_t)b * NQ + grow + 8) * DM + col] = o1;
    }
}

// ---------------------------------------------------------------------------
// Launch
// ---------------------------------------------------------------------------
extern "C" void kernel_launch(void* const* d_in, const int* in_sizes, int n_in,
                              void* d_out, int out_size)
{
    const float* queries = (const float*)d_in[0];
    const float* keys    = (const float*)d_in[1];
    const float* values  = (const float*)d_in[2];
    const float* Wq      = (const float*)d_in[3];
    const float* Wk      = (const float*)d_in[4];
    const float* Wv      = (const float*)d_in[5];
    const float* Wo      = (const float*)d_in[6];
    const float* bo      = (const float*)d_in[7];
    float* out           = (float*)d_out;

    float *Qp, *Kp, *Vp, *Op, *WT;
    cudaGetSymbolAddress((void**)&Qp, g_Q);
    cudaGetSymbolAddress((void**)&Kp, g_K);
    cudaGetSymbolAddress((void**)&Vp, g_V);
    cudaGetSymbolAddress((void**)&Op, g_O);
    cudaGetSymbolAddress((void**)&WT, g_WT);

    static bool attr_set = false;
    if (!attr_set) {
        cudaFuncSetAttribute(attn_mma,
                             cudaFuncAttributeMaxDynamicSharedMemorySize, SMEM_ATT);
        attr_set = true;
    }

    const int M = BATCH * NQ;  // 8192
    const size_t WSZ = (size_t)DM * DM;

    dim3 tgrid(DM / 32, DM / 32), tblk(32, 8);
    transpose_tf32<<<tgrid, tblk>>>(Wq, WT + 0 * WSZ);
    transpose_tf32<<<tgrid, tblk>>>(Wk, WT + 1 * WSZ);
    transpose_tf32<<<tgrid, tblk>>>(Wv, WT + 2 * WSZ);
    transpose_tf32<<<tgrid, tblk>>>(Wo, WT + 3 * WSZ);

    dim3 ggrid(DM / GBN, M / GBM);  // (8, 64)
    gemm_mma<<<ggrid, 256>>>(queries, WT + 0 * WSZ, nullptr, Qp, M, DM, DM);
    gemm_mma<<<ggrid, 256>>>(keys,    WT + 1 * WSZ, nullptr, Kp, M, DM, DM);
    gemm_mma<<<ggrid, 256>>>(values,  WT + 2 * WSZ, nullptr, Vp, M, DM, DM);

    dim3 agrid(NQ / 128, NH, BATCH);  // (16, 16, 4)
    attn_mma<<<agrid, 256, SMEM_ATT>>>(Qp, Kp, Vp, Op);

    gemm_mma<<<ggrid, 256>>>(Op, WT + 3 * WSZ, bo, out, M, DM, DM);
}

// round 6
// speedup vs baseline: 3.1829x; 1.0588x over previous
#include <cuda_runtime.h>
#include <math.h>
#include <stdint.h>

#define BATCH 4
#define NQ 2048
#define NK 2048
#define DM 1024
#define NH 16
#define HD 64
#define MROWS (BATCH * NQ)   // 8192

// Scratch
__device__ float g_Q[BATCH * NQ * DM];
__device__ float g_K[BATCH * NK * DM];
__device__ float g_V[BATCH * NK * DM];
__device__ float g_O[BATCH * NQ * DM];
__device__ float g_WT[4 * DM * DM];          // transposed + tf32(RNA) weights
__device__ float g_IN[3 * MROWS * DM];       // tf32(RNA)-rounded inputs q/k/v

__device__ __forceinline__ float to_tf32(float x) {
    float r;
    asm("cvt.rna.tf32.f32 %0, %1;" : "=f"(r) : "f"(x));
    return r;
}

__device__ __forceinline__ float ex2(float x) {
    float r;
    asm("ex2.approx.ftz.f32 %0, %1;" : "=f"(r) : "f"(x));
    return r;
}

__device__ __forceinline__ void mma_tf32(float* c, const uint32_t* a, const uint32_t* b) {
    asm volatile(
        "mma.sync.aligned.m16n8k8.row.col.f32.tf32.tf32.f32 "
        "{%0,%1,%2,%3}, {%4,%5,%6,%7}, {%8,%9}, {%0,%1,%2,%3};"
        : "+f"(c[0]), "+f"(c[1]), "+f"(c[2]), "+f"(c[3])
        : "r"(a[0]), "r"(a[1]), "r"(a[2]), "r"(a[3]), "r"(b[0]), "r"(b[1]));
}

__device__ __forceinline__ uint32_t smem_u32(const void* p) {
    uint32_t a;
    asm("{ .reg .u64 t; cvta.to.shared.u64 t, %1; cvt.u32.u64 %0, t; }"
        : "=r"(a) : "l"(p));
    return a;
}

__device__ __forceinline__ void cp16(uint32_t dst, const void* src) {
    asm volatile("cp.async.ca.shared.global [%0], [%1], 16;" :: "r"(dst), "l"(src));
}
#define CP_COMMIT() asm volatile("cp.async.commit_group;" ::: "memory")
#define CP_WAIT(n)  asm volatile("cp.async.wait_group %0;" :: "n"(n) : "memory")

// ---------------------------------------------------------------------------
// Weight transpose (+ tf32 RNA): W[K][N] -> WT[N][K]; z selects one of 4.
// ---------------------------------------------------------------------------
__global__ void transpose4_tf32(const float* __restrict__ W0, const float* __restrict__ W1,
                                const float* __restrict__ W2, const float* __restrict__ W3,
                                float* __restrict__ WT)
{
    __shared__ float t[32][33];
    const int z = blockIdx.z;
    const float* W = (z == 0) ? W0 : (z == 1) ? W1 : (z == 2) ? W2 : W3;
    float* WTz = WT + (size_t)z * DM * DM;
    int bx = blockIdx.x * 32, by = blockIdx.y * 32;
    for (int j = threadIdx.y; j < 32; j += 8)
        t[j][threadIdx.x] = W[(size_t)(by + j) * DM + bx + threadIdx.x];
    __syncthreads();
    for (int j = threadIdx.y; j < 32; j += 8)
        WTz[(size_t)(bx + j) * DM + by + threadIdx.x] = to_tf32(t[threadIdx.x][j]);
}

// ---------------------------------------------------------------------------
// tf32 RNA rounding prepass for the 3 input activations (z selects tensor)
// ---------------------------------------------------------------------------
__global__ __launch_bounds__(256) void round3(
    const float* __restrict__ q, const float* __restrict__ k,
    const float* __restrict__ v, float* __restrict__ dst)
{
    const int z = blockIdx.z;
    const float* src = (z == 0) ? q : (z == 1) ? k : v;
    float* d = dst + (size_t)z * MROWS * DM;
    const size_t n4 = (size_t)MROWS * DM / 4;
    for (size_t i = blockIdx.x * 256 + threadIdx.x; i < n4; i += (size_t)gridDim.x * 256) {
        float4 x = ((const float4*)src)[i];
        x.x = to_tf32(x.x); x.y = to_tf32(x.y);
        x.z = to_tf32(x.z); x.w = to_tf32(x.w);
        ((float4*)d)[i] = x;
    }
}

// ---------------------------------------------------------------------------
// TF32 mma GEMM core with 2-stage cp.async pipeline.
// A [8192][1024] pre-rounded, BT [1024][1024] pre-rounded (row-major [N][K]).
// CTA tile 128x128, BK=32, 8 warps (warp tile 64x32).
// ---------------------------------------------------------------------------
#define GBM 128
#define GBN 128
#define GBK 32
#define SSTRIDE 36
#define TILE_FLOATS (GBM * SSTRIDE)          // per A or B tile
#define STAGE_FLOATS (2 * TILE_FLOATS)       // A + B
#define SMEM_GEMM (2 * STAGE_FLOATS * 4)     // 73728 bytes

__device__ __forceinline__ void gemm_stage_issue(
    const float* __restrict__ A, const float* __restrict__ BT,
    int bm, int bn, int k0, uint32_t sA_addr, uint32_t sB_addr, int tid)
{
#pragma unroll
    for (int i = 0; i < 4; i++) {
        int idx = tid + i * 256;
        int r = idx >> 3;      // 0..127
        int c4 = idx & 7;      // 0..7
        uint32_t off = (uint32_t)(r * SSTRIDE + c4 * 4) * 4;
        cp16(sA_addr + off, &A[(size_t)(bm + r) * DM + k0 + c4 * 4]);
        cp16(sB_addr + off, &BT[(size_t)(bn + r) * DM + k0 + c4 * 4]);
    }
    CP_COMMIT();
}

__device__ __forceinline__ void gemm_core(
    const float* __restrict__ A, const float* __restrict__ BT,
    const float* __restrict__ bias, float* __restrict__ C,
    bool round_c, float* dsm)
{
    const uint32_t sbase = smem_u32(dsm);
    const int tid = threadIdx.x;
    const int wid = tid >> 5;
    const int lane = tid & 31;
    const int gID = lane >> 2;
    const int ig  = lane & 3;
    const int warp_m = wid >> 2;
    const int warp_n = wid & 3;
    const int bm = blockIdx.y * GBM;
    const int bn = blockIdx.x * GBN;

    float acc[4][4][4];
#pragma unroll
    for (int i = 0; i < 4; i++)
#pragma unroll
        for (int j = 0; j < 4; j++)
#pragma unroll
            for (int v = 0; v < 4; v++) acc[i][j][v] = 0.0f;

    const int kSteps = DM / GBK;   // 32

    // prologue
    gemm_stage_issue(A, BT, bm, bn, 0,
                     sbase, sbase + TILE_FLOATS * 4, tid);

    for (int kt = 0; kt < kSteps; kt++) {
        const int cur = kt & 1;
        if (kt + 1 < kSteps) {
            const int nxt = (kt + 1) & 1;
            gemm_stage_issue(A, BT, bm, bn, (kt + 1) * GBK,
                             sbase + nxt * STAGE_FLOATS * 4,
                             sbase + (nxt * STAGE_FLOATS + TILE_FLOATS) * 4, tid);
            CP_WAIT(1);
        } else {
            CP_WAIT(0);
        }
        __syncthreads();

        const float* sA = dsm + cur * STAGE_FLOATS;
        const float* sB = sA + TILE_FLOATS;

#pragma unroll
        for (int kk = 0; kk < GBK; kk += 8) {
            uint32_t afrag[4][4];
#pragma unroll
            for (int mt = 0; mt < 4; mt++) {
                int r0 = warp_m * 64 + mt * 16 + gID;
                afrag[mt][0] = __float_as_uint(sA[r0 * SSTRIDE + kk + ig]);
                afrag[mt][1] = __float_as_uint(sA[(r0 + 8) * SSTRIDE + kk + ig]);
                afrag[mt][2] = __float_as_uint(sA[r0 * SSTRIDE + kk + ig + 4]);
                afrag[mt][3] = __float_as_uint(sA[(r0 + 8) * SSTRIDE + kk + ig + 4]);
            }
            uint32_t bfrag[4][2];
#pragma unroll
            for (int nt = 0; nt < 4; nt++) {
                int n0 = warp_n * 32 + nt * 8 + gID;
                bfrag[nt][0] = __float_as_uint(sB[n0 * SSTRIDE + kk + ig]);
                bfrag[nt][1] = __float_as_uint(sB[n0 * SSTRIDE + kk + ig + 4]);
            }
#pragma unroll
            for (int mt = 0; mt < 4; mt++)
#pragma unroll
                for (int nt = 0; nt < 4; nt++)
                    mma_tf32(acc[mt][nt], afrag[mt], bfrag[nt]);
        }
        __syncthreads();
    }

#pragma unroll
    for (int mt = 0; mt < 4; mt++) {
#pragma unroll
        for (int nt = 0; nt < 4; nt++) {
            int row = bm + warp_m * 64 + mt * 16 + gID;
            int col = bn + warp_n * 32 + nt * 8 + ig * 2;
            float2 v0, v1;
            v0.x = acc[mt][nt][0]; v0.y = acc[mt][nt][1];
            v1.x = acc[mt][nt][2]; v1.y = acc[mt][nt][3];
            if (bias) {
                float b0 = bias[col], b1 = bias[col + 1];
                v0.x += b0; v0.y += b1;
                v1.x += b0; v1.y += b1;
            }
            if (round_c) {
                v0.x = to_tf32(v0.x); v0.y = to_tf32(v0.y);
                v1.x = to_tf32(v1.x); v1.y = to_tf32(v1.y);
            }
            *(float2*)&C[(size_t)row * DM + col] = v0;
            *(float2*)&C[(size_t)(row + 8) * DM + col] = v1;
        }
    }
}

// Q/K/V projections fused: z selects (input, weight, output). Output rounded tf32.
__global__ __launch_bounds__(256) void gemm_qkv(
    const float* __restrict__ IN, const float* __restrict__ WT,
    float* __restrict__ Qo, float* __restrict__ Ko, float* __restrict__ Vo)
{
    extern __shared__ float dsm[];
    const int z = blockIdx.z;
    const float* A = IN + (size_t)z * MROWS * DM;
    const float* BT = WT + (size_t)z * DM * DM;
    float* C = (z == 0) ? Qo : (z == 1) ? Ko : Vo;
    gemm_core(A, BT, nullptr, C, true, dsm);
}

// Final output GEMM: out = Op @ Wo + bo (no rounding of C)
__global__ __launch_bounds__(256) void gemm_out(
    const float* __restrict__ A, const float* __restrict__ BT,
    const float* __restrict__ bias, float* __restrict__ C)
{
    extern __shared__ float dsm[];
    gemm_core(A, BT, bias, C, false, dsm);
}

// ---------------------------------------------------------------------------
// Tensor-core flash attention (R5 structure). K/V arrive pre-rounded tf32.
// Epilogue writes tf32-rounded Op for the final GEMM.
// ---------------------------------------------------------------------------
#define AST 68
#define SMEM_ATT ((128 * AST + 64 * AST + 64 * AST + 128 * AST) * 4)

__global__ __launch_bounds__(256) void attn_mma(
    const float* __restrict__ Qp, const float* __restrict__ Kp,
    const float* __restrict__ Vp, float* __restrict__ Op)
{
    extern __shared__ float sm[];
    float* sQ  = sm;                      // [128][AST]
    float* sK  = sQ + 128 * AST;          // [64][AST]
    float* sVT = sK + 64 * AST;           // [64][AST]
    float* sP  = sVT + 64 * AST;          // [128][AST]

    const int tid = threadIdx.x;
    const int wid = tid >> 5;
    const int lane = tid & 31;
    const int gID = lane >> 2;
    const int ig  = lane & 3;
    const int qt = blockIdx.x;
    const int h  = blockIdx.y;
    const int b  = blockIdx.z;

    const float scale = 0.03125f * 1.4426950408889634f;  // 1/sqrt(1024) * log2(e)
    const int r0 = wid * 16 + gID;

    const float* Qbase = Qp + ((size_t)b * NQ + qt * 128) * DM + h * HD;
    for (int i = tid; i < 128 * 16; i += 256) {
        int r = i >> 4, c4 = i & 15;
        float4 v = *(const float4*)&Qbase[(size_t)r * DM + c4 * 4];
        v.x = to_tf32(v.x * scale); v.y = to_tf32(v.y * scale);
        v.z = to_tf32(v.z * scale); v.w = to_tf32(v.w * scale);
        *(float4*)&sQ[r * AST + c4 * 4] = v;
    }

    float m0 = -1e30f, m1 = -1e30f, l0 = 0.0f, l1 = 0.0f;
    float oacc[8][4];
#pragma unroll
    for (int nt = 0; nt < 8; nt++)
#pragma unroll
        for (int v = 0; v < 4; v++) oacc[nt][v] = 0.0f;

    for (int kt = 0; kt < NK / 64; kt++) {
        const float* Kbase = Kp + ((size_t)b * NK + kt * 64) * DM + h * HD;
        const float* Vbase = Vp + ((size_t)b * NK + kt * 64) * DM + h * HD;

        __syncthreads();
        for (int i = tid; i < 64 * 16; i += 256) {
            int r = i >> 4, c4 = i & 15;
            float4 kv = *(const float4*)&Kbase[(size_t)r * DM + c4 * 4];
            *(float4*)&sK[r * AST + c4 * 4] = kv;   // already tf32
            float4 vv = *(const float4*)&Vbase[(size_t)r * DM + c4 * 4];
            sVT[(c4 * 4 + 0) * AST + r] = vv.x;     // already tf32
            sVT[(c4 * 4 + 1) * AST + r] = vv.y;
            sVT[(c4 * 4 + 2) * AST + r] = vv.z;
            sVT[(c4 * 4 + 3) * AST + r] = vv.w;
        }
        __syncthreads();

        float s[8][4];
#pragma unroll
        for (int nt = 0; nt < 8; nt++)
#pragma unroll
            for (int v = 0; v < 4; v++) s[nt][v] = 0.0f;

#pragma unroll
        for (int kk = 0; kk < 64; kk += 8) {
            uint32_t af[4];
            af[0] = __float_as_uint(sQ[r0 * AST + kk + ig]);
            af[1] = __float_as_uint(sQ[(r0 + 8) * AST + kk + ig]);
            af[2] = __float_as_uint(sQ[r0 * AST + kk + ig + 4]);
            af[3] = __float_as_uint(sQ[(r0 + 8) * AST + kk + ig + 4]);
#pragma unroll
            for (int nt = 0; nt < 8; nt++) {
                int n0 = nt * 8 + gID;
                uint32_t bf[2];
                bf[0] = __float_as_uint(sK[n0 * AST + kk + ig]);
                bf[1] = __float_as_uint(sK[n0 * AST + kk + ig + 4]);
                mma_tf32(s[nt], af, bf);
            }
        }

        float mt0 = -1e30f, mt1 = -1e30f;
#pragma unroll
        for (int nt = 0; nt < 8; nt++) {
            mt0 = fmaxf(mt0, fmaxf(s[nt][0], s[nt][1]));
            mt1 = fmaxf(mt1, fmaxf(s[nt][2], s[nt][3]));
        }
        mt0 = fmaxf(mt0, __shfl_xor_sync(0xffffffffu, mt0, 1));
        mt0 = fmaxf(mt0, __shfl_xor_sync(0xffffffffu, mt0, 2));
        mt1 = fmaxf(mt1, __shfl_xor_sync(0xffffffffu, mt1, 1));
        mt1 = fmaxf(mt1, __shfl_xor_sync(0xffffffffu, mt1, 2));

        float mn0 = fmaxf(m0, mt0), mn1 = fmaxf(m1, mt1);
        float a0 = ex2(m0 - mn0), a1 = ex2(m1 - mn1);
        m0 = mn0; m1 = mn1;

        float rs0 = 0.0f, rs1 = 0.0f;
#pragma unroll
        for (int nt = 0; nt < 8; nt++) {
            float p00 = ex2(s[nt][0] - mn0);
            float p01 = ex2(s[nt][1] - mn0);
            float p10 = ex2(s[nt][2] - mn1);
            float p11 = ex2(s[nt][3] - mn1);
            rs0 += p00 + p01;
            rs1 += p10 + p11;
            int c = nt * 8 + ig * 2;
            float2 q0; q0.x = to_tf32(p00); q0.y = to_tf32(p01);
            *(float2*)&sP[r0 * AST + c] = q0;
            float2 q1; q1.x = to_tf32(p10); q1.y = to_tf32(p11);
            *(float2*)&sP[(r0 + 8) * AST + c] = q1;
        }
        rs0 += __shfl_xor_sync(0xffffffffu, rs0, 1);
        rs0 += __shfl_xor_sync(0xffffffffu, rs0, 2);
        rs1 += __shfl_xor_sync(0xffffffffu, rs1, 1);
        rs1 += __shfl_xor_sync(0xffffffffu, rs1, 2);
        l0 = l0 * a0 + rs0;
        l1 = l1 * a1 + rs1;

#pragma unroll
        for (int nt = 0; nt < 8; nt++) {
            oacc[nt][0] *= a0; oacc[nt][1] *= a0;
            oacc[nt][2] *= a1; oacc[nt][3] *= a1;
        }
        __syncwarp();

#pragma unroll
        for (int kk = 0; kk < 64; kk += 8) {
            uint32_t af[4];
            af[0] = __float_as_uint(sP[r0 * AST + kk + ig]);
            af[1] = __float_as_uint(sP[(r0 + 8) * AST + kk + ig]);
            af[2] = __float_as_uint(sP[r0 * AST + kk + ig + 4]);
            af[3] = __float_as_uint(sP[(r0 + 8) * AST + kk + ig + 4]);
#pragma unroll
            for (int nt = 0; nt < 8; nt++) {
                int n0 = nt * 8 + gID;
                uint32_t bf[2];
                bf[0] = __float_as_uint(sVT[n0 * AST + kk + ig]);
                bf[1] = __float_as_uint(sVT[n0 * AST + kk + ig + 4]);
                mma_tf32(oacc[nt], af, bf);
            }
        }
    }

    float inv0 = 1.0f / l0, inv1 = 1.0f / l1;
    const int grow = qt * 128 + r0;
#pragma unroll
    for (int nt = 0; nt < 8; nt++) {
        int col = h * HD + nt * 8 + ig * 2;
        float2 o0;
        o0.x = to_tf32(oacc[nt][0] * inv0);
        o0.y = to_tf32(oacc[nt][1] * inv0);
        *(float2*)&Op[((size_t)b * NQ + grow) * DM + col] = o0;
        float2 o1;
        o1.x = to_tf32(oacc[nt][2] * inv1);
        o1.y = to_tf32(oacc[nt][3] * inv1);
        *(float2*)&Op[((size_t)b * NQ + grow + 8) * DM + col] = o1;
    }
}

// ---------------------------------------------------------------------------
// Launch
// ---------------------------------------------------------------------------
extern "C" void kernel_launch(void* const* d_in, const int* in_sizes, int n_in,
                              void* d_out, int out_size)
{
    const float* queries = (const float*)d_in[0];
    const float* keys    = (const float*)d_in[1];
    const float* values  = (const float*)d_in[2];
    const float* Wq      = (const float*)d_in[3];
    const float* Wk      = (const float*)d_in[4];
    const float* Wv      = (const float*)d_in[5];
    const float* Wo      = (const float*)d_in[6];
    const float* bo      = (const float*)d_in[7];
    float* out           = (float*)d_out;

    float *Qp, *Kp, *Vp, *Op, *WT, *IN;
    cudaGetSymbolAddress((void**)&Qp, g_Q);
    cudaGetSymbolAddress((void**)&Kp, g_K);
    cudaGetSymbolAddress((void**)&Vp, g_V);
    cudaGetSymbolAddress((void**)&Op, g_O);
    cudaGetSymbolAddress((void**)&WT, g_WT);
    cudaGetSymbolAddress((void**)&IN, g_IN);

    static bool attr_set = false;
    if (!attr_set) {
        cudaFuncSetAttribute(attn_mma,
                             cudaFuncAttributeMaxDynamicSharedMemorySize, SMEM_ATT);
        cudaFuncSetAttribute(gemm_qkv,
                             cudaFuncAttributeMaxDynamicSharedMemorySize, SMEM_GEMM);
        cudaFuncSetAttribute(gemm_out,
                             cudaFuncAttributeMaxDynamicSharedMemorySize, SMEM_GEMM);
        attr_set = true;
    }

    // weight transposes (z=4) and input rounding (z=3)
    dim3 tgrid(DM / 32, DM / 32, 4), tblk(32, 8);
    transpose4_tf32<<<tgrid, tblk>>>(Wq, Wk, Wv, Wo, WT);

    dim3 rgrid(512, 1, 3);
    round3<<<rgrid, 256>>>(queries, keys, values, IN);

    // fused QKV projections
    dim3 qgrid(DM / GBN, MROWS / GBM, 3);  // (8, 64, 3)
    gemm_qkv<<<qgrid, 256, SMEM_GEMM>>>(IN, WT, Qp, Kp, Vp);

    // attention
    dim3 agrid(NQ / 128, NH, BATCH);  // (16, 16, 4)
    attn_mma<<<agrid, 256, SMEM_ATT>>>(Qp, Kp, Vp, Op);

    // output projection
    dim3 ogrid(DM / GBN, MROWS / GBM);
    gemm_out<<<ogrid, 256, SMEM_GEMM>>>(Op, WT + 3 * (size_t)DM * DM, bo, out);
}

// round 7
// speedup vs baseline: 3.4614x; 1.0875x over previous
#include <cuda_runtime.h>
#include <math.h>
#include <stdint.h>

#define BATCH 4
#define NQ 2048
#define NK 2048
#define DM 1024
#define NH 16
#define HD 64
#define MROWS (BATCH * NQ)   // 8192

// Scratch
__device__ float g_Q[BATCH * NQ * DM];
__device__ float g_K[BATCH * NK * DM];
__device__ float g_V[BATCH * NK * DM];
__device__ float g_O[BATCH * NQ * DM];
__device__ float g_WT[4 * DM * DM];          // transposed + tf32(RNA) weights
__device__ float g_IN[3 * MROWS * DM];       // tf32(RNA)-rounded inputs q/k/v

__device__ __forceinline__ float to_tf32(float x) {
    float r;
    asm("cvt.rna.tf32.f32 %0, %1;" : "=f"(r) : "f"(x));
    return r;
}

__device__ __forceinline__ float ex2(float x) {
    float r;
    asm("ex2.approx.ftz.f32 %0, %1;" : "=f"(r) : "f"(x));
    return r;
}

__device__ __forceinline__ void mma_tf32(float* c, const uint32_t* a, const uint32_t* b) {
    asm volatile(
        "mma.sync.aligned.m16n8k8.row.col.f32.tf32.tf32.f32 "
        "{%0,%1,%2,%3}, {%4,%5,%6,%7}, {%8,%9}, {%0,%1,%2,%3};"
        : "+f"(c[0]), "+f"(c[1]), "+f"(c[2]), "+f"(c[3])
        : "r"(a[0]), "r"(a[1]), "r"(a[2]), "r"(a[3]), "r"(b[0]), "r"(b[1]));
}

__device__ __forceinline__ uint32_t smem_u32(const void* p) {
    uint32_t a;
    asm("{ .reg .u64 t; cvta.to.shared.u64 t, %1; cvt.u32.u64 %0, t; }"
        : "=r"(a) : "l"(p));
    return a;
}

__device__ __forceinline__ void cp16(uint32_t dst, const void* src) {
    asm volatile("cp.async.ca.shared.global [%0], [%1], 16;" :: "r"(dst), "l"(src));
}
#define CP_COMMIT() asm volatile("cp.async.commit_group;" ::: "memory")
#define CP_WAIT(n)  asm volatile("cp.async.wait_group %0;" :: "n"(n) : "memory")

// ---------------------------------------------------------------------------
// Weight transpose (+ tf32 RNA): W[K][N] -> WT[N][K]; z selects one of 4.
// ---------------------------------------------------------------------------
__global__ void transpose4_tf32(const float* __restrict__ W0, const float* __restrict__ W1,
                                const float* __restrict__ W2, const float* __restrict__ W3,
                                float* __restrict__ WT)
{
    __shared__ float t[32][33];
    const int z = blockIdx.z;
    const float* W = (z == 0) ? W0 : (z == 1) ? W1 : (z == 2) ? W2 : W3;
    float* WTz = WT + (size_t)z * DM * DM;
    int bx = blockIdx.x * 32, by = blockIdx.y * 32;
    for (int j = threadIdx.y; j < 32; j += 8)
        t[j][threadIdx.x] = W[(size_t)(by + j) * DM + bx + threadIdx.x];
    __syncthreads();
    for (int j = threadIdx.y; j < 32; j += 8)
        WTz[(size_t)(bx + j) * DM + by + threadIdx.x] = to_tf32(t[threadIdx.x][j]);
}

// ---------------------------------------------------------------------------
// tf32 RNA rounding prepass for the 3 input activations
// ---------------------------------------------------------------------------
__global__ __launch_bounds__(256) void round3(
    const float* __restrict__ q, const float* __restrict__ k,
    const float* __restrict__ v, float* __restrict__ dst)
{
    const int z = blockIdx.z;
    const float* src = (z == 0) ? q : (z == 1) ? k : v;
    float* d = dst + (size_t)z * MROWS * DM;
    const size_t n4 = (size_t)MROWS * DM / 4;
    for (size_t i = blockIdx.x * 256 + threadIdx.x; i < n4; i += (size_t)gridDim.x * 256) {
        float4 x = ((const float4*)src)[i];
        x.x = to_tf32(x.x); x.y = to_tf32(x.y);
        x.z = to_tf32(x.z); x.w = to_tf32(x.w);
        ((float4*)d)[i] = x;
    }
}

// ---------------------------------------------------------------------------
// TF32 mma GEMM core with 2-stage cp.async pipeline (unchanged from R6).
// ---------------------------------------------------------------------------
#define GBM 128
#define GBN 128
#define GBK 32
#define SSTRIDE 36
#define TILE_FLOATS (GBM * SSTRIDE)
#define STAGE_FLOATS (2 * TILE_FLOATS)
#define SMEM_GEMM (2 * STAGE_FLOATS * 4)

__device__ __forceinline__ void gemm_stage_issue(
    const float* __restrict__ A, const float* __restrict__ BT,
    int bm, int bn, int k0, uint32_t sA_addr, uint32_t sB_addr, int tid)
{
#pragma unroll
    for (int i = 0; i < 4; i++) {
        int idx = tid + i * 256;
        int r = idx >> 3;
        int c4 = idx & 7;
        uint32_t off = (uint32_t)(r * SSTRIDE + c4 * 4) * 4;
        cp16(sA_addr + off, &A[(size_t)(bm + r) * DM + k0 + c4 * 4]);
        cp16(sB_addr + off, &BT[(size_t)(bn + r) * DM + k0 + c4 * 4]);
    }
    CP_COMMIT();
}

__device__ __forceinline__ void gemm_core(
    const float* __restrict__ A, const float* __restrict__ BT,
    const float* __restrict__ bias, float* __restrict__ C,
    bool round_c, float* dsm)
{
    const uint32_t sbase = smem_u32(dsm);
    const int tid = threadIdx.x;
    const int wid = tid >> 5;
    const int lane = tid & 31;
    const int gID = lane >> 2;
    const int ig  = lane & 3;
    const int warp_m = wid >> 2;
    const int warp_n = wid & 3;
    const int bm = blockIdx.y * GBM;
    const int bn = blockIdx.x * GBN;

    float acc[4][4][4];
#pragma unroll
    for (int i = 0; i < 4; i++)
#pragma unroll
        for (int j = 0; j < 4; j++)
#pragma unroll
            for (int v = 0; v < 4; v++) acc[i][j][v] = 0.0f;

    const int kSteps = DM / GBK;

    gemm_stage_issue(A, BT, bm, bn, 0, sbase, sbase + TILE_FLOATS * 4, tid);

    for (int kt = 0; kt < kSteps; kt++) {
        const int cur = kt & 1;
        if (kt + 1 < kSteps) {
            const int nxt = (kt + 1) & 1;
            gemm_stage_issue(A, BT, bm, bn, (kt + 1) * GBK,
                             sbase + nxt * STAGE_FLOATS * 4,
                             sbase + (nxt * STAGE_FLOATS + TILE_FLOATS) * 4, tid);
            CP_WAIT(1);
        } else {
            CP_WAIT(0);
        }
        __syncthreads();

        const float* sA = dsm + cur * STAGE_FLOATS;
        const float* sB = sA + TILE_FLOATS;

#pragma unroll
        for (int kk = 0; kk < GBK; kk += 8) {
            uint32_t afrag[4][4];
#pragma unroll
            for (int mt = 0; mt < 4; mt++) {
                int r0 = warp_m * 64 + mt * 16 + gID;
                afrag[mt][0] = __float_as_uint(sA[r0 * SSTRIDE + kk + ig]);
                afrag[mt][1] = __float_as_uint(sA[(r0 + 8) * SSTRIDE + kk + ig]);
                afrag[mt][2] = __float_as_uint(sA[r0 * SSTRIDE + kk + ig + 4]);
                afrag[mt][3] = __float_as_uint(sA[(r0 + 8) * SSTRIDE + kk + ig + 4]);
            }
            uint32_t bfrag[4][2];
#pragma unroll
            for (int nt = 0; nt < 4; nt++) {
                int n0 = warp_n * 32 + nt * 8 + gID;
                bfrag[nt][0] = __float_as_uint(sB[n0 * SSTRIDE + kk + ig]);
                bfrag[nt][1] = __float_as_uint(sB[n0 * SSTRIDE + kk + ig + 4]);
            }
#pragma unroll
            for (int mt = 0; mt < 4; mt++)
#pragma unroll
                for (int nt = 0; nt < 4; nt++)
                    mma_tf32(acc[mt][nt], afrag[mt], bfrag[nt]);
        }
        __syncthreads();
    }

#pragma unroll
    for (int mt = 0; mt < 4; mt++) {
#pragma unroll
        for (int nt = 0; nt < 4; nt++) {
            int row = bm + warp_m * 64 + mt * 16 + gID;
            int col = bn + warp_n * 32 + nt * 8 + ig * 2;
            float2 v0, v1;
            v0.x = acc[mt][nt][0]; v0.y = acc[mt][nt][1];
            v1.x = acc[mt][nt][2]; v1.y = acc[mt][nt][3];
            if (bias) {
                float b0 = bias[col], b1 = bias[col + 1];
                v0.x += b0; v0.y += b1;
                v1.x += b0; v1.y += b1;
            }
            if (round_c) {
                v0.x = to_tf32(v0.x); v0.y = to_tf32(v0.y);
                v1.x = to_tf32(v1.x); v1.y = to_tf32(v1.y);
            }
            *(float2*)&C[(size_t)row * DM + col] = v0;
            *(float2*)&C[(size_t)(row + 8) * DM + col] = v1;
        }
    }
}

__global__ __launch_bounds__(256) void gemm_qkv(
    const float* __restrict__ IN, const float* __restrict__ WT,
    float* __restrict__ Qo, float* __restrict__ Ko, float* __restrict__ Vo)
{
    extern __shared__ float dsm[];
    const int z = blockIdx.z;
    const float* A = IN + (size_t)z * MROWS * DM;
    const float* BT = WT + (size_t)z * DM * DM;
    float* C = (z == 0) ? Qo : (z == 1) ? Ko : Vo;
    gemm_core(A, BT, nullptr, C, true, dsm);
}

__global__ __launch_bounds__(256) void gemm_out(
    const float* __restrict__ A, const float* __restrict__ BT,
    const float* __restrict__ bias, float* __restrict__ C)
{
    extern __shared__ float dsm[];
    gemm_core(A, BT, bias, C, false, dsm);
}

// ---------------------------------------------------------------------------
// Tensor-core flash attention, rev 2.
// CTA = 256 q-rows x (head, batch); 8 warps, warp tile 32(m) x 64(keys), mt=2.
// K and V staged row-major via double-buffered cp.async (pre-rounded tf32).
// V row-major with VST=72 -> PV B-frag loads conflict-free (banks 8*ig+g).
// ---------------------------------------------------------------------------
#define QROWS 256
#define AST 68
#define VST 72
#define KTILE 64
// floats
#define SQ_F (QROWS * AST)
#define SP_F (QROWS * AST)
#define SK_F (KTILE * AST)
#define SV_F (KTILE * VST)
#define SMEM_ATT ((SQ_F + SP_F + 2 * SK_F + 2 * SV_F) * 4)

__device__ __forceinline__ void attn_stage_issue(
    const float* __restrict__ Kp, const float* __restrict__ Vp,
    int b, int h, int kt, uint32_t sK_addr, uint32_t sV_addr, int tid)
{
    const float* Kbase = Kp + ((size_t)b * NK + kt * KTILE) * DM + h * HD;
    const float* Vbase = Vp + ((size_t)b * NK + kt * KTILE) * DM + h * HD;
#pragma unroll
    for (int i = 0; i < 4; i++) {
        int idx = tid + i * 256;
        int r = idx >> 4;      // 0..63
        int c4 = idx & 15;     // 0..15
        cp16(sK_addr + (uint32_t)(r * AST + c4 * 4) * 4, &Kbase[(size_t)r * DM + c4 * 4]);
        cp16(sV_addr + (uint32_t)(r * VST + c4 * 4) * 4, &Vbase[(size_t)r * DM + c4 * 4]);
    }
    CP_COMMIT();
}

__global__ __launch_bounds__(256) void attn_mma(
    const float* __restrict__ Qp, const float* __restrict__ Kp,
    const float* __restrict__ Vp, float* __restrict__ Op)
{
    extern __shared__ float sm[];
    float* sQ = sm;                 // [256][AST]
    float* sP = sQ + SQ_F;          // [256][AST]
    float* sK = sP + SP_F;          // 2 x [64][AST]
    float* sV = sK + 2 * SK_F;      // 2 x [64][VST]
    const uint32_t sKa = smem_u32(sK);
    const uint32_t sVa = smem_u32(sV);

    const int tid = threadIdx.x;
    const int wid = tid >> 5;
    const int lane = tid & 31;
    const int gID = lane >> 2;
    const int ig  = lane & 3;
    const int qt = blockIdx.x;
    const int h  = blockIdx.y;
    const int b  = blockIdx.z;

    const float scale = 0.03125f * 1.4426950408889634f;  // 1/sqrt(1024) * log2(e)
    // warp owns rows [wid*32, wid*32+32); mt in {0,1}
    int rr[2];
    rr[0] = wid * 32 + gID;
    rr[1] = wid * 32 + 16 + gID;

    // prologue: stage K/V tile 0
    attn_stage_issue(Kp, Vp, b, h, 0, sKa, sVa, tid);

    // Stage Q (256 rows x 16 float4), pre-scaled, tf32
    const float* Qbase = Qp + ((size_t)b * NQ + qt * QROWS) * DM + h * HD;
    for (int i = tid; i < QROWS * 16; i += 256) {
        int r = i >> 4, c4 = i & 15;
        float4 v = *(const float4*)&Qbase[(size_t)r * DM + c4 * 4];
        v.x = to_tf32(v.x * scale); v.y = to_tf32(v.y * scale);
        v.z = to_tf32(v.z * scale); v.w = to_tf32(v.w * scale);
        *(float4*)&sQ[r * AST + c4 * 4] = v;
    }

    float m[2][2], l[2][2];
#pragma unroll
    for (int mt = 0; mt < 2; mt++) {
        m[mt][0] = -1e30f; m[mt][1] = -1e30f;
        l[mt][0] = 0.0f;   l[mt][1] = 0.0f;
    }
    float oacc[2][8][4];
#pragma unroll
    for (int mt = 0; mt < 2; mt++)
#pragma unroll
        for (int nt = 0; nt < 8; nt++)
#pragma unroll
            for (int v = 0; v < 4; v++) oacc[mt][nt][v] = 0.0f;

    const int nTiles = NK / KTILE;   // 32
    for (int kt = 0; kt < nTiles; kt++) {
        const int cur = kt & 1;
        CP_WAIT(0);
        __syncthreads();
        if (kt + 1 < nTiles) {
            const int nxt = (kt + 1) & 1;
            attn_stage_issue(Kp, Vp, b, h, kt + 1,
                             sKa + nxt * SK_F * 4, sVa + nxt * SV_F * 4, tid);
        }
        const float* cK = sK + cur * SK_F;
        const float* cV = sV + cur * SV_F;

        // ---- S = Q @ K^T : warp 32 rows x 64 keys ----
        float s[2][8][4];
#pragma unroll
        for (int mt = 0; mt < 2; mt++)
#pragma unroll
            for (int nt = 0; nt < 8; nt++)
#pragma unroll
                for (int v = 0; v < 4; v++) s[mt][nt][v] = 0.0f;

#pragma unroll
        for (int kk = 0; kk < 64; kk += 8) {
            uint32_t af[2][4];
#pragma unroll
            for (int mt = 0; mt < 2; mt++) {
                int r0 = rr[mt];
                af[mt][0] = __float_as_uint(sQ[r0 * AST + kk + ig]);
                af[mt][1] = __float_as_uint(sQ[(r0 + 8) * AST + kk + ig]);
                af[mt][2] = __float_as_uint(sQ[r0 * AST + kk + ig + 4]);
                af[mt][3] = __float_as_uint(sQ[(r0 + 8) * AST + kk + ig + 4]);
            }
#pragma unroll
            for (int nt = 0; nt < 8; nt++) {
                int n0 = nt * 8 + gID;
                uint32_t bf[2];
                bf[0] = __float_as_uint(cK[n0 * AST + kk + ig]);
                bf[1] = __float_as_uint(cK[n0 * AST + kk + ig + 4]);
                mma_tf32(s[0][nt], af[0], bf);
                mma_tf32(s[1][nt], af[1], bf);
            }
        }

        // ---- Online softmax per mt ----
#pragma unroll
        for (int mt = 0; mt < 2; mt++) {
            float mt0 = -1e30f, mt1 = -1e30f;
#pragma unroll
            for (int nt = 0; nt < 8; nt++) {
                mt0 = fmaxf(mt0, fmaxf(s[mt][nt][0], s[mt][nt][1]));
                mt1 = fmaxf(mt1, fmaxf(s[mt][nt][2], s[mt][nt][3]));
            }
            mt0 = fmaxf(mt0, __shfl_xor_sync(0xffffffffu, mt0, 1));
            mt0 = fmaxf(mt0, __shfl_xor_sync(0xffffffffu, mt0, 2));
            mt1 = fmaxf(mt1, __shfl_xor_sync(0xffffffffu, mt1, 1));
            mt1 = fmaxf(mt1, __shfl_xor_sync(0xffffffffu, mt1, 2));

            float mn0 = fmaxf(m[mt][0], mt0), mn1 = fmaxf(m[mt][1], mt1);
            float a0 = ex2(m[mt][0] - mn0), a1 = ex2(m[mt][1] - mn1);
            m[mt][0] = mn0; m[mt][1] = mn1;

            float rs0 = 0.0f, rs1 = 0.0f;
            int r0 = rr[mt];
#pragma unroll
            for (int nt = 0; nt < 8; nt++) {
                float p00 = ex2(s[mt][nt][0] - mn0);
                float p01 = ex2(s[mt][nt][1] - mn0);
                float p10 = ex2(s[mt][nt][2] - mn1);
                float p11 = ex2(s[mt][nt][3] - mn1);
                rs0 += p00 + p01;
                rs1 += p10 + p11;
                int c = nt * 8 + ig * 2;
                float2 q0; q0.x = to_tf32(p00); q0.y = to_tf32(p01);
                *(float2*)&sP[r0 * AST + c] = q0;
                float2 q1; q1.x = to_tf32(p10); q1.y = to_tf32(p11);
                *(float2*)&sP[(r0 + 8) * AST + c] = q1;
            }
            rs0 += __shfl_xor_sync(0xffffffffu, rs0, 1);
            rs0 += __shfl_xor_sync(0xffffffffu, rs0, 2);
            rs1 += __shfl_xor_sync(0xffffffffu, rs1, 1);
            rs1 += __shfl_xor_sync(0xffffffffu, rs1, 2);
            l[mt][0] = l[mt][0] * a0 + rs0;
            l[mt][1] = l[mt][1] * a1 + rs1;

#pragma unroll
            for (int nt = 0; nt < 8; nt++) {
                oacc[mt][nt][0] *= a0; oacc[mt][nt][1] *= a0;
                oacc[mt][nt][2] *= a1; oacc[mt][nt][3] *= a1;
            }
        }
        __syncwarp();

        // ---- oacc += P @ V (V row-major: B-frag (n0=d, k=key)) ----
#pragma unroll
        for (int kk = 0; kk < 64; kk += 8) {
            uint32_t af[2][4];
#pragma unroll
            for (int mt = 0; mt < 2; mt++) {
                int r0 = rr[mt];
                af[mt][0] = __float_as_uint(sP[r0 * AST + kk + ig]);
                af[mt][1] = __float_as_uint(sP[(r0 + 8) * AST + kk + ig]);
                af[mt][2] = __float_as_uint(sP[r0 * AST + kk + ig + 4]);
                af[mt][3] = __float_as_uint(sP[(r0 + 8) * AST + kk + ig + 4]);
            }
#pragma unroll
            for (int nt = 0; nt < 8; nt++) {
                int n0 = nt * 8 + gID;
                uint32_t bf[2];
                bf[0] = __float_as_uint(cV[(kk + ig) * VST + n0]);
                bf[1] = __float_as_uint(cV[(kk + ig + 4) * VST + n0]);
                mma_tf32(oacc[0][nt], af[0], bf);
                mma_tf32(oacc[1][nt], af[1], bf);
            }
        }
        __syncthreads();   // all warps done with cur K/V before next overwrite wait
    }

    // ---- Epilogue ----
#pragma unroll
    for (int mt = 0; mt < 2; mt++) {
        float inv0 = 1.0f / l[mt][0], inv1 = 1.0f / l[mt][1];
        const int grow = qt * QROWS + rr[mt];
#pragma unroll
        for (int nt = 0; nt < 8; nt++) {
            int col = h * HD + nt * 8 + ig * 2;
            float2 o0;
            o0.x = to_tf32(oacc[mt][nt][0] * inv0);
            o0.y = to_tf32(oacc[mt][nt][1] * inv0);
            *(float2*)&Op[((size_t)b * NQ + grow) * DM + col] = o0;
            float2 o1;
            o1.x = to_tf32(oacc[mt][nt][2] * inv1);
            o1.y = to_tf32(oacc[mt][nt][3] * inv1);
            *(float2*)&Op[((size_t)b * NQ + grow + 8) * DM + col] = o1;
        }
    }
}

// ---------------------------------------------------------------------------
// Launch
// ---------------------------------------------------------------------------
extern "C" void kernel_launch(void* const* d_in, const int* in_sizes, int n_in,
                              void* d_out, int out_size)
{
    const float* queries = (const float*)d_in[0];
    const float* keys    = (const float*)d_in[1];
    const float* values  = (const float*)d_in[2];
    const float* Wq      = (const float*)d_in[3];
    const float* Wk      = (const float*)d_in[4];
    const float* Wv      = (const float*)d_in[5];
    const float* Wo      = (const float*)d_in[6];
    const float* bo      = (const float*)d_in[7];
    float* out           = (float*)d_out;

    float *Qp, *Kp, *Vp, *Op, *WT, *IN;
    cudaGetSymbolAddress((void**)&Qp, g_Q);
    cudaGetSymbolAddress((void**)&Kp, g_K);
    cudaGetSymbolAddress((void**)&Vp, g_V);
    cudaGetSymbolAddress((void**)&Op, g_O);
    cudaGetSymbolAddress((void**)&WT, g_WT);
    cudaGetSymbolAddress((void**)&IN, g_IN);

    static bool attr_set = false;
    if (!attr_set) {
        cudaFuncSetAttribute(attn_mma,
                             cudaFuncAttributeMaxDynamicSharedMemorySize, SMEM_ATT);
        cudaFuncSetAttribute(gemm_qkv,
                             cudaFuncAttributeMaxDynamicSharedMemorySize, SMEM_GEMM);
        cudaFuncSetAttribute(gemm_out,
                             cudaFuncAttributeMaxDynamicSharedMemorySize, SMEM_GEMM);
        attr_set = true;
    }

    dim3 tgrid(DM / 32, DM / 32, 4), tblk(32, 8);
    transpose4_tf32<<<tgrid, tblk>>>(Wq, Wk, Wv, Wo, WT);

    dim3 rgrid(512, 1, 3);
    round3<<<rgrid, 256>>>(queries, keys, values, IN);

    dim3 qgrid(DM / GBN, MROWS / GBM, 3);
    gemm_qkv<<<qgrid, 256, SMEM_GEMM>>>(IN, WT, Qp, Kp, Vp);

    dim3 agrid(NQ / QROWS, NH, BATCH);  // (8, 16, 4)
    attn_mma<<<agrid, 256, SMEM_ATT>>>(Qp, Kp, Vp, Op);

    dim3 ogrid(DM / GBN, MROWS / GBM);
    gemm_out<<<ogrid, 256, SMEM_GEMM>>>(Op, WT + 3 * (size_t)DM * DM, bo, out);
}

// round 8
// speedup vs baseline: 3.8043x; 1.0990x over previous
#include <cuda_runtime.h>
#include <math.h>
#include <stdint.h>

#define BATCH 4
#define NQ 2048
#define NK 2048
#define DM 1024
#define NH 16
#define HD 64
#define MROWS (BATCH * NQ)   // 8192

// Scratch
__device__ float g_Q[BATCH * NQ * DM];
__device__ float g_K[BATCH * NK * DM];
__device__ float g_V[BATCH * NK * DM];
__device__ float g_O[BATCH * NQ * DM];
__device__ float g_WT[4 * DM * DM];          // transposed + tf32(RNA) weights
__device__ float g_IN[3 * MROWS * DM];       // tf32(RNA)-rounded inputs q/k/v

__device__ __forceinline__ float to_tf32(float x) {
    float r;
    asm("cvt.rna.tf32.f32 %0, %1;" : "=f"(r) : "f"(x));
    return r;
}

__device__ __forceinline__ float ex2(float x) {
    float r;
    asm("ex2.approx.ftz.f32 %0, %1;" : "=f"(r) : "f"(x));
    return r;
}

__device__ __forceinline__ void mma_tf32(float* c, const uint32_t* a, const uint32_t* b) {
    asm volatile(
        "mma.sync.aligned.m16n8k8.row.col.f32.tf32.tf32.f32 "
        "{%0,%1,%2,%3}, {%4,%5,%6,%7}, {%8,%9}, {%0,%1,%2,%3};"
        : "+f"(c[0]), "+f"(c[1]), "+f"(c[2]), "+f"(c[3])
        : "r"(a[0]), "r"(a[1]), "r"(a[2]), "r"(a[3]), "r"(b[0]), "r"(b[1]));
}

__device__ __forceinline__ uint32_t smem_u32(const void* p) {
    uint32_t a;
    asm("{ .reg .u64 t; cvta.to.shared.u64 t, %1; cvt.u32.u64 %0, t; }"
        : "=r"(a) : "l"(p));
    return a;
}

__device__ __forceinline__ void cp16(uint32_t dst, const void* src) {
    asm volatile("cp.async.ca.shared.global [%0], [%1], 16;" :: "r"(dst), "l"(src));
}
#define CP_COMMIT() asm volatile("cp.async.commit_group;" ::: "memory")
#define CP_WAIT(n)  asm volatile("cp.async.wait_group %0;" :: "n"(n) : "memory")

// ---------------------------------------------------------------------------
// Weight transpose (+ tf32 RNA): W[K][N] -> WT[N][K]; z selects one of 4.
// ---------------------------------------------------------------------------
__global__ void transpose4_tf32(const float* __restrict__ W0, const float* __restrict__ W1,
                                const float* __restrict__ W2, const float* __restrict__ W3,
                                float* __restrict__ WT)
{
    __shared__ float t[32][33];
    const int z = blockIdx.z;
    const float* W = (z == 0) ? W0 : (z == 1) ? W1 : (z == 2) ? W2 : W3;
    float* WTz = WT + (size_t)z * DM * DM;
    int bx = blockIdx.x * 32, by = blockIdx.y * 32;
    for (int j = threadIdx.y; j < 32; j += 8)
        t[j][threadIdx.x] = W[(size_t)(by + j) * DM + bx + threadIdx.x];
    __syncthreads();
    for (int j = threadIdx.y; j < 32; j += 8)
        WTz[(size_t)(bx + j) * DM + by + threadIdx.x] = to_tf32(t[threadIdx.x][j]);
}

// ---------------------------------------------------------------------------
// tf32 RNA rounding prepass for the 3 input activations
// ---------------------------------------------------------------------------
__global__ __launch_bounds__(256) void round3(
    const float* __restrict__ q, const float* __restrict__ k,
    const float* __restrict__ v, float* __restrict__ dst)
{
    const int z = blockIdx.z;
    const float* src = (z == 0) ? q : (z == 1) ? k : v;
    float* d = dst + (size_t)z * MROWS * DM;
    const size_t n4 = (size_t)MROWS * DM / 4;
    for (size_t i = blockIdx.x * 256 + threadIdx.x; i < n4; i += (size_t)gridDim.x * 256) {
        float4 x = ((const float4*)src)[i];
        x.x = to_tf32(x.x); x.y = to_tf32(x.y);
        x.z = to_tf32(x.z); x.w = to_tf32(x.w);
        ((float4*)d)[i] = x;
    }
}

// ---------------------------------------------------------------------------
// TF32 mma GEMM core with 2-stage cp.async pipeline. Now capped at 128 regs
// for 2 CTAs/SM.
// ---------------------------------------------------------------------------
#define GBM 128
#define GBN 128
#define GBK 32
#define SSTRIDE 36
#define TILE_FLOATS (GBM * SSTRIDE)
#define STAGE_FLOATS (2 * TILE_FLOATS)
#define SMEM_GEMM (2 * STAGE_FLOATS * 4)

__device__ __forceinline__ void gemm_stage_issue(
    const float* __restrict__ A, const float* __restrict__ BT,
    int bm, int bn, int k0, uint32_t sA_addr, uint32_t sB_addr, int tid)
{
#pragma unroll
    for (int i = 0; i < 4; i++) {
        int idx = tid + i * 256;
        int r = idx >> 3;
        int c4 = idx & 7;
        uint32_t off = (uint32_t)(r * SSTRIDE + c4 * 4) * 4;
        cp16(sA_addr + off, &A[(size_t)(bm + r) * DM + k0 + c4 * 4]);
        cp16(sB_addr + off, &BT[(size_t)(bn + r) * DM + k0 + c4 * 4]);
    }
    CP_COMMIT();
}

__device__ __forceinline__ void gemm_core(
    const float* __restrict__ A, const float* __restrict__ BT,
    const float* __restrict__ bias, float* __restrict__ C,
    bool round_c, float* dsm)
{
    const uint32_t sbase = smem_u32(dsm);
    const int tid = threadIdx.x;
    const int wid = tid >> 5;
    const int lane = tid & 31;
    const int gID = lane >> 2;
    const int ig  = lane & 3;
    const int warp_m = wid >> 2;
    const int warp_n = wid & 3;
    const int bm = blockIdx.y * GBM;
    const int bn = blockIdx.x * GBN;

    float acc[4][4][4];
#pragma unroll
    for (int i = 0; i < 4; i++)
#pragma unroll
        for (int j = 0; j < 4; j++)
#pragma unroll
            for (int v = 0; v < 4; v++) acc[i][j][v] = 0.0f;

    const int kSteps = DM / GBK;

    gemm_stage_issue(A, BT, bm, bn, 0, sbase, sbase + TILE_FLOATS * 4, tid);

    for (int kt = 0; kt < kSteps; kt++) {
        const int cur = kt & 1;
        if (kt + 1 < kSteps) {
            const int nxt = (kt + 1) & 1;
            gemm_stage_issue(A, BT, bm, bn, (kt + 1) * GBK,
                             sbase + nxt * STAGE_FLOATS * 4,
                             sbase + (nxt * STAGE_FLOATS + TILE_FLOATS) * 4, tid);
            CP_WAIT(1);
        } else {
            CP_WAIT(0);
        }
        __syncthreads();

        const float* sA = dsm + cur * STAGE_FLOATS;
        const float* sB = sA + TILE_FLOATS;

#pragma unroll
        for (int kk = 0; kk < GBK; kk += 8) {
            uint32_t afrag[4][4];
#pragma unroll
            for (int mt = 0; mt < 4; mt++) {
                int r0 = warp_m * 64 + mt * 16 + gID;
                afrag[mt][0] = __float_as_uint(sA[r0 * SSTRIDE + kk + ig]);
                afrag[mt][1] = __float_as_uint(sA[(r0 + 8) * SSTRIDE + kk + ig]);
                afrag[mt][2] = __float_as_uint(sA[r0 * SSTRIDE + kk + ig + 4]);
                afrag[mt][3] = __float_as_uint(sA[(r0 + 8) * SSTRIDE + kk + ig + 4]);
            }
            uint32_t bfrag[4][2];
#pragma unroll
            for (int nt = 0; nt < 4; nt++) {
                int n0 = warp_n * 32 + nt * 8 + gID;
                bfrag[nt][0] = __float_as_uint(sB[n0 * SSTRIDE + kk + ig]);
                bfrag[nt][1] = __float_as_uint(sB[n0 * SSTRIDE + kk + ig + 4]);
            }
#pragma unroll
            for (int mt = 0; mt < 4; mt++)
#pragma unroll
                for (int nt = 0; nt < 4; nt++)
                    mma_tf32(acc[mt][nt], afrag[mt], bfrag[nt]);
        }
        __syncthreads();
    }

#pragma unroll
    for (int mt = 0; mt < 4; mt++) {
#pragma unroll
        for (int nt = 0; nt < 4; nt++) {
            int row = bm + warp_m * 64 + mt * 16 + gID;
            int col = bn + warp_n * 32 + nt * 8 + ig * 2;
            float2 v0, v1;
            v0.x = acc[mt][nt][0]; v0.y = acc[mt][nt][1];
            v1.x = acc[mt][nt][2]; v1.y = acc[mt][nt][3];
            if (bias) {
                float b0 = bias[col], b1 = bias[col + 1];
                v0.x += b0; v0.y += b1;
                v1.x += b0; v1.y += b1;
            }
            if (round_c) {
                v0.x = to_tf32(v0.x); v0.y = to_tf32(v0.y);
                v1.x = to_tf32(v1.x); v1.y = to_tf32(v1.y);
            }
            *(float2*)&C[(size_t)row * DM + col] = v0;
            *(float2*)&C[(size_t)(row + 8) * DM + col] = v1;
        }
    }
}

__global__ __launch_bounds__(256, 2) void gemm_qkv(
    const float* __restrict__ IN, const float* __restrict__ WT,
    float* __restrict__ Qo, float* __restrict__ Ko, float* __restrict__ Vo)
{
    extern __shared__ float dsm[];
    const int z = blockIdx.z;
    const float* A = IN + (size_t)z * MROWS * DM;
    const float* BT = WT + (size_t)z * DM * DM;
    float* C = (z == 0) ? Qo : (z == 1) ? Ko : Vo;
    gemm_core(A, BT, nullptr, C, true, dsm);
}

__global__ __launch_bounds__(256, 2) void gemm_out(
    const float* __restrict__ A, const float* __restrict__ BT,
    const float* __restrict__ bias, float* __restrict__ C)
{
    extern __shared__ float dsm[];
    gemm_core(A, BT, bias, C, false, dsm);
}

// ---------------------------------------------------------------------------
// Tensor-core flash attention, rev 3.
// CTA = 128 q-rows x (head, batch); 8 warps, warp = 16 rows (mt=1).
// Q lives in registers (qf[8][4]); sP only 128 rows; K/V double-buffered
// cp.async. smem = 106.5 KB -> 2 CTAs/SM (16 warps/SM), regs capped 128.
// ---------------------------------------------------------------------------
#define QROWS 128
#define AST 68
#define VST 72
#define KTILE 64
#define SP_F (QROWS * AST)
#define SK_F (KTILE * AST)
#define SV_F (KTILE * VST)
#define SMEM_ATT ((SP_F + 2 * SK_F + 2 * SV_F) * 4)   // 106496 bytes

__device__ __forceinline__ void attn_stage_issue(
    const float* __restrict__ Kp, const float* __restrict__ Vp,
    int b, int h, int kt, uint32_t sK_addr, uint32_t sV_addr, int tid)
{
    const float* Kbase = Kp + ((size_t)b * NK + kt * KTILE) * DM + h * HD;
    const float* Vbase = Vp + ((size_t)b * NK + kt * KTILE) * DM + h * HD;
#pragma unroll
    for (int i = 0; i < 4; i++) {
        int idx = tid + i * 256;
        int r = idx >> 4;      // 0..63
        int c4 = idx & 15;     // 0..15
        cp16(sK_addr + (uint32_t)(r * AST + c4 * 4) * 4, &Kbase[(size_t)r * DM + c4 * 4]);
        cp16(sV_addr + (uint32_t)(r * VST + c4 * 4) * 4, &Vbase[(size_t)r * DM + c4 * 4]);
    }
    CP_COMMIT();
}

__global__ __launch_bounds__(256, 2) void attn_mma(
    const float* __restrict__ Qp, const float* __restrict__ Kp,
    const float* __restrict__ Vp, float* __restrict__ Op)
{
    extern __shared__ float sm[];
    float* sP = sm;                 // [128][AST]; doubles as Q staging
    float* sK = sP + SP_F;          // 2 x [64][AST]
    float* sV = sK + 2 * SK_F;      // 2 x [64][VST]
    const uint32_t sKa = smem_u32(sK);
    const uint32_t sVa = smem_u32(sV);

    const int tid = threadIdx.x;
    const int wid = tid >> 5;
    const int lane = tid & 31;
    const int gID = lane >> 2;
    const int ig  = lane & 3;
    const int qt = blockIdx.x;
    const int h  = blockIdx.y;
    const int b  = blockIdx.z;

    const float scale = 0.03125f * 1.4426950408889634f;  // 1/sqrt(1024) * log2(e)
    const int r0 = wid * 16 + gID;   // warp's first q-row (in tile)

    // Kick off K/V tile 0 before anything else
    attn_stage_issue(Kp, Vp, b, h, 0, sKa, sVa, tid);

    // Stage Q into sP (scaled, tf32), bounce into registers
    const float* Qbase = Qp + ((size_t)b * NQ + qt * QROWS) * DM + h * HD;
    for (int i = tid; i < QROWS * 16; i += 256) {
        int r = i >> 4, c4 = i & 15;
        float4 v = *(const float4*)&Qbase[(size_t)r * DM + c4 * 4];
        v.x = to_tf32(v.x * scale); v.y = to_tf32(v.y * scale);
        v.z = to_tf32(v.z * scale); v.w = to_tf32(v.w * scale);
        *(float4*)&sP[r * AST + c4 * 4] = v;
    }
    __syncthreads();

    uint32_t qf[8][4];
#pragma unroll
    for (int k8 = 0; k8 < 8; k8++) {
        int kk = k8 * 8;
        qf[k8][0] = __float_as_uint(sP[r0 * AST + kk + ig]);
        qf[k8][1] = __float_as_uint(sP[(r0 + 8) * AST + kk + ig]);
        qf[k8][2] = __float_as_uint(sP[r0 * AST + kk + ig + 4]);
        qf[k8][3] = __float_as_uint(sP[(r0 + 8) * AST + kk + ig + 4]);
    }
    __syncthreads();   // everyone has Q in regs; sP is now free for P

    float m0 = -1e30f, m1 = -1e30f, l0 = 0.0f, l1 = 0.0f;
    float oacc[8][4];
#pragma unroll
    for (int nt = 0; nt < 8; nt++)
#pragma unroll
        for (int v = 0; v < 4; v++) oacc[nt][v] = 0.0f;

    const int nTiles = NK / KTILE;   // 32
    for (int kt = 0; kt < nTiles; kt++) {
        const int cur = kt & 1;
        CP_WAIT(0);
        __syncthreads();
        if (kt + 1 < nTiles) {
            const int nxt = (kt + 1) & 1;
            attn_stage_issue(Kp, Vp, b, h, kt + 1,
                             sKa + nxt * SK_F * 4, sVa + nxt * SV_F * 4, tid);
        }
        const float* cK = sK + cur * SK_F;
        const float* cV = sV + cur * SV_F;

        // ---- S = Q @ K^T : A-frags from registers, B-frags from sK ----
        float s[8][4];
#pragma unroll
        for (int nt = 0; nt < 8; nt++)
#pragma unroll
            for (int v = 0; v < 4; v++) s[nt][v] = 0.0f;

#pragma unroll
        for (int k8 = 0; k8 < 8; k8++) {
            const int kk = k8 * 8;
#pragma unroll
            for (int nt = 0; nt < 8; nt++) {
                int n0 = nt * 8 + gID;
                uint32_t bf[2];
                bf[0] = __float_as_uint(cK[n0 * AST + kk + ig]);
                bf[1] = __float_as_uint(cK[n0 * AST + kk + ig + 4]);
                mma_tf32(s[nt], qf[k8], bf);
            }
        }

        // ---- Online softmax (rows r0, r0+8) ----
        float mt0 = -1e30f, mt1 = -1e30f;
#pragma unroll
        for (int nt = 0; nt < 8; nt++) {
            mt0 = fmaxf(mt0, fmaxf(s[nt][0], s[nt][1]));
            mt1 = fmaxf(mt1, fmaxf(s[nt][2], s[nt][3]));
        }
        mt0 = fmaxf(mt0, __shfl_xor_sync(0xffffffffu, mt0, 1));
        mt0 = fmaxf(mt0, __shfl_xor_sync(0xffffffffu, mt0, 2));
        mt1 = fmaxf(mt1, __shfl_xor_sync(0xffffffffu, mt1, 1));
        mt1 = fmaxf(mt1, __shfl_xor_sync(0xffffffffu, mt1, 2));

        float mn0 = fmaxf(m0, mt0), mn1 = fmaxf(m1, mt1);
        float a0 = ex2(m0 - mn0), a1 = ex2(m1 - mn1);
        m0 = mn0; m1 = mn1;

        float rs0 = 0.0f, rs1 = 0.0f;
#pragma unroll
        for (int nt = 0; nt < 8; nt++) {
            float p00 = ex2(s[nt][0] - mn0);
            float p01 = ex2(s[nt][1] - mn0);
            float p10 = ex2(s[nt][2] - mn1);
            float p11 = ex2(s[nt][3] - mn1);
            rs0 += p00 + p01;
            rs1 += p10 + p11;
            int c = nt * 8 + ig * 2;
            float2 q0; q0.x = to_tf32(p00); q0.y = to_tf32(p01);
            *(float2*)&sP[r0 * AST + c] = q0;
            float2 q1; q1.x = to_tf32(p10); q1.y = to_tf32(p11);
            *(float2*)&sP[(r0 + 8) * AST + c] = q1;
        }
        rs0 += __shfl_xor_sync(0xffffffffu, rs0, 1);
        rs0 += __shfl_xor_sync(0xffffffffu, rs0, 2);
        rs1 += __shfl_xor_sync(0xffffffffu, rs1, 1);
        rs1 += __shfl_xor_sync(0xffffffffu, rs1, 2);
        l0 = l0 * a0 + rs0;
        l1 = l1 * a1 + rs1;

#pragma unroll
        for (int nt = 0; nt < 8; nt++) {
            oacc[nt][0] *= a0; oacc[nt][1] *= a0;
            oacc[nt][2] *= a1; oacc[nt][3] *= a1;
        }
        __syncwarp();   // warp-private sP slab

        // ---- oacc += P @ V (V row-major) ----
#pragma unroll
        for (int k8 = 0; k8 < 8; k8++) {
            const int kk = k8 * 8;
            uint32_t af[4];
            af[0] = __float_as_uint(sP[r0 * AST + kk + ig]);
            af[1] = __float_as_uint(sP[(r0 + 8) * AST + kk + ig]);
            af[2] = __float_as_uint(sP[r0 * AST + kk + ig + 4]);
            af[3] = __float_as_uint(sP[(r0 + 8) * AST + kk + ig + 4]);
#pragma unroll
            for (int nt = 0; nt < 8; nt++) {
                int n0 = nt * 8 + gID;
                uint32_t bf[2];
                bf[0] = __float_as_uint(cV[(kk + ig) * VST + n0]);
                bf[1] = __float_as_uint(cV[(kk + ig + 4) * VST + n0]);
                mma_tf32(oacc[nt], af, bf);
            }
        }
        __syncthreads();   // all warps done with cur K/V before next wait
    }

    // ---- Epilogue ----
    float inv0 = 1.0f / l0, inv1 = 1.0f / l1;
    const int grow = qt * QROWS + r0;
#pragma unroll
    for (int nt = 0; nt < 8; nt++) {
        int col = h * HD + nt * 8 + ig * 2;
        float2 o0;
        o0.x = to_tf32(oacc[nt][0] * inv0);
        o0.y = to_tf32(oacc[nt][1] * inv0);
        *(float2*)&Op[((size_t)b * NQ + grow) * DM + col] = o0;
        float2 o1;
        o1.x = to_tf32(oacc[nt][2] * inv1);
        o1.y = to_tf32(oacc[nt][3] * inv1);
        *(float2*)&Op[((size_t)b * NQ + grow + 8) * DM + col] = o1;
    }
}

// ---------------------------------------------------------------------------
// Launch
// ---------------------------------------------------------------------------
extern "C" void kernel_launch(void* const* d_in, const int* in_sizes, int n_in,
                              void* d_out, int out_size)
{
    const float* queries = (const float*)d_in[0];
    const float* keys    = (const float*)d_in[1];
    const float* values  = (const float*)d_in[2];
    const float* Wq      = (const float*)d_in[3];
    const float* Wk      = (const float*)d_in[4];
    const float* Wv      = (const float*)d_in[5];
    const float* Wo      = (const float*)d_in[6];
    const float* bo      = (const float*)d_in[7];
    float* out           = (float*)d_out;

    float *Qp, *Kp, *Vp, *Op, *WT, *IN;
    cudaGetSymbolAddress((void**)&Qp, g_Q);
    cudaGetSymbolAddress((void**)&Kp, g_K);
    cudaGetSymbolAddress((void**)&Vp, g_V);
    cudaGetSymbolAddress((void**)&Op, g_O);
    cudaGetSymbolAddress((void**)&WT, g_WT);
    cudaGetSymbolAddress((void**)&IN, g_IN);

    static bool attr_set = false;
    if (!attr_set) {
        cudaFuncSetAttribute(attn_mma,
                             cudaFuncAttributeMaxDynamicSharedMemorySize, SMEM_ATT);
        cudaFuncSetAttribute(gemm_qkv,
                             cudaFuncAttributeMaxDynamicSharedMemorySize, SMEM_GEMM);
        cudaFuncSetAttribute(gemm_out,
                             cudaFuncAttributeMaxDynamicSharedMemorySize, SMEM_GEMM);
        attr_set = true;
    }

    dim3 tgrid(DM / 32, DM / 32, 4), tblk(32, 8);
    transpose4_tf32<<<tgrid, tblk>>>(Wq, Wk, Wv, Wo, WT);

    dim3 rgrid(512, 1, 3);
    round3<<<rgrid, 256>>>(queries, keys, values, IN);

    dim3 qgrid(DM / GBN, MROWS / GBM, 3);
    gemm_qkv<<<qgrid, 256, SMEM_GEMM>>>(IN, WT, Qp, Kp, Vp);

    dim3 agrid(NQ / QROWS, NH, BATCH);  // (16, 16, 4)
    attn_mma<<<agrid, 256, SMEM_ATT>>>(Qp, Kp, Vp, Op);

    dim3 ogrid(DM / GBN, MROWS / GBM);
    gemm_out<<<ogrid, 256, SMEM_GEMM>>>(Op, WT + 3 * (size_t)DM * DM, bo, out);
}

// round 9
// speedup vs baseline: 4.3245x; 1.1368x over previous
#include <cuda_runtime.h>
#include <cuda_bf16.h>
#include <math.h>
#include <stdint.h>

#define BATCH 4
#define NQ 2048
#define NK 2048
#define DM 1024
#define NH 16
#define HD 64
#define MROWS (BATCH * NQ)   // 8192

// Scratch
__device__ __nv_bfloat16 g_Qh[MROWS * DM];   // Q projection, bf16, pre-scaled
__device__ __nv_bfloat16 g_Kh[MROWS * DM];   // K projection, bf16
__device__ float g_V[MROWS * DM];            // V projection, tf32-rounded fp32
__device__ float g_O[MROWS * DM];            // attention out, tf32-rounded
__device__ float g_WT[4 * DM * DM];          // transposed + tf32(RNA) weights
__device__ float g_IN[3 * MROWS * DM];       // tf32(RNA)-rounded inputs q/k/v

#define QSCALE (0.03125f * 1.4426950408889634f)   // 1/sqrt(1024) * log2(e)

__device__ __forceinline__ float to_tf32(float x) {
    float r;
    asm("cvt.rna.tf32.f32 %0, %1;" : "=f"(r) : "f"(x));
    return r;
}

__device__ __forceinline__ float ex2(float x) {
    float r;
    asm("ex2.approx.ftz.f32 %0, %1;" : "=f"(r) : "f"(x));
    return r;
}

__device__ __forceinline__ void mma_tf32(float* c, const uint32_t* a, const uint32_t* b) {
    asm volatile(
        "mma.sync.aligned.m16n8k8.row.col.f32.tf32.tf32.f32 "
        "{%0,%1,%2,%3}, {%4,%5,%6,%7}, {%8,%9}, {%0,%1,%2,%3};"
        : "+f"(c[0]), "+f"(c[1]), "+f"(c[2]), "+f"(c[3])
        : "r"(a[0]), "r"(a[1]), "r"(a[2]), "r"(a[3]), "r"(b[0]), "r"(b[1]));
}

__device__ __forceinline__ void mma_bf16(float* c, const uint32_t* a, const uint32_t* b) {
    asm volatile(
        "mma.sync.aligned.m16n8k16.row.col.f32.bf16.bf16.f32 "
        "{%0,%1,%2,%3}, {%4,%5,%6,%7}, {%8,%9}, {%0,%1,%2,%3};"
        : "+f"(c[0]), "+f"(c[1]), "+f"(c[2]), "+f"(c[3])
        : "r"(a[0]), "r"(a[1]), "r"(a[2]), "r"(a[3]), "r"(b[0]), "r"(b[1]));
}

__device__ __forceinline__ uint32_t smem_u32(const void* p) {
    uint32_t a;
    asm("{ .reg .u64 t; cvta.to.shared.u64 t, %1; cvt.u32.u64 %0, t; }"
        : "=r"(a) : "l"(p));
    return a;
}

__device__ __forceinline__ void cp16(uint32_t dst, const void* src) {
    asm volatile("cp.async.ca.shared.global [%0], [%1], 16;" :: "r"(dst), "l"(src));
}
#define CP_COMMIT() asm volatile("cp.async.commit_group;" ::: "memory")
#define CP_WAIT(n)  asm volatile("cp.async.wait_group %0;" :: "n"(n) : "memory")

// ---------------------------------------------------------------------------
// Weight transpose (+ tf32 RNA): W[K][N] -> WT[N][K]; z selects one of 4.
// ---------------------------------------------------------------------------
__global__ void transpose4_tf32(const float* __restrict__ W0, const float* __restrict__ W1,
                                const float* __restrict__ W2, const float* __restrict__ W3,
                                float* __restrict__ WT)
{
    __shared__ float t[32][33];
    const int z = blockIdx.z;
    const float* W = (z == 0) ? W0 : (z == 1) ? W1 : (z == 2) ? W2 : W3;
    float* WTz = WT + (size_t)z * DM * DM;
    int bx = blockIdx.x * 32, by = blockIdx.y * 32;
    for (int j = threadIdx.y; j < 32; j += 8)
        t[j][threadIdx.x] = W[(size_t)(by + j) * DM + bx + threadIdx.x];
    __syncthreads();
    for (int j = threadIdx.y; j < 32; j += 8)
        WTz[(size_t)(bx + j) * DM + by + threadIdx.x] = to_tf32(t[threadIdx.x][j]);
}

// ---------------------------------------------------------------------------
// tf32 RNA rounding prepass for the 3 input activations
// ---------------------------------------------------------------------------
__global__ __launch_bounds__(256) void round3(
    const float* __restrict__ q, const float* __restrict__ k,
    const float* __restrict__ v, float* __restrict__ dst)
{
    const int z = blockIdx.z;
    const float* src = (z == 0) ? q : (z == 1) ? k : v;
    float* d = dst + (size_t)z * MROWS * DM;
    const size_t n4 = (size_t)MROWS * DM / 4;
    for (size_t i = blockIdx.x * 256 + threadIdx.x; i < n4; i += (size_t)gridDim.x * 256) {
        float4 x = ((const float4*)src)[i];
        x.x = to_tf32(x.x); x.y = to_tf32(x.y);
        x.z = to_tf32(x.z); x.w = to_tf32(x.w);
        ((float4*)d)[i] = x;
    }
}

// ---------------------------------------------------------------------------
// TF32 mma GEMM core, 2-stage cp.async pipeline.
// Epilogue mode: 0 = fp32 (+bias); 1 = fp32 tf32-rounded; 2 = bf16; 3 = bf16*QSCALE
// ---------------------------------------------------------------------------
#define GBM 128
#define GBN 128
#define GBK 32
#define SSTRIDE 36
#define TILE_FLOATS (GBM * SSTRIDE)
#define STAGE_FLOATS (2 * TILE_FLOATS)
#define SMEM_GEMM (2 * STAGE_FLOATS * 4)

__device__ __forceinline__ void gemm_stage_issue(
    const float* __restrict__ A, const float* __restrict__ BT,
    int bm, int bn, int k0, uint32_t sA_addr, uint32_t sB_addr, int tid)
{
#pragma unroll
    for (int i = 0; i < 4; i++) {
        int idx = tid + i * 256;
        int r = idx >> 3;
        int c4 = idx & 7;
        uint32_t off = (uint32_t)(r * SSTRIDE + c4 * 4) * 4;
        cp16(sA_addr + off, &A[(size_t)(bm + r) * DM + k0 + c4 * 4]);
        cp16(sB_addr + off, &BT[(size_t)(bn + r) * DM + k0 + c4 * 4]);
    }
    CP_COMMIT();
}

__device__ __forceinline__ void gemm_core(
    const float* __restrict__ A, const float* __restrict__ BT,
    const float* __restrict__ bias, void* __restrict__ Cv,
    int mode, float* dsm)
{
    const uint32_t sbase = smem_u32(dsm);
    const int tid = threadIdx.x;
    const int wid = tid >> 5;
    const int lane = tid & 31;
    const int gID = lane >> 2;
    const int ig  = lane & 3;
    const int warp_m = wid >> 2;
    const int warp_n = wid & 3;
    const int bm = blockIdx.y * GBM;
    const int bn = blockIdx.x * GBN;

    float acc[4][4][4];
#pragma unroll
    for (int i = 0; i < 4; i++)
#pragma unroll
        for (int j = 0; j < 4; j++)
#pragma unroll
            for (int v = 0; v < 4; v++) acc[i][j][v] = 0.0f;

    const int kSteps = DM / GBK;

    gemm_stage_issue(A, BT, bm, bn, 0, sbase, sbase + TILE_FLOATS * 4, tid);

    for (int kt = 0; kt < kSteps; kt++) {
        const int cur = kt & 1;
        if (kt + 1 < kSteps) {
            const int nxt = (kt + 1) & 1;
            gemm_stage_issue(A, BT, bm, bn, (kt + 1) * GBK,
                             sbase + nxt * STAGE_FLOATS * 4,
                             sbase + (nxt * STAGE_FLOATS + TILE_FLOATS) * 4, tid);
            CP_WAIT(1);
        } else {
            CP_WAIT(0);
        }
        __syncthreads();

        const float* sA = dsm + cur * STAGE_FLOATS;
        const float* sB = sA + TILE_FLOATS;

#pragma unroll
        for (int kk = 0; kk < GBK; kk += 8) {
            uint32_t afrag[4][4];
#pragma unroll
            for (int mt = 0; mt < 4; mt++) {
                int r0 = warp_m * 64 + mt * 16 + gID;
                afrag[mt][0] = __float_as_uint(sA[r0 * SSTRIDE + kk + ig]);
                afrag[mt][1] = __float_as_uint(sA[(r0 + 8) * SSTRIDE + kk + ig]);
                afrag[mt][2] = __float_as_uint(sA[r0 * SSTRIDE + kk + ig + 4]);
                afrag[mt][3] = __float_as_uint(sA[(r0 + 8) * SSTRIDE + kk + ig + 4]);
            }
            uint32_t bfrag[4][2];
#pragma unroll
            for (int nt = 0; nt < 4; nt++) {
                int n0 = warp_n * 32 + nt * 8 + gID;
                bfrag[nt][0] = __float_as_uint(sB[n0 * SSTRIDE + kk + ig]);
                bfrag[nt][1] = __float_as_uint(sB[n0 * SSTRIDE + kk + ig + 4]);
            }
#pragma unroll
            for (int mt = 0; mt < 4; mt++)
#pragma unroll
                for (int nt = 0; nt < 4; nt++)
                    mma_tf32(acc[mt][nt], afrag[mt], bfrag[nt]);
        }
        __syncthreads();
    }

#pragma unroll
    for (int mt = 0; mt < 4; mt++) {
#pragma unroll
        for (int nt = 0; nt < 4; nt++) {
            int row = bm + warp_m * 64 + mt * 16 + gID;
            int col = bn + warp_n * 32 + nt * 8 + ig * 2;
            float2 v0, v1;
            v0.x = acc[mt][nt][0]; v0.y = acc[mt][nt][1];
            v1.x = acc[mt][nt][2]; v1.y = acc[mt][nt][3];
            if (mode == 0 && bias) {
                float b0 = bias[col], b1 = bias[col + 1];
                v0.x += b0; v0.y += b1;
                v1.x += b0; v1.y += b1;
            }
            if (mode <= 1) {
                float* C = (float*)Cv;
                if (mode == 1) {
                    v0.x = to_tf32(v0.x); v0.y = to_tf32(v0.y);
                    v1.x = to_tf32(v1.x); v1.y = to_tf32(v1.y);
                }
                *(float2*)&C[(size_t)row * DM + col] = v0;
                *(float2*)&C[(size_t)(row + 8) * DM + col] = v1;
            } else {
                __nv_bfloat16* C = (__nv_bfloat16*)Cv;
                if (mode == 3) {
                    v0.x *= QSCALE; v0.y *= QSCALE;
                    v1.x *= QSCALE; v1.y *= QSCALE;
                }
                *(__nv_bfloat162*)&C[(size_t)row * DM + col] =
                    __float22bfloat162_rn(v0);
                *(__nv_bfloat162*)&C[(size_t)(row + 8) * DM + col] =
                    __float22bfloat162_rn(v1);
            }
        }
    }
}

__global__ __launch_bounds__(256, 2) void gemm_qkv(
    const float* __restrict__ IN, const float* __restrict__ WT,
    __nv_bfloat16* __restrict__ Qo, __nv_bfloat16* __restrict__ Ko,
    float* __restrict__ Vo)
{
    extern __shared__ float dsm[];
    const int z = blockIdx.z;
    const float* A = IN + (size_t)z * MROWS * DM;
    const float* BT = WT + (size_t)z * DM * DM;
    if (z == 0)      gemm_core(A, BT, nullptr, Qo, 3, dsm);
    else if (z == 1) gemm_core(A, BT, nullptr, Ko, 2, dsm);
    else             gemm_core(A, BT, nullptr, Vo, 1, dsm);
}

__global__ __launch_bounds__(256, 2) void gemm_out(
    const float* __restrict__ A, const float* __restrict__ BT,
    const float* __restrict__ bias, float* __restrict__ C)
{
    extern __shared__ float dsm[];
    gemm_core(A, BT, bias, C, 0, dsm);
}

// ---------------------------------------------------------------------------
// Flash attention, rev 4: bf16 QK (m16n8k16), tf32 PV (m16n8k8).
// CTA = 128 q-rows, 8 warps (warp = 16 rows). Q in regs (packed bf16).
// K (bf16) and V (fp32) double-buffered cp.async. smem ~88 KB -> 2 CTAs/SM.
// ---------------------------------------------------------------------------
#define QROWS 128
#define PST 68      // P stride (floats)
#define KST 72      // K stride (bf16 elements) -> 144 B/row
#define VST 72      // V stride (floats)        -> 288 B/row
#define KTILE 64
#define SP_F (QROWS * PST)                 // floats
#define SK_H (KTILE * KST)                 // bf16 elems per K buffer
#define SV_F (KTILE * VST)                 // floats per V buffer
// layout: sP | sV[2] | sKh[2]
#define SMEM_ATT (SP_F * 4 + 2 * SV_F * 4 + 2 * SK_H * 2)

__device__ __forceinline__ void attn_stage_issue(
    const __nv_bfloat16* __restrict__ Kh, const float* __restrict__ Vp,
    int b, int h, int kt, uint32_t sK_addr, uint32_t sV_addr, int tid)
{
    const __nv_bfloat16* Kbase = Kh + ((size_t)b * NK + kt * KTILE) * DM + h * HD;
    const float* Vbase = Vp + ((size_t)b * NK + kt * KTILE) * DM + h * HD;
    // K: 64 rows x 128 B  = 512 cp16 -> 2 per thread
#pragma unroll
    for (int i = 0; i < 2; i++) {
        int idx = tid + i * 256;
        int r = idx >> 3;       // 0..63
        int c16 = idx & 7;      // 0..7 (16B chunks)
        cp16(sK_addr + (uint32_t)(r * KST * 2 + c16 * 16),
             Kbase + (size_t)r * DM + c16 * 8);
    }
    // V: 64 rows x 256 B = 1024 cp16 -> 4 per thread
#pragma unroll
    for (int i = 0; i < 4; i++) {
        int idx = tid + i * 256;
        int r = idx >> 4;       // 0..63
        int c4 = idx & 15;      // 0..15
        cp16(sV_addr + (uint32_t)(r * VST + c4 * 4) * 4,
             Vbase + (size_t)r * DM + c4 * 4);
    }
    CP_COMMIT();
}

__global__ __launch_bounds__(256, 2) void attn_mma(
    const __nv_bfloat16* __restrict__ Qh, const __nv_bfloat16* __restrict__ Kh,
    const float* __restrict__ Vp, float* __restrict__ Op)
{
    extern __shared__ float sm[];
    float* sP = sm;                                  // [128][PST] floats
    float* sV = sP + SP_F;                           // 2 x [64][VST] floats
    __nv_bfloat16* sKh = (__nv_bfloat16*)(sV + 2 * SV_F);  // 2 x [64][KST] bf16
    const uint32_t sKa = smem_u32(sKh);
    const uint32_t sVa = smem_u32(sV);

    const int tid = threadIdx.x;
    const int wid = tid >> 5;
    const int lane = tid & 31;
    const int gID = lane >> 2;
    const int ig  = lane & 3;
    const int qt = blockIdx.x;
    const int h  = blockIdx.y;
    const int b  = blockIdx.z;

    const int r0 = wid * 16 + gID;   // warp's first q-row (in tile)

    // Kick off K/V tile 0
    attn_stage_issue(Kh, Vp, b, h, 0, sKa, sVa, tid);

    // Q fragments straight from gmem (bf16, pre-scaled in projection).
    // m16n8k16 A-frag: packed pairs (2 bf16 per 32-bit reg).
    uint32_t qf[4][4];
    {
        const __nv_bfloat16* Qb =
            Qh + ((size_t)b * NQ + qt * QROWS + r0) * DM + h * HD;
#pragma unroll
        for (int st = 0; st < 4; st++) {
            int kk0 = st * 16;
            qf[st][0] = *(const uint32_t*)&Qb[kk0 + 2 * ig];
            qf[st][1] = *(const uint32_t*)&Qb[8 * DM + kk0 + 2 * ig];
            qf[st][2] = *(const uint32_t*)&Qb[kk0 + 8 + 2 * ig];
            qf[st][3] = *(const uint32_t*)&Qb[8 * DM + kk0 + 8 + 2 * ig];
        }
    }

    float m0 = -1e30f, m1 = -1e30f, l0 = 0.0f, l1 = 0.0f;
    float oacc[8][4];
#pragma unroll
    for (int nt = 0; nt < 8; nt++)
#pragma unroll
        for (int v = 0; v < 4; v++) oacc[nt][v] = 0.0f;

    const int nTiles = NK / KTILE;   // 32
    for (int kt = 0; kt < nTiles; kt++) {
        const int cur = kt & 1;
        CP_WAIT(0);
        __syncthreads();
        if (kt + 1 < nTiles) {
            const int nxt = (kt + 1) & 1;
            attn_stage_issue(Kh, Vp, b, h, kt + 1,
                             sKa + nxt * SK_H * 2, sVa + nxt * SV_F * 4, tid);
        }
        const __nv_bfloat16* cK = sKh + cur * SK_H;
        const float* cV = sV + cur * SV_F;

        // ---- S = Q @ K^T : bf16 m16n8k16, 4 k-steps x 8 n-tiles ----
        float s[8][4];
#pragma unroll
        for (int nt = 0; nt < 8; nt++)
#pragma unroll
            for (int v = 0; v < 4; v++) s[nt][v] = 0.0f;

#pragma unroll
        for (int st = 0; st < 4; st++) {
            const int kk0 = st * 16;
#pragma unroll
            for (int nt = 0; nt < 8; nt++) {
                int n0 = nt * 8 + gID;
                uint32_t bf[2];
                bf[0] = *(const uint32_t*)&cK[n0 * KST + kk0 + 2 * ig];
                bf[1] = *(const uint32_t*)&cK[n0 * KST + kk0 + 8 + 2 * ig];
                mma_bf16(s[nt], qf[st], bf);
            }
        }

        // ---- Online softmax (rows r0, r0+8; quad-local reductions) ----
        float mt0 = -1e30f, mt1 = -1e30f;
#pragma unroll
        for (int nt = 0; nt < 8; nt++) {
            mt0 = fmaxf(mt0, fmaxf(s[nt][0], s[nt][1]));
            mt1 = fmaxf(mt1, fmaxf(s[nt][2], s[nt][3]));
        }
        mt0 = fmaxf(mt0, __shfl_xor_sync(0xffffffffu, mt0, 1));
        mt0 = fmaxf(mt0, __shfl_xor_sync(0xffffffffu, mt0, 2));
        mt1 = fmaxf(mt1, __shfl_xor_sync(0xffffffffu, mt1, 1));
        mt1 = fmaxf(mt1, __shfl_xor_sync(0xffffffffu, mt1, 2));

        float mn0 = fmaxf(m0, mt0), mn1 = fmaxf(m1, mt1);
        float a0 = ex2(m0 - mn0), a1 = ex2(m1 - mn1);
        m0 = mn0; m1 = mn1;

        float rs0 = 0.0f, rs1 = 0.0f;
#pragma unroll
        for (int nt = 0; nt < 8; nt++) {
            float p00 = ex2(s[nt][0] - mn0);
            float p01 = ex2(s[nt][1] - mn0);
            float p10 = ex2(s[nt][2] - mn1);
            float p11 = ex2(s[nt][3] - mn1);
            rs0 += p00 + p01;
            rs1 += p10 + p11;
            int c = nt * 8 + ig * 2;
            float2 q0; q0.x = to_tf32(p00); q0.y = to_tf32(p01);
            *(float2*)&sP[r0 * PST + c] = q0;
            float2 q1; q1.x = to_tf32(p10); q1.y = to_tf32(p11);
            *(float2*)&sP[(r0 + 8) * PST + c] = q1;
        }
        rs0 += __shfl_xor_sync(0xffffffffu, rs0, 1);
        rs0 += __shfl_xor_sync(0xffffffffu, rs0, 2);
        rs1 += __shfl_xor_sync(0xffffffffu, rs1, 1);
        rs1 += __shfl_xor_sync(0xffffffffu, rs1, 2);
        l0 = l0 * a0 + rs0;
        l1 = l1 * a1 + rs1;

#pragma unroll
        for (int nt = 0; nt < 8; nt++) {
            oacc[nt][0] *= a0; oacc[nt][1] *= a0;
            oacc[nt][2] *= a1; oacc[nt][3] *= a1;
        }
        __syncwarp();   // warp-private sP slab

        // ---- oacc += P @ V (tf32, V row-major) ----
#pragma unroll
        for (int k8 = 0; k8 < 8; k8++) {
            const int kk = k8 * 8;
            uint32_t af[4];
            af[0] = __float_as_uint(sP[r0 * PST + kk + ig]);
            af[1] = __float_as_uint(sP[(r0 + 8) * PST + kk + ig]);
            af[2] = __float_as_uint(sP[r0 * PST + kk + ig + 4]);
            af[3] = __float_as_uint(sP[(r0 + 8) * PST + kk + ig + 4]);
#pragma unroll
            for (int nt = 0; nt < 8; nt++) {
                int n0 = nt * 8 + gID;
                uint32_t bf[2];
                bf[0] = __float_as_uint(cV[(kk + ig) * VST + n0]);
                bf[1] = __float_as_uint(cV[(kk + ig + 4) * VST + n0]);
                mma_tf32(oacc[nt], af, bf);
            }
        }
        __syncthreads();   // all warps done with cur buffers
    }

    // ---- Epilogue: normalize, tf32-round, write [b, n, h*64+d] ----
    float inv0 = 1.0f / l0, inv1 = 1.0f / l1;
    const int grow = qt * QROWS + r0;
#pragma unroll
    for (int nt = 0; nt < 8; nt++) {
        int col = h * HD + nt * 8 + ig * 2;
        float2 o0;
        o0.x = to_tf32(oacc[nt][0] * inv0);
        o0.y = to_tf32(oacc[nt][1] * inv0);
        *(float2*)&Op[((size_t)b * NQ + grow) * DM + col] = o0;
        float2 o1;
        o1.x = to_tf32(oacc[nt][2] * inv1);
        o1.y = to_tf32(oacc[nt][3] * inv1);
        *(float2*)&Op[((size_t)b * NQ + grow + 8) * DM + col] = o1;
    }
}

// ---------------------------------------------------------------------------
// Launch
// ---------------------------------------------------------------------------
extern "C" void kernel_launch(void* const* d_in, const int* in_sizes, int n_in,
                              void* d_out, int out_size)
{
    const float* queries = (const float*)d_in[0];
    const float* keys    = (const float*)d_in[1];
    const float* values  = (const float*)d_in[2];
    const float* Wq      = (const float*)d_in[3];
    const float* Wk      = (const float*)d_in[4];
    const float* Wv      = (const float*)d_in[5];
    const float* Wo      = (const float*)d_in[6];
    const float* bo      = (const float*)d_in[7];
    float* out           = (float*)d_out;

    __nv_bfloat16 *Qh, *Kh;
    float *Vp, *Op, *WT, *IN;
    cudaGetSymbolAddress((void**)&Qh, g_Qh);
    cudaGetSymbolAddress((void**)&Kh, g_Kh);
    cudaGetSymbolAddress((void**)&Vp, g_V);
    cudaGetSymbolAddress((void**)&Op, g_O);
    cudaGetSymbolAddress((void**)&WT, g_WT);
    cudaGetSymbolAddress((void**)&IN, g_IN);

    static bool attr_set = false;
    if (!attr_set) {
        cudaFuncSetAttribute(attn_mma,
                             cudaFuncAttributeMaxDynamicSharedMemorySize, SMEM_ATT);
        cudaFuncSetAttribute(gemm_qkv,
                             cudaFuncAttributeMaxDynamicSharedMemorySize, SMEM_GEMM);
        cudaFuncSetAttribute(gemm_out,
                             cudaFuncAttributeMaxDynamicSharedMemorySize, SMEM_GEMM);
        attr_set = true;
    }

    dim3 tgrid(DM / 32, DM / 32, 4), tblk(32, 8);
    transpose4_tf32<<<tgrid, tblk>>>(Wq, Wk, Wv, Wo, WT);

    dim3 rgrid(512, 1, 3);
    round3<<<rgrid, 256>>>(queries, keys, values, IN);

    dim3 qgrid(DM / GBN, MROWS / GBM, 3);
    gemm_qkv<<<qgrid, 256, SMEM_GEMM>>>(IN, WT, Qh, Kh, Vp);

    dim3 agrid(NQ / QROWS, NH, BATCH);  // (16, 16, 4)
    attn_mma<<<agrid, 256, SMEM_ATT>>>(Qh, Kh, Vp, Op);

    dim3 ogrid(DM / GBN, MROWS / GBM);
    gemm_out<<<ogrid, 256, SMEM_GEMM>>>(Op, WT + 3 * (size_t)DM * DM, bo, out);
}

// round 10
// speedup vs baseline: 4.7182x; 1.0910x over previous
#include <cuda_runtime.h>
#include <cuda_bf16.h>
#include <math.h>
#include <stdint.h>

#define BATCH 4
#define NQ 2048
#define NK 2048
#define DM 1024
#define NH 16
#define HD 64
#define MROWS (BATCH * NQ)   // 8192

// Scratch
__device__ __nv_bfloat16 g_Qh[MROWS * DM];       // Q proj, bf16, pre-scaled
__device__ __nv_bfloat16 g_Kh[MROWS * DM];       // K proj, bf16
__device__ float g_V[MROWS * DM];                // V proj, tf32-rounded fp32
__device__ float g_O[MROWS * DM];                // attention out, tf32-rounded
__device__ __nv_bfloat16 g_WTH[2 * DM * DM];     // Wq^T, Wk^T in bf16
__device__ float g_WT[2 * DM * DM];              // Wv^T, Wo^T in fp32 tf32
__device__ __nv_bfloat16 g_INH[2 * MROWS * DM];  // bf16 queries, keys
__device__ float g_IN[MROWS * DM];               // tf32 values

#define QSCALE (0.03125f * 1.4426950408889634f)   // 1/sqrt(1024) * log2(e)

__device__ __forceinline__ float to_tf32(float x) {
    float r;
    asm("cvt.rna.tf32.f32 %0, %1;" : "=f"(r) : "f"(x));
    return r;
}

__device__ __forceinline__ float ex2(float x) {
    float r;
    asm("ex2.approx.ftz.f32 %0, %1;" : "=f"(r) : "f"(x));
    return r;
}

__device__ __forceinline__ void mma_tf32(float* c, const uint32_t* a, const uint32_t* b) {
    asm volatile(
        "mma.sync.aligned.m16n8k8.row.col.f32.tf32.tf32.f32 "
        "{%0,%1,%2,%3}, {%4,%5,%6,%7}, {%8,%9}, {%0,%1,%2,%3};"
        : "+f"(c[0]), "+f"(c[1]), "+f"(c[2]), "+f"(c[3])
        : "r"(a[0]), "r"(a[1]), "r"(a[2]), "r"(a[3]), "r"(b[0]), "r"(b[1]));
}

__device__ __forceinline__ void mma_bf16(float* c, const uint32_t* a, const uint32_t* b) {
    asm volatile(
        "mma.sync.aligned.m16n8k16.row.col.f32.bf16.bf16.f32 "
        "{%0,%1,%2,%3}, {%4,%5,%6,%7}, {%8,%9}, {%0,%1,%2,%3};"
        : "+f"(c[0]), "+f"(c[1]), "+f"(c[2]), "+f"(c[3])
        : "r"(a[0]), "r"(a[1]), "r"(a[2]), "r"(a[3]), "r"(b[0]), "r"(b[1]));
}

__device__ __forceinline__ uint32_t smem_u32(const void* p) {
    uint32_t a;
    asm("{ .reg .u64 t; cvta.to.shared.u64 t, %1; cvt.u32.u64 %0, t; }"
        : "=r"(a) : "l"(p));
    return a;
}

__device__ __forceinline__ void cp16(uint32_t dst, const void* src) {
    asm volatile("cp.async.ca.shared.global [%0], [%1], 16;" :: "r"(dst), "l"(src));
}
#define CP_COMMIT() asm volatile("cp.async.commit_group;" ::: "memory")
#define CP_WAIT(n)  asm volatile("cp.async.wait_group %0;" :: "n"(n) : "memory")

// ---------------------------------------------------------------------------
// Weight transpose: z=0,1 -> bf16 (Wq, Wk); z=2,3 -> tf32 fp32 (Wv, Wo)
// ---------------------------------------------------------------------------
__global__ void transpose4(const float* __restrict__ W0, const float* __restrict__ W1,
                           const float* __restrict__ W2, const float* __restrict__ W3,
                           __nv_bfloat16* __restrict__ WTH, float* __restrict__ WT)
{
    __shared__ float t[32][33];
    const int z = blockIdx.z;
    const float* W = (z == 0) ? W0 : (z == 1) ? W1 : (z == 2) ? W2 : W3;
    int bx = blockIdx.x * 32, by = blockIdx.y * 32;
    for (int j = threadIdx.y; j < 32; j += 8)
        t[j][threadIdx.x] = W[(size_t)(by + j) * DM + bx + threadIdx.x];
    __syncthreads();
    if (z < 2) {
        __nv_bfloat16* d = g_WTH + (size_t)z * DM * DM;
        for (int j = threadIdx.y; j < 32; j += 8)
            d[(size_t)(bx + j) * DM + by + threadIdx.x] =
                __float2bfloat16_rn(t[threadIdx.x][j]);
    } else {
        float* d = WT + (size_t)(z - 2) * DM * DM;
        for (int j = threadIdx.y; j < 32; j += 8)
            d[(size_t)(bx + j) * DM + by + threadIdx.x] = to_tf32(t[threadIdx.x][j]);
    }
}

// ---------------------------------------------------------------------------
// Input prep: z=0,1 -> bf16 (queries, keys); z=2 -> tf32 fp32 (values)
// ---------------------------------------------------------------------------
__global__ __launch_bounds__(256) void prep_inputs(
    const float* __restrict__ q, const float* __restrict__ k,
    const float* __restrict__ v)
{
    const int z = blockIdx.z;
    const float* src = (z == 0) ? q : (z == 1) ? k : v;
    const size_t n4 = (size_t)MROWS * DM / 4;
    if (z < 2) {
        __nv_bfloat16* d = g_INH + (size_t)z * MROWS * DM;
        for (size_t i = blockIdx.x * 256 + threadIdx.x; i < n4; i += (size_t)gridDim.x * 256) {
            float4 x = ((const float4*)src)[i];
            __nv_bfloat162 lo = __float22bfloat162_rn(make_float2(x.x, x.y));
            __nv_bfloat162 hi = __float22bfloat162_rn(make_float2(x.z, x.w));
            uint2 pk;
            pk.x = *(uint32_t*)&lo;
            pk.y = *(uint32_t*)&hi;
            ((uint2*)d)[i] = pk;
        }
    } else {
        float* d = g_IN;
        for (size_t i = blockIdx.x * 256 + threadIdx.x; i < n4; i += (size_t)gridDim.x * 256) {
            float4 x = ((const float4*)src)[i];
            x.x = to_tf32(x.x); x.y = to_tf32(x.y);
            x.z = to_tf32(x.z); x.w = to_tf32(x.w);
            ((float4*)d)[i] = x;
        }
    }
}

// ---------------------------------------------------------------------------
// TF32 mma GEMM core, 2-stage cp.async pipeline (V-proj + out-proj).
// mode: 0 = fp32 +bias; 1 = fp32 tf32-rounded
// ---------------------------------------------------------------------------
#define GBM 128
#define GBN 128
#define GBK 32
#define SSTRIDE 36
#define TILE_FLOATS (GBM * SSTRIDE)
#define STAGE_FLOATS (2 * TILE_FLOATS)
#define SMEM_GEMM (2 * STAGE_FLOATS * 4)

__device__ __forceinline__ void gemm_stage_issue(
    const float* __restrict__ A, const float* __restrict__ BT,
    int bm, int bn, int k0, uint32_t sA_addr, uint32_t sB_addr, int tid)
{
#pragma unroll
    for (int i = 0; i < 4; i++) {
        int idx = tid + i * 256;
        int r = idx >> 3;
        int c4 = idx & 7;
        uint32_t off = (uint32_t)(r * SSTRIDE + c4 * 4) * 4;
        cp16(sA_addr + off, &A[(size_t)(bm + r) * DM + k0 + c4 * 4]);
        cp16(sB_addr + off, &BT[(size_t)(bn + r) * DM + k0 + c4 * 4]);
    }
    CP_COMMIT();
}

__device__ __forceinline__ void gemm_core(
    const float* __restrict__ A, const float* __restrict__ BT,
    const float* __restrict__ bias, float* __restrict__ C,
    int mode, float* dsm)
{
    const uint32_t sbase = smem_u32(dsm);
    const int tid = threadIdx.x;
    const int wid = tid >> 5;
    const int lane = tid & 31;
    const int gID = lane >> 2;
    const int ig  = lane & 3;
    const int warp_m = wid >> 2;
    const int warp_n = wid & 3;
    const int bm = blockIdx.y * GBM;
    const int bn = blockIdx.x * GBN;

    float acc[4][4][4];
#pragma unroll
    for (int i = 0; i < 4; i++)
#pragma unroll
        for (int j = 0; j < 4; j++)
#pragma unroll
            for (int v = 0; v < 4; v++) acc[i][j][v] = 0.0f;

    const int kSteps = DM / GBK;

    gemm_stage_issue(A, BT, bm, bn, 0, sbase, sbase + TILE_FLOATS * 4, tid);

    for (int kt = 0; kt < kSteps; kt++) {
        const int cur = kt & 1;
        if (kt + 1 < kSteps) {
            const int nxt = (kt + 1) & 1;
            gemm_stage_issue(A, BT, bm, bn, (kt + 1) * GBK,
                             sbase + nxt * STAGE_FLOATS * 4,
                             sbase + (nxt * STAGE_FLOATS + TILE_FLOATS) * 4, tid);
            CP_WAIT(1);
        } else {
            CP_WAIT(0);
        }
        __syncthreads();

        const float* sA = dsm + cur * STAGE_FLOATS;
        const float* sB = sA + TILE_FLOATS;

#pragma unroll
        for (int kk = 0; kk < GBK; kk += 8) {
            uint32_t afrag[4][4];
#pragma unroll
            for (int mt = 0; mt < 4; mt++) {
                int r0 = warp_m * 64 + mt * 16 + gID;
                afrag[mt][0] = __float_as_uint(sA[r0 * SSTRIDE + kk + ig]);
                afrag[mt][1] = __float_as_uint(sA[(r0 + 8) * SSTRIDE + kk + ig]);
                afrag[mt][2] = __float_as_uint(sA[r0 * SSTRIDE + kk + ig + 4]);
                afrag[mt][3] = __float_as_uint(sA[(r0 + 8) * SSTRIDE + kk + ig + 4]);
            }
            uint32_t bfrag[4][2];
#pragma unroll
            for (int nt = 0; nt < 4; nt++) {
                int n0 = warp_n * 32 + nt * 8 + gID;
                bfrag[nt][0] = __float_as_uint(sB[n0 * SSTRIDE + kk + ig]);
                bfrag[nt][1] = __float_as_uint(sB[n0 * SSTRIDE + kk + ig + 4]);
            }
#pragma unroll
            for (int mt = 0; mt < 4; mt++)
#pragma unroll
                for (int nt = 0; nt < 4; nt++)
                    mma_tf32(acc[mt][nt], afrag[mt], bfrag[nt]);
        }
        __syncthreads();
    }

#pragma unroll
    for (int mt = 0; mt < 4; mt++) {
#pragma unroll
        for (int nt = 0; nt < 4; nt++) {
            int row = bm + warp_m * 64 + mt * 16 + gID;
            int col = bn + warp_n * 32 + nt * 8 + ig * 2;
            float2 v0, v1;
            v0.x = acc[mt][nt][0]; v0.y = acc[mt][nt][1];
            v1.x = acc[mt][nt][2]; v1.y = acc[mt][nt][3];
            if (mode == 0 && bias) {
                float b0 = bias[col], b1 = bias[col + 1];
                v0.x += b0; v0.y += b1;
                v1.x += b0; v1.y += b1;
            }
            if (mode == 1) {
                v0.x = to_tf32(v0.x); v0.y = to_tf32(v0.y);
                v1.x = to_tf32(v1.x); v1.y = to_tf32(v1.y);
            }
            *(float2*)&C[(size_t)row * DM + col] = v0;
            *(float2*)&C[(size_t)(row + 8) * DM + col] = v1;
        }
    }
}

__global__ __launch_bounds__(256, 2) void gemm_v(
    const float* __restrict__ A, const float* __restrict__ BT,
    float* __restrict__ C)
{
    extern __shared__ float dsm[];
    gemm_core(A, BT, nullptr, C, 1, dsm);
}

__global__ __launch_bounds__(256, 2) void gemm_out(
    const float* __restrict__ A, const float* __restrict__ BT,
    const float* __restrict__ bias, float* __restrict__ C)
{
    extern __shared__ float dsm[];
    gemm_core(A, BT, bias, C, 0, dsm);
}

// ---------------------------------------------------------------------------
// BF16 mma GEMM (Q and K projections): m16n8k16, tile 128x128, BK=32 bf16.
// Row stride 28 uint32 (112 B): conflict-free frags + 16B-aligned cp.async.
// z=0 -> Q (scaled by QSCALE), z=1 -> K.
// ---------------------------------------------------------------------------
#define HST 28                       // uint32 per smem row
#define HTILE_U32 (GBM * HST)        // 3584 u32 per A or B tile
#define HSTAGE_U32 (2 * HTILE_U32)
#define SMEM_GEMMH (2 * HSTAGE_U32 * 4)   // 57344 bytes

__device__ __forceinline__ void gemmh_stage_issue(
    const __nv_bfloat16* __restrict__ A, const __nv_bfloat16* __restrict__ BT,
    int bm, int bn, int k0, uint32_t sA_addr, uint32_t sB_addr, int tid)
{
#pragma unroll
    for (int i = 0; i < 2; i++) {
        int idx = tid + i * 256;
        int r = idx >> 2;      // 0..127
        int c = idx & 3;       // 0..3 (16B chunks of the 64B row)
        uint32_t off = (uint32_t)(r * HST * 4 + c * 16);
        cp16(sA_addr + off, A + (size_t)(bm + r) * DM + k0 + c * 8);
        cp16(sB_addr + off, BT + (size_t)(bn + r) * DM + k0 + c * 8);
    }
    CP_COMMIT();
}

__global__ __launch_bounds__(256, 2) void gemm_bf16qk(
    const __nv_bfloat16* __restrict__ INH, const __nv_bfloat16* __restrict__ WTH,
    __nv_bfloat16* __restrict__ Qo, __nv_bfloat16* __restrict__ Ko)
{
    extern __shared__ uint32_t hsm[];
    const int z = blockIdx.z;
    const __nv_bfloat16* A  = INH + (size_t)z * MROWS * DM;
    const __nv_bfloat16* BT = WTH + (size_t)z * DM * DM;
    __nv_bfloat16* C = z ? Ko : Qo;

    const uint32_t sbase = smem_u32(hsm);
    const int tid = threadIdx.x;
    const int wid = tid >> 5;
    const int lane = tid & 31;
    const int gID = lane >> 2;
    const int ig  = lane & 3;
    const int warp_m = wid >> 2;
    const int warp_n = wid & 3;
    const int bm = blockIdx.y * GBM;
    const int bn = blockIdx.x * GBN;

    float acc[4][4][4];
#pragma unroll
    for (int i = 0; i < 4; i++)
#pragma unroll
        for (int j = 0; j < 4; j++)
#pragma unroll
            for (int v = 0; v < 4; v++) acc[i][j][v] = 0.0f;

    const int kSteps = DM / GBK;   // 32 (BK = 32 bf16 elements)

    gemmh_stage_issue(A, BT, bm, bn, 0, sbase, sbase + HTILE_U32 * 4, tid);

    for (int kt = 0; kt < kSteps; kt++) {
        const int cur = kt & 1;
        if (kt + 1 < kSteps) {
            const int nxt = (kt + 1) & 1;
            gemmh_stage_issue(A, BT, bm, bn, (kt + 1) * GBK,
                              sbase + nxt * HSTAGE_U32 * 4,
                              sbase + (nxt * HSTAGE_U32 + HTILE_U32) * 4, tid);
            CP_WAIT(1);
        } else {
            CP_WAIT(0);
        }
        __syncthreads();

        const uint32_t* sA = hsm + cur * HSTAGE_U32;
        const uint32_t* sB = sA + HTILE_U32;

#pragma unroll
        for (int st = 0; st < 2; st++) {       // two k16 steps
            const int c0 = st * 8;
            uint32_t afrag[4][4];
#pragma unroll
            for (int mt = 0; mt < 4; mt++) {
                int r0 = warp_m * 64 + mt * 16 + gID;
                afrag[mt][0] = sA[r0 * HST + c0 + ig];
                afrag[mt][1] = sA[(r0 + 8) * HST + c0 + ig];
                afrag[mt][2] = sA[r0 * HST + c0 + ig + 4];
                afrag[mt][3] = sA[(r0 + 8) * HST + c0 + ig + 4];
            }
            uint32_t bfrag[4][2];
#pragma unroll
            for (int nt = 0; nt < 4; nt++) {
                int n0 = warp_n * 32 + nt * 8 + gID;
                bfrag[nt][0] = sB[n0 * HST + c0 + ig];
                bfrag[nt][1] = sB[n0 * HST + c0 + ig + 4];
            }
#pragma unroll
            for (int mt = 0; mt < 4; mt++)
#pragma unroll
                for (int nt = 0; nt < 4; nt++)
                    mma_bf16(acc[mt][nt], afrag[mt], bfrag[nt]);
        }
        __syncthreads();
    }

    const float esc = z ? 1.0f : QSCALE;
#pragma unroll
    for (int mt = 0; mt < 4; mt++) {
#pragma unroll
        for (int nt = 0; nt < 4; nt++) {
            int row = bm + warp_m * 64 + mt * 16 + gID;
            int col = bn + warp_n * 32 + nt * 8 + ig * 2;
            float2 v0, v1;
            v0.x = acc[mt][nt][0] * esc; v0.y = acc[mt][nt][1] * esc;
            v1.x = acc[mt][nt][2] * esc; v1.y = acc[mt][nt][3] * esc;
            *(__nv_bfloat162*)&C[(size_t)row * DM + col] = __float22bfloat162_rn(v0);
            *(__nv_bfloat162*)&C[(size_t)(row + 8) * DM + col] = __float22bfloat162_rn(v1);
        }
    }
}

// ---------------------------------------------------------------------------
// Flash attention (unchanged from R9): bf16 QK, tf32 PV.
// ---------------------------------------------------------------------------
#define QROWS 128
#define PST 68
#define KST 72
#define VST 72
#define KTILE 64
#define SP_F (QROWS * PST)
#define SK_H (KTILE * KST)
#define SV_F (KTILE * VST)
#define SMEM_ATT (SP_F * 4 + 2 * SV_F * 4 + 2 * SK_H * 2)

__device__ __forceinline__ void attn_stage_issue(
    const __nv_bfloat16* __restrict__ Kh, const float* __restrict__ Vp,
    int b, int h, int kt, uint32_t sK_addr, uint32_t sV_addr, int tid)
{
    const __nv_bfloat16* Kbase = Kh + ((size_t)b * NK + kt * KTILE) * DM + h * HD;
    const float* Vbase = Vp + ((size_t)b * NK + kt * KTILE) * DM + h * HD;
#pragma unroll
    for (int i = 0; i < 2; i++) {
        int idx = tid + i * 256;
        int r = idx >> 3;
        int c16 = idx & 7;
        cp16(sK_addr + (uint32_t)(r * KST * 2 + c16 * 16),
             Kbase + (size_t)r * DM + c16 * 8);
    }
#pragma unroll
    for (int i = 0; i < 4; i++) {
        int idx = tid + i * 256;
        int r = idx >> 4;
        int c4 = idx & 15;
        cp16(sV_addr + (uint32_t)(r * VST + c4 * 4) * 4,
             Vbase + (size_t)r * DM + c4 * 4);
    }
    CP_COMMIT();
}

__global__ __launch_bounds__(256, 2) void attn_mma(
    const __nv_bfloat16* __restrict__ Qh, const __nv_bfloat16* __restrict__ Kh,
    const float* __restrict__ Vp, float* __restrict__ Op)
{
    extern __shared__ float sm[];
    float* sP = sm;
    float* sV = sP + SP_F;
    __nv_bfloat16* sKh = (__nv_bfloat16*)(sV + 2 * SV_F);
    const uint32_t sKa = smem_u32(sKh);
    const uint32_t sVa = smem_u32(sV);

    const int tid = threadIdx.x;
    const int wid = tid >> 5;
    const int lane = tid & 31;
    const int gID = lane >> 2;
    const int ig  = lane & 3;
    const int qt = blockIdx.x;
    const int h  = blockIdx.y;
    const int b  = blockIdx.z;

    const int r0 = wid * 16 + gID;

    attn_stage_issue(Kh, Vp, b, h, 0, sKa, sVa, tid);

    uint32_t qf[4][4];
    {
        const __nv_bfloat16* Qb =
            Qh + ((size_t)b * NQ + qt * QROWS + r0) * DM + h * HD;
#pragma unroll
        for (int st = 0; st < 4; st++) {
            int kk0 = st * 16;
            qf[st][0] = *(const uint32_t*)&Qb[kk0 + 2 * ig];
            qf[st][1] = *(const uint32_t*)&Qb[8 * DM + kk0 + 2 * ig];
            qf[st][2] = *(const uint32_t*)&Qb[kk0 + 8 + 2 * ig];
            qf[st][3] = *(const uint32_t*)&Qb[8 * DM + kk0 + 8 + 2 * ig];
        }
    }

    float m0 = -1e30f, m1 = -1e30f, l0 = 0.0f, l1 = 0.0f;
    float oacc[8][4];
#pragma unroll
    for (int nt = 0; nt < 8; nt++)
#pragma unroll
        for (int v = 0; v < 4; v++) oacc[nt][v] = 0.0f;

    const int nTiles = NK / KTILE;
    for (int kt = 0; kt < nTiles; kt++) {
        const int cur = kt & 1;
        CP_WAIT(0);
        __syncthreads();
        if (kt + 1 < nTiles) {
            const int nxt = (kt + 1) & 1;
            attn_stage_issue(Kh, Vp, b, h, kt + 1,
                             sKa + nxt * SK_H * 2, sVa + nxt * SV_F * 4, tid);
        }
        const __nv_bfloat16* cK = sKh + cur * SK_H;
        const float* cV = sV + cur * SV_F;

        float s[8][4];
#pragma unroll
        for (int nt = 0; nt < 8; nt++)
#pragma unroll
            for (int v = 0; v < 4; v++) s[nt][v] = 0.0f;

#pragma unroll
        for (int st = 0; st < 4; st++) {
            const int kk0 = st * 16;
#pragma unroll
            for (int nt = 0; nt < 8; nt++) {
                int n0 = nt * 8 + gID;
                uint32_t bf[2];
                bf[0] = *(const uint32_t*)&cK[n0 * KST + kk0 + 2 * ig];
                bf[1] = *(const uint32_t*)&cK[n0 * KST + kk0 + 8 + 2 * ig];
                mma_bf16(s[nt], qf[st], bf);
            }
        }

        float mt0 = -1e30f, mt1 = -1e30f;
#pragma unroll
        for (int nt = 0; nt < 8; nt++) {
            mt0 = fmaxf(mt0, fmaxf(s[nt][0], s[nt][1]));
            mt1 = fmaxf(mt1, fmaxf(s[nt][2], s[nt][3]));
        }
        mt0 = fmaxf(mt0, __shfl_xor_sync(0xffffffffu, mt0, 1));
        mt0 = fmaxf(mt0, __shfl_xor_sync(0xffffffffu, mt0, 2));
        mt1 = fmaxf(mt1, __shfl_xor_sync(0xffffffffu, mt1, 1));
        mt1 = fmaxf(mt1, __shfl_xor_sync(0xffffffffu, mt1, 2));

        float mn0 = fmaxf(m0, mt0), mn1 = fmaxf(m1, mt1);
        float a0 = ex2(m0 - mn0), a1 = ex2(m1 - mn1);
        m0 = mn0; m1 = mn1;

        float rs0 = 0.0f, rs1 = 0.0f;
#pragma unroll
        for (int nt = 0; nt < 8; nt++) {
            float p00 = ex2(s[nt][0] - mn0);
            float p01 = ex2(s[nt][1] - mn0);
            float p10 = ex2(s[nt][2] - mn1);
            float p11 = ex2(s[nt][3] - mn1);
            rs0 += p00 + p01;
            rs1 += p10 + p11;
            int c = nt * 8 + ig * 2;
            float2 q0; q0.x = to_tf32(p00); q0.y = to_tf32(p01);
            *(float2*)&sP[r0 * PST + c] = q0;
            float2 q1; q1.x = to_tf32(p10); q1.y = to_tf32(p11);
            *(float2*)&sP[(r0 + 8) * PST + c] = q1;
        }
        rs0 += __shfl_xor_sync(0xffffffffu, rs0, 1);
        rs0 += __shfl_xor_sync(0xffffffffu, rs0, 2);
        rs1 += __shfl_xor_sync(0xffffffffu, rs1, 1);
        rs1 += __shfl_xor_sync(0xffffffffu, rs1, 2);
        l0 = l0 * a0 + rs0;
        l1 = l1 * a1 + rs1;

#pragma unroll
        for (int nt = 0; nt < 8; nt++) {
            oacc[nt][0] *= a0; oacc[nt][1] *= a0;
            oacc[nt][2] *= a1; oacc[nt][3] *= a1;
        }
        __syncwarp();

#pragma unroll
        for (int k8 = 0; k8 < 8; k8++) {
            const int kk = k8 * 8;
            uint32_t af[4];
            af[0] = __float_as_uint(sP[r0 * PST + kk + ig]);
            af[1] = __float_as_uint(sP[(r0 + 8) * PST + kk + ig]);
            af[2] = __float_as_uint(sP[r0 * PST + kk + ig + 4]);
            af[3] = __float_as_uint(sP[(r0 + 8) * PST + kk + ig + 4]);
#pragma unroll
            for (int nt = 0; nt < 8; nt++) {
                int n0 = nt * 8 + gID;
                uint32_t bf[2];
                bf[0] = __float_as_uint(cV[(kk + ig) * VST + n0]);
                bf[1] = __float_as_uint(cV[(kk + ig + 4) * VST + n0]);
                mma_tf32(oacc[nt], af, bf);
            }
        }
        __syncthreads();
    }

    float inv0 = 1.0f / l0, inv1 = 1.0f / l1;
    const int grow = qt * QROWS + r0;
#pragma unroll
    for (int nt = 0; nt < 8; nt++) {
        int col = h * HD + nt * 8 + ig * 2;
        float2 o0;
        o0.x = to_tf32(oacc[nt][0] * inv0);
        o0.y = to_tf32(oacc[nt][1] * inv0);
        *(float2*)&Op[((size_t)b * NQ + grow) * DM + col] = o0;
        float2 o1;
        o1.x = to_tf32(oacc[nt][2] * inv1);
        o1.y = to_tf32(oacc[nt][3] * inv1);
        *(float2*)&Op[((size_t)b * NQ + grow + 8) * DM + col] = o1;
    }
}

// ---------------------------------------------------------------------------
// Launch
// ---------------------------------------------------------------------------
extern "C" void kernel_launch(void* const* d_in, const int* in_sizes, int n_in,
                              void* d_out, int out_size)
{
    const float* queries = (const float*)d_in[0];
    const float* keys    = (const float*)d_in[1];
    const float* values  = (const float*)d_in[2];
    const float* Wq      = (const float*)d_in[3];
    const float* Wk      = (const float*)d_in[4];
    const float* Wv      = (const float*)d_in[5];
    const float* Wo      = (const float*)d_in[6];
    const float* bo      = (const float*)d_in[7];
    float* out           = (float*)d_out;

    __nv_bfloat16 *Qh, *Kh, *WTH, *INH;
    float *Vp, *Op, *WT, *IN;
    cudaGetSymbolAddress((void**)&Qh, g_Qh);
    cudaGetSymbolAddress((void**)&Kh, g_Kh);
    cudaGetSymbolAddress((void**)&Vp, g_V);
    cudaGetSymbolAddress((void**)&Op, g_O);
    cudaGetSymbolAddress((void**)&WTH, g_WTH);
    cudaGetSymbolAddress((void**)&WT, g_WT);
    cudaGetSymbolAddress((void**)&INH, g_INH);
    cudaGetSymbolAddress((void**)&IN, g_IN);

    static bool attr_set = false;
    if (!attr_set) {
        cudaFuncSetAttribute(attn_mma,
                             cudaFuncAttributeMaxDynamicSharedMemorySize, SMEM_ATT);
        cudaFuncSetAttribute(gemm_bf16qk,
                             cudaFuncAttributeMaxDynamicSharedMemorySize, SMEM_GEMMH);
        cudaFuncSetAttribute(gemm_v,
                             cudaFuncAttributeMaxDynamicSharedMemorySize, SMEM_GEMM);
        cudaFuncSetAttribute(gemm_out,
                             cudaFuncAttributeMaxDynamicSharedMemorySize, SMEM_GEMM);
        attr_set = true;
    }

    dim3 tgrid(DM / 32, DM / 32, 4), tblk(32, 8);
    transpose4<<<tgrid, tblk>>>(Wq, Wk, Wv, Wo, WTH, WT);

    dim3 pgrid(512, 1, 3);
    prep_inputs<<<pgrid, 256>>>(queries, keys, values);

    dim3 hgrid(DM / GBN, MROWS / GBM, 2);   // Q and K projections, bf16
    gemm_bf16qk<<<hgrid, 256, SMEM_GEMMH>>>(INH, WTH, Qh, Kh);

    dim3 vgrid(DM / GBN, MROWS / GBM);      // V projection, tf32
    gemm_v<<<vgrid, 256, SMEM_GEMM>>>(IN, WT, Vp);

    dim3 agrid(NQ / QROWS, NH, BATCH);
    attn_mma<<<agrid, 256, SMEM_ATT>>>(Qh, Kh, Vp, Op);

    dim3 ogrid(DM / GBN, MROWS / GBM);
    gemm_out<<<ogrid, 256, SMEM_GEMM>>>(Op, WT + (size_t)DM * DM, bo, out);
}

// round 11
// speedup vs baseline: 4.9317x; 1.0452x over previous
#include <cuda_runtime.h>
#include <cuda_bf16.h>
#include <math.h>
#include <stdint.h>

#define BATCH 4
#define NQ 2048
#define NK 2048
#define DM 1024
#define NH 16
#define HD 64
#define MROWS (BATCH * NQ)   // 8192

// Scratch
__device__ __nv_bfloat16 g_Qh[MROWS * DM];       // Q proj, bf16, pre-scaled
__device__ __nv_bfloat16 g_Kh[MROWS * DM];       // K proj, bf16
__device__ float g_V[MROWS * DM];                // V proj, tf32-rounded fp32
__device__ float g_O[MROWS * DM];                // attention out, tf32-rounded
__device__ __nv_bfloat16 g_WTH[2 * DM * DM];     // Wq^T, Wk^T in bf16
__device__ float g_WT[2 * DM * DM];              // Wv^T, Wo^T in fp32 tf32
__device__ __nv_bfloat16 g_INH[2 * MROWS * DM];  // bf16 queries, keys
__device__ float g_IN[MROWS * DM];               // tf32 values

#define QSCALE (0.03125f * 1.4426950408889634f)   // 1/sqrt(1024) * log2(e)

__device__ __forceinline__ float to_tf32(float x) {
    float r;
    asm("cvt.rna.tf32.f32 %0, %1;" : "=f"(r) : "f"(x));
    return r;
}

__device__ __forceinline__ float ex2(float x) {
    float r;
    asm("ex2.approx.ftz.f32 %0, %1;" : "=f"(r) : "f"(x));
    return r;
}

__device__ __forceinline__ void mma_tf32(float* c, const uint32_t* a, const uint32_t* b) {
    asm volatile(
        "mma.sync.aligned.m16n8k8.row.col.f32.tf32.tf32.f32 "
        "{%0,%1,%2,%3}, {%4,%5,%6,%7}, {%8,%9}, {%0,%1,%2,%3};"
        : "+f"(c[0]), "+f"(c[1]), "+f"(c[2]), "+f"(c[3])
        : "r"(a[0]), "r"(a[1]), "r"(a[2]), "r"(a[3]), "r"(b[0]), "r"(b[1]));
}

__device__ __forceinline__ void mma_bf16(float* c, const uint32_t* a, const uint32_t* b) {
    asm volatile(
        "mma.sync.aligned.m16n8k16.row.col.f32.bf16.bf16.f32 "
        "{%0,%1,%2,%3}, {%4,%5,%6,%7}, {%8,%9}, {%0,%1,%2,%3};"
        : "+f"(c[0]), "+f"(c[1]), "+f"(c[2]), "+f"(c[3])
        : "r"(a[0]), "r"(a[1]), "r"(a[2]), "r"(a[3]), "r"(b[0]), "r"(b[1]));
}

__device__ __forceinline__ void ldsm_x4(uint32_t& r0, uint32_t& r1,
                                        uint32_t& r2, uint32_t& r3, uint32_t addr) {
    asm volatile("ldmatrix.sync.aligned.m8n8.x4.shared.b16 {%0,%1,%2,%3}, [%4];"
        : "=r"(r0), "=r"(r1), "=r"(r2), "=r"(r3) : "r"(addr));
}

__device__ __forceinline__ uint32_t smem_u32(const void* p) {
    uint32_t a;
    asm("{ .reg .u64 t; cvta.to.shared.u64 t, %1; cvt.u32.u64 %0, t; }"
        : "=r"(a) : "l"(p));
    return a;
}

__device__ __forceinline__ void cp16(uint32_t dst, const void* src) {
    asm volatile("cp.async.ca.shared.global [%0], [%1], 16;" :: "r"(dst), "l"(src));
}
#define CP_COMMIT() asm volatile("cp.async.commit_group;" ::: "memory")
#define CP_WAIT(n)  asm volatile("cp.async.wait_group %0;" :: "n"(n) : "memory")

// ---------------------------------------------------------------------------
// Weight transpose: z=0,1 -> bf16 (Wq, Wk); z=2,3 -> tf32 fp32 (Wv, Wo)
// ---------------------------------------------------------------------------
__global__ void transpose4(const float* __restrict__ W0, const float* __restrict__ W1,
                           const float* __restrict__ W2, const float* __restrict__ W3,
                           __nv_bfloat16* __restrict__ WTH, float* __restrict__ WT)
{
    __shared__ float t[32][33];
    const int z = blockIdx.z;
    const float* W = (z == 0) ? W0 : (z == 1) ? W1 : (z == 2) ? W2 : W3;
    int bx = blockIdx.x * 32, by = blockIdx.y * 32;
    for (int j = threadIdx.y; j < 32; j += 8)
        t[j][threadIdx.x] = W[(size_t)(by + j) * DM + bx + threadIdx.x];
    __syncthreads();
    if (z < 2) {
        __nv_bfloat16* d = WTH + (size_t)z * DM * DM;
        for (int j = threadIdx.y; j < 32; j += 8)
            d[(size_t)(bx + j) * DM + by + threadIdx.x] =
                __float2bfloat16_rn(t[threadIdx.x][j]);
    } else {
        float* d = WT + (size_t)(z - 2) * DM * DM;
        for (int j = threadIdx.y; j < 32; j += 8)
            d[(size_t)(bx + j) * DM + by + threadIdx.x] = to_tf32(t[threadIdx.x][j]);
    }
}

// ---------------------------------------------------------------------------
// Input prep: z=0,1 -> bf16 (queries, keys); z=2 -> tf32 fp32 (values)
// ---------------------------------------------------------------------------
__global__ __launch_bounds__(256) void prep_inputs(
    const float* __restrict__ q, const float* __restrict__ k,
    const float* __restrict__ v, __nv_bfloat16* __restrict__ INH,
    float* __restrict__ IN)
{
    const int z = blockIdx.z;
    const float* src = (z == 0) ? q : (z == 1) ? k : v;
    const size_t n4 = (size_t)MROWS * DM / 4;
    if (z < 2) {
        __nv_bfloat16* d = INH + (size_t)z * MROWS * DM;
        for (size_t i = blockIdx.x * 256 + threadIdx.x; i < n4; i += (size_t)gridDim.x * 256) {
            float4 x = ((const float4*)src)[i];
            __nv_bfloat162 lo = __float22bfloat162_rn(make_float2(x.x, x.y));
            __nv_bfloat162 hi = __float22bfloat162_rn(make_float2(x.z, x.w));
            uint2 pk;
            pk.x = *(uint32_t*)&lo;
            pk.y = *(uint32_t*)&hi;
            ((uint2*)d)[i] = pk;
        }
    } else {
        for (size_t i = blockIdx.x * 256 + threadIdx.x; i < n4; i += (size_t)gridDim.x * 256) {
            float4 x = ((const float4*)src)[i];
            x.x = to_tf32(x.x); x.y = to_tf32(x.y);
            x.z = to_tf32(x.z); x.w = to_tf32(x.w);
            ((float4*)IN)[i] = x;
        }
    }
}

// ---------------------------------------------------------------------------
// TF32 mma GEMM core, 2-stage cp.async pipeline (V-proj + out-proj). Unchanged.
// mode: 0 = fp32 +bias; 1 = fp32 tf32-rounded
// ---------------------------------------------------------------------------
#define GBM 128
#define GBN 128
#define GBK 32
#define SSTRIDE 36
#define TILE_FLOATS (GBM * SSTRIDE)
#define STAGE_FLOATS (2 * TILE_FLOATS)
#define SMEM_GEMM (2 * STAGE_FLOATS * 4)

__device__ __forceinline__ void gemm_stage_issue(
    const float* __restrict__ A, const float* __restrict__ BT,
    int bm, int bn, int k0, uint32_t sA_addr, uint32_t sB_addr, int tid)
{
#pragma unroll
    for (int i = 0; i < 4; i++) {
        int idx = tid + i * 256;
        int r = idx >> 3;
        int c4 = idx & 7;
        uint32_t off = (uint32_t)(r * SSTRIDE + c4 * 4) * 4;
        cp16(sA_addr + off, &A[(size_t)(bm + r) * DM + k0 + c4 * 4]);
        cp16(sB_addr + off, &BT[(size_t)(bn + r) * DM + k0 + c4 * 4]);
    }
    CP_COMMIT();
}

__device__ __forceinline__ void gemm_core(
    const float* __restrict__ A, const float* __restrict__ BT,
    const float* __restrict__ bias, float* __restrict__ C,
    int mode, float* dsm)
{
    const uint32_t sbase = smem_u32(dsm);
    const int tid = threadIdx.x;
    const int wid = tid >> 5;
    const int lane = tid & 31;
    const int gID = lane >> 2;
    const int ig  = lane & 3;
    const int warp_m = wid >> 2;
    const int warp_n = wid & 3;
    const int bm = blockIdx.y * GBM;
    const int bn = blockIdx.x * GBN;

    float acc[4][4][4];
#pragma unroll
    for (int i = 0; i < 4; i++)
#pragma unroll
        for (int j = 0; j < 4; j++)
#pragma unroll
            for (int v = 0; v < 4; v++) acc[i][j][v] = 0.0f;

    const int kSteps = DM / GBK;

    gemm_stage_issue(A, BT, bm, bn, 0, sbase, sbase + TILE_FLOATS * 4, tid);

    for (int kt = 0; kt < kSteps; kt++) {
        const int cur = kt & 1;
        if (kt + 1 < kSteps) {
            const int nxt = (kt + 1) & 1;
            gemm_stage_issue(A, BT, bm, bn, (kt + 1) * GBK,
                             sbase + nxt * STAGE_FLOATS * 4,
                             sbase + (nxt * STAGE_FLOATS + TILE_FLOATS) * 4, tid);
            CP_WAIT(1);
        } else {
            CP_WAIT(0);
        }
        __syncthreads();

        const float* sA = dsm + cur * STAGE_FLOATS;
        const float* sB = sA + TILE_FLOATS;

#pragma unroll
        for (int kk = 0; kk < GBK; kk += 8) {
            uint32_t afrag[4][4];
#pragma unroll
            for (int mt = 0; mt < 4; mt++) {
                int r0 = warp_m * 64 + mt * 16 + gID;
                afrag[mt][0] = __float_as_uint(sA[r0 * SSTRIDE + kk + ig]);
                afrag[mt][1] = __float_as_uint(sA[(r0 + 8) * SSTRIDE + kk + ig]);
                afrag[mt][2] = __float_as_uint(sA[r0 * SSTRIDE + kk + ig + 4]);
                afrag[mt][3] = __float_as_uint(sA[(r0 + 8) * SSTRIDE + kk + ig + 4]);
            }
            uint32_t bfrag[4][2];
#pragma unroll
            for (int nt = 0; nt < 4; nt++) {
                int n0 = warp_n * 32 + nt * 8 + gID;
                bfrag[nt][0] = __float_as_uint(sB[n0 * SSTRIDE + kk + ig]);
                bfrag[nt][1] = __float_as_uint(sB[n0 * SSTRIDE + kk + ig + 4]);
            }
#pragma unroll
            for (int mt = 0; mt < 4; mt++)
#pragma unroll
                for (int nt = 0; nt < 4; nt++)
                    mma_tf32(acc[mt][nt], afrag[mt], bfrag[nt]);
        }
        __syncthreads();
    }

#pragma unroll
    for (int mt = 0; mt < 4; mt++) {
#pragma unroll
        for (int nt = 0; nt < 4; nt++) {
            int row = bm + warp_m * 64 + mt * 16 + gID;
            int col = bn + warp_n * 32 + nt * 8 + ig * 2;
            float2 v0, v1;
            v0.x = acc[mt][nt][0]; v0.y = acc[mt][nt][1];
            v1.x = acc[mt][nt][2]; v1.y = acc[mt][nt][3];
            if (mode == 0 && bias) {
                float b0 = bias[col], b1 = bias[col + 1];
                v0.x += b0; v0.y += b1;
                v1.x += b0; v1.y += b1;
            }
            if (mode == 1) {
                v0.x = to_tf32(v0.x); v0.y = to_tf32(v0.y);
                v1.x = to_tf32(v1.x); v1.y = to_tf32(v1.y);
            }
            *(float2*)&C[(size_t)row * DM + col] = v0;
            *(float2*)&C[(size_t)(row + 8) * DM + col] = v1;
        }
    }
}

__global__ __launch_bounds__(256, 2) void gemm_v(
    const float* __restrict__ A, const float* __restrict__ BT,
    float* __restrict__ C)
{
    extern __shared__ float dsm[];
    gemm_core(A, BT, nullptr, C, 1, dsm);
}

__global__ __launch_bounds__(256, 2) void gemm_out(
    const float* __restrict__ A, const float* __restrict__ BT,
    const float* __restrict__ bias, float* __restrict__ C)
{
    extern __shared__ float dsm[];
    gemm_core(A, BT, bias, C, 0, dsm);
}

// ---------------------------------------------------------------------------
// BF16 mma GEMM (Q and K projections): m16n8k16, tile 128x128, BK=32 bf16.
// Fragments via ldmatrix.x4 (6 loads per k16-step instead of 24 scalar LDS).
// ---------------------------------------------------------------------------
#define HST 28                       // uint32 per smem row
#define HTILE_U32 (GBM * HST)
#define HSTAGE_U32 (2 * HTILE_U32)
#define SMEM_GEMMH (2 * HSTAGE_U32 * 4)

__device__ __forceinline__ void gemmh_stage_issue(
    const __nv_bfloat16* __restrict__ A, const __nv_bfloat16* __restrict__ BT,
    int bm, int bn, int k0, uint32_t sA_addr, uint32_t sB_addr, int tid)
{
#pragma unroll
    for (int i = 0; i < 2; i++) {
        int idx = tid + i * 256;
        int r = idx >> 2;
        int c = idx & 3;
        uint32_t off = (uint32_t)(r * HST * 4 + c * 16);
        cp16(sA_addr + off, A + (size_t)(bm + r) * DM + k0 + c * 8);
        cp16(sB_addr + off, BT + (size_t)(bn + r) * DM + k0 + c * 8);
    }
    CP_COMMIT();
}

__global__ __launch_bounds__(256, 2) void gemm_bf16qk(
    const __nv_bfloat16* __restrict__ INH, const __nv_bfloat16* __restrict__ WTH,
    __nv_bfloat16* __restrict__ Qo, __nv_bfloat16* __restrict__ Ko)
{
    extern __shared__ uint32_t hsm[];
    const int z = blockIdx.z;
    const __nv_bfloat16* A  = INH + (size_t)z * MROWS * DM;
    const __nv_bfloat16* BT = WTH + (size_t)z * DM * DM;
    __nv_bfloat16* C = z ? Ko : Qo;

    const uint32_t sbase = smem_u32(hsm);
    const int tid = threadIdx.x;
    const int wid = tid >> 5;
    const int lane = tid & 31;
    const int gID = lane >> 2;
    const int ig  = lane & 3;
    const int lm_m = lane >> 3;   // ldmatrix matrix id
    const int lm_r = lane & 7;    // ldmatrix row within matrix
    const int warp_m = wid >> 2;
    const int warp_n = wid & 3;
    const int bm = blockIdx.y * GBM;
    const int bn = blockIdx.x * GBN;

    float acc[4][4][4];
#pragma unroll
    for (int i = 0; i < 4; i++)
#pragma unroll
        for (int j = 0; j < 4; j++)
#pragma unroll
            for (int v = 0; v < 4; v++) acc[i][j][v] = 0.0f;

    const int kSteps = DM / GBK;   // 32 (BK = 32 bf16 elements)

    gemmh_stage_issue(A, BT, bm, bn, 0, sbase, sbase + HTILE_U32 * 4, tid);

    for (int kt = 0; kt < kSteps; kt++) {
        const int cur = kt & 1;
        if (kt + 1 < kSteps) {
            const int nxt = (kt + 1) & 1;
            gemmh_stage_issue(A, BT, bm, bn, (kt + 1) * GBK,
                              sbase + nxt * HSTAGE_U32 * 4,
                              sbase + (nxt * HSTAGE_U32 + HTILE_U32) * 4, tid);
            CP_WAIT(1);
        } else {
            CP_WAIT(0);
        }
        __syncthreads();

        const uint32_t sAa = sbase + (uint32_t)(cur * HSTAGE_U32 * 4);
        const uint32_t sBa = sAa + HTILE_U32 * 4;

#pragma unroll
        for (int st = 0; st < 2; st++) {       // two k16 steps per buffer
            uint32_t afrag[4][4];
#pragma unroll
            for (int mt = 0; mt < 4; mt++) {
                uint32_t addr = sAa + (uint32_t)(
                    ((warp_m * 64 + mt * 16 + (lm_m & 1) * 8 + lm_r) * HST
                     + st * 8 + (lm_m >> 1) * 4) * 4);
                ldsm_x4(afrag[mt][0], afrag[mt][1], afrag[mt][2], afrag[mt][3], addr);
            }
            uint32_t bfrag[4][2];
#pragma unroll
            for (int p = 0; p < 2; p++) {
                uint32_t addr = sBa + (uint32_t)(
                    ((warp_n * 32 + p * 16 + (lm_m >> 1) * 8 + lm_r) * HST
                     + st * 8 + (lm_m & 1) * 4) * 4);
                ldsm_x4(bfrag[2*p][0], bfrag[2*p][1],
                        bfrag[2*p+1][0], bfrag[2*p+1][1], addr);
            }
#pragma unroll
            for (int mt = 0; mt < 4; mt++)
#pragma unroll
                for (int nt = 0; nt < 4; nt++)
                    mma_bf16(acc[mt][nt], afrag[mt], bfrag[nt]);
        }
        __syncthreads();
    }

    const float esc = z ? 1.0f : QSCALE;
#pragma unroll
    for (int mt = 0; mt < 4; mt++) {
#pragma unroll
        for (int nt = 0; nt < 4; nt++) {
            int row = bm + warp_m * 64 + mt * 16 + gID;
            int col = bn + warp_n * 32 + nt * 8 + ig * 2;
            float2 v0, v1;
            v0.x = acc[mt][nt][0] * esc; v0.y = acc[mt][nt][1] * esc;
            v1.x = acc[mt][nt][2] * esc; v1.y = acc[mt][nt][3] * esc;
            *(__nv_bfloat162*)&C[(size_t)row * DM + col] = __float22bfloat162_rn(v0);
            *(__nv_bfloat162*)&C[(size_t)(row + 8) * DM + col] = __float22bfloat162_rn(v1);
        }
    }
}

// ---------------------------------------------------------------------------
// Flash attention: bf16 QK (K frags via ldmatrix), tf32 PV.
// CTA = 128 q-rows, 8 warps; Q in regs; K/V double-buffered cp.async.
// ---------------------------------------------------------------------------
#define QROWS 128
#define PST 68
#define KST 72
#define VST 72
#define KTILE 64
#define SP_F (QROWS * PST)
#define SK_H (KTILE * KST)
#define SV_F (KTILE * VST)
#define SMEM_ATT (SP_F * 4 + 2 * SV_F * 4 + 2 * SK_H * 2)

__device__ __forceinline__ void attn_stage_issue(
    const __nv_bfloat16* __restrict__ Kh, const float* __restrict__ Vp,
    int b, int h, int kt, uint32_t sK_addr, uint32_t sV_addr, int tid)
{
    const __nv_bfloat16* Kbase = Kh + ((size_t)b * NK + kt * KTILE) * DM + h * HD;
    const float* Vbase = Vp + ((size_t)b * NK + kt * KTILE) * DM + h * HD;
#pragma unroll
    for (int i = 0; i < 2; i++) {
        int idx = tid + i * 256;
        int r = idx >> 3;
        int c16 = idx & 7;
        cp16(sK_addr + (uint32_t)(r * KST * 2 + c16 * 16),
             Kbase + (size_t)r * DM + c16 * 8);
    }
#pragma unroll
    for (int i = 0; i < 4; i++) {
        int idx = tid + i * 256;
        int r = idx >> 4;
        int c4 = idx & 15;
        cp16(sV_addr + (uint32_t)(r * VST + c4 * 4) * 4,
             Vbase + (size_t)r * DM + c4 * 4);
    }
    CP_COMMIT();
}

__global__ __launch_bounds__(256, 2) void attn_mma(
    const __nv_bfloat16* __restrict__ Qh, const __nv_bfloat16* __restrict__ Kh,
    const float* __restrict__ Vp, float* __restrict__ Op)
{
    extern __shared__ float sm[];
    float* sP = sm;
    float* sV = sP + SP_F;
    __nv_bfloat16* sKh = (__nv_bfloat16*)(sV + 2 * SV_F);
    const uint32_t sKa = smem_u32(sKh);
    const uint32_t sVa = smem_u32(sV);

    const int tid = threadIdx.x;
    const int wid = tid >> 5;
    const int lane = tid & 31;
    const int gID = lane >> 2;
    const int ig  = lane & 3;
    const int lm_m = lane >> 3;
    const int lm_r = lane & 7;
    const int qt = blockIdx.x;
    const int h  = blockIdx.y;
    const int b  = blockIdx.z;

    const int r0 = wid * 16 + gID;

    attn_stage_issue(Kh, Vp, b, h, 0, sKa, sVa, tid);

    uint32_t qf[4][4];
    {
        const __nv_bfloat16* Qb =
            Qh + ((size_t)b * NQ + qt * QROWS + r0) * DM + h * HD;
#pragma unroll
        for (int st = 0; st < 4; st++) {
            int kk0 = st * 16;
            qf[st][0] = *(const uint32_t*)&Qb[kk0 + 2 * ig];
            qf[st][1] = *(const uint32_t*)&Qb[8 * DM + kk0 + 2 * ig];
            qf[st][2] = *(const uint32_t*)&Qb[kk0 + 8 + 2 * ig];
            qf[st][3] = *(const uint32_t*)&Qb[8 * DM + kk0 + 8 + 2 * ig];
        }
    }

    // per-lane ldmatrix row/col offsets for K tiles (pair p covers n-tiles 2p, 2p+1)
    const uint32_t lm_rowoff = (uint32_t)((lm_m >> 1) * 8 + lm_r);  // row within pair
    const uint32_t lm_coloff = (uint32_t)((lm_m & 1) * 8);          // k-half (bf16 elems)

    float m0 = -1e30f, m1 = -1e30f, l0 = 0.0f, l1 = 0.0f;
    float oacc[8][4];
#pragma unroll
    for (int nt = 0; nt < 8; nt++)
#pragma unroll
        for (int v = 0; v < 4; v++) oacc[nt][v] = 0.0f;

    const int nTiles = NK / KTILE;
    for (int kt = 0; kt < nTiles; kt++) {
        const int cur = kt & 1;
        CP_WAIT(0);
        __syncthreads();
        if (kt + 1 < nTiles) {
            const int nxt = (kt + 1) & 1;
            attn_stage_issue(Kh, Vp, b, h, kt + 1,
                             sKa + nxt * SK_H * 2, sVa + nxt * SV_F * 4, tid);
        }
        const uint32_t cKa = sKa + (uint32_t)(cur * SK_H * 2);
        const float* cV = sV + cur * SV_F;

        // ---- S = Q @ K^T : K B-frags via ldmatrix.x4 (2 n-tiles per load) ----
        float s[8][4];
#pragma unroll
        for (int nt = 0; nt < 8; nt++)
#pragma unroll
            for (int v = 0; v < 4; v++) s[nt][v] = 0.0f;

#pragma unroll
        for (int st = 0; st < 4; st++) {
#pragma unroll
            for (int p = 0; p < 4; p++) {
                uint32_t addr = cKa + (uint32_t)(
                    ((p * 16 + lm_rowoff) * KST + st * 16 + lm_coloff) * 2);
                uint32_t b0, b1, b2, b3;
                ldsm_x4(b0, b1, b2, b3, addr);
                uint32_t bb0[2] = {b0, b1};
                uint32_t bb1[2] = {b2, b3};
                mma_bf16(s[2*p],     qf[st], bb0);
                mma_bf16(s[2*p + 1], qf[st], bb1);
            }
        }

        // ---- Online softmax (rows r0, r0+8; quad-local reductions) ----
        float mt0 = -1e30f, mt1 = -1e30f;
#pragma unroll
        for (int nt = 0; nt < 8; nt++) {
            mt0 = fmaxf(mt0, fmaxf(s[nt][0], s[nt][1]));
            mt1 = fmaxf(mt1, fmaxf(s[nt][2], s[nt][3]));
        }
        mt0 = fmaxf(mt0, __shfl_xor_sync(0xffffffffu, mt0, 1));
        mt0 = fmaxf(mt0, __shfl_xor_sync(0xffffffffu, mt0, 2));
        mt1 = fmaxf(mt1, __shfl_xor_sync(0xffffffffu, mt1, 1));
        mt1 = fmaxf(mt1, __shfl_xor_sync(0xffffffffu, mt1, 2));

        float mn0 = fmaxf(m0, mt0), mn1 = fmaxf(m1, mt1);
        float a0 = ex2(m0 - mn0), a1 = ex2(m1 - mn1);
        m0 = mn0; m1 = mn1;

        float rs0 = 0.0f, rs1 = 0.0f;
#pragma unroll
        for (int nt = 0; nt < 8; nt++) {
            float p00 = ex2(s[nt][0] - mn0);
            float p01 = ex2(s[nt][1] - mn0);
            float p10 = ex2(s[nt][2] - mn1);
            float p11 = ex2(s[nt][3] - mn1);
            rs0 += p00 + p01;
            rs1 += p10 + p11;
            int c = nt * 8 + ig * 2;
            float2 q0; q0.x = to_tf32(p00); q0.y = to_tf32(p01);
            *(float2*)&sP[r0 * PST + c] = q0;
            float2 q1; q1.x = to_tf32(p10); q1.y = to_tf32(p11);
            *(float2*)&sP[(r0 + 8) * PST + c] = q1;
        }
        rs0 += __shfl_xor_sync(0xffffffffu, rs0, 1);
        rs0 += __shfl_xor_sync(0xffffffffu, rs0, 2);
        rs1 += __shfl_xor_sync(0xffffffffu, rs1, 1);
        rs1 += __shfl_xor_sync(0xffffffffu, rs1, 2);
        l0 = l0 * a0 + rs0;
        l1 = l1 * a1 + rs1;

#pragma unroll
        for (int nt = 0; nt < 8; nt++) {
            oacc[nt][0] *= a0; oacc[nt][1] *= a0;
            oacc[nt][2] *= a1; oacc[nt][3] *= a1;
        }
        __syncwarp();   // warp-private sP slab

        // ---- oacc += P @ V (tf32, V row-major) ----
#pragma unroll
        for (int k8 = 0; k8 < 8; k8++) {
            const int kk = k8 * 8;
            uint32_t af[4];
            af[0] = __float_as_uint(sP[r0 * PST + kk + ig]);
            af[1] = __float_as_uint(sP[(r0 + 8) * PST + kk + ig]);
            af[2] = __float_as_uint(sP[r0 * PST + kk + ig + 4]);
            af[3] = __float_as_uint(sP[(r0 + 8) * PST + kk + ig + 4]);
#pragma unroll
            for (int nt = 0; nt < 8; nt++) {
                int n0 = nt * 8 + gID;
                uint32_t bf[2];
                bf[0] = __float_as_uint(cV[(kk + ig) * VST + n0]);
                bf[1] = __float_as_uint(cV[(kk + ig + 4) * VST + n0]);
                mma_tf32(oacc[nt], af, bf);
            }
        }
        // no trailing __syncthreads: the top-of-loop barrier (after CP_WAIT)
        // already orders all reads of buffer `cur` before any warp can issue
        // the prefetch that overwrites it (issued only after that barrier).
    }

    float inv0 = 1.0f / l0, inv1 = 1.0f / l1;
    const int grow = qt * QROWS + r0;
#pragma unroll
    for (int nt = 0; nt < 8; nt++) {
        int col = h * HD + nt * 8 + ig * 2;
        float2 o0;
        o0.x = to_tf32(oacc[nt][0] * inv0);
        o0.y = to_tf32(oacc[nt][1] * inv0);
        *(float2*)&Op[((size_t)b * NQ + grow) * DM + col] = o0;
        float2 o1;
        o1.x = to_tf32(oacc[nt][2] * inv1);
        o1.y = to_tf32(oacc[nt][3] * inv1);
        *(float2*)&Op[((size_t)b * NQ + grow + 8) * DM + col] = o1;
    }
}

// ---------------------------------------------------------------------------
// Launch
// ---------------------------------------------------------------------------
extern "C" void kernel_launch(void* const* d_in, const int* in_sizes, int n_in,
                              void* d_out, int out_size)
{
    const float* queries = (const float*)d_in[0];
    const float* keys    = (const float*)d_in[1];
    const float* values  = (const float*)d_in[2];
    const float* Wq      = (const float*)d_in[3];
    const float* Wk      = (const float*)d_in[4];
    const float* Wv      = (const float*)d_in[5];
    const float* Wo      = (const float*)d_in[6];
    const float* bo      = (const float*)d_in[7];
    float* out           = (float*)d_out;

    __nv_bfloat16 *Qh, *Kh, *WTH, *INH;
    float *Vp, *Op, *WT, *IN;
    cudaGetSymbolAddress((void**)&Qh, g_Qh);
    cudaGetSymbolAddress((void**)&Kh, g_Kh);
    cudaGetSymbolAddress((void**)&Vp, g_V);
    cudaGetSymbolAddress((void**)&Op, g_O);
    cudaGetSymbolAddress((void**)&WTH, g_WTH);
    cudaGetSymbolAddress((void**)&WT, g_WT);
    cudaGetSymbolAddress((void**)&INH, g_INH);
    cudaGetSymbolAddress((void**)&IN, g_IN);

    static bool attr_set = false;
    if (!attr_set) {
        cudaFuncSetAttribute(attn_mma,
                             cudaFuncAttributeMaxDynamicSharedMemorySize, SMEM_ATT);
        cudaFuncSetAttribute(gemm_bf16qk,
                             cudaFuncAttributeMaxDynamicSharedMemorySize, SMEM_GEMMH);
        cudaFuncSetAttribute(gemm_v,
                             cudaFuncAttributeMaxDynamicSharedMemorySize, SMEM_GEMM);
        cudaFuncSetAttribute(gemm_out,
                             cudaFuncAttributeMaxDynamicSharedMemorySize, SMEM_GEMM);
        attr_set = true;
    }

    dim3 tgrid(DM / 32, DM / 32, 4), tblk(32, 8);
    transpose4<<<tgrid, tblk>>>(Wq, Wk, Wv, Wo, WTH, WT);

    dim3 pgrid(1024, 1, 3);
    prep_inputs<<<pgrid, 256>>>(queries, keys, values, INH, IN);

    dim3 hgrid(DM / GBN, MROWS / GBM, 2);   // Q and K projections, bf16
    gemm_bf16qk<<<hgrid, 256, SMEM_GEMMH>>>(INH, WTH, Qh, Kh);

    dim3 vgrid(DM / GBN, MROWS / GBM);      // V projection, tf32
    gemm_v<<<vgrid, 256, SMEM_GEMM>>>(IN, WT, Vp);

    dim3 agrid(NQ / QROWS, NH, BATCH);
    attn_mma<<<agrid, 256, SMEM_ATT>>>(Qh, Kh, Vp, Op);

    dim3 ogrid(DM / GBN, MROWS / GBM);
    gemm_out<<<ogrid, 256, SMEM_GEMM>>>(Op, WT + (size_t)DM * DM, bo, out);
}

// round 12
// speedup vs baseline: 5.1378x; 1.0418x over previous
#include <cuda_runtime.h>
#include <cuda_bf16.h>
#include <math.h>
#include <stdint.h>

#define BATCH 4
#define NQ 2048
#define NK 2048
#define DM 1024
#define NH 16
#define HD 64
#define MROWS (BATCH * NQ)   // 8192

// Scratch
__device__ __nv_bfloat16 g_Qh[MROWS * DM];
__device__ __nv_bfloat16 g_Kh[MROWS * DM];
__device__ float g_V[MROWS * DM];
__device__ float g_O[MROWS * DM];
__device__ __nv_bfloat16 g_WTH[2 * DM * DM];
__device__ float g_WT[2 * DM * DM];
__device__ __nv_bfloat16 g_INH[2 * MROWS * DM];
__device__ float g_IN[MROWS * DM];

#define QSCALE (0.03125f * 1.4426950408889634f)   // 1/sqrt(1024) * log2(e)

__device__ __forceinline__ float to_tf32(float x) {
    float r;
    asm("cvt.rna.tf32.f32 %0, %1;" : "=f"(r) : "f"(x));
    return r;
}

__device__ __forceinline__ float ex2(float x) {
    float r;
    asm("ex2.approx.ftz.f32 %0, %1;" : "=f"(r) : "f"(x));
    return r;
}

__device__ __forceinline__ void mma_tf32(float* c, const uint32_t* a, const uint32_t* b) {
    asm volatile(
        "mma.sync.aligned.m16n8k8.row.col.f32.tf32.tf32.f32 "
        "{%0,%1,%2,%3}, {%4,%5,%6,%7}, {%8,%9}, {%0,%1,%2,%3};"
        : "+f"(c[0]), "+f"(c[1]), "+f"(c[2]), "+f"(c[3])
        : "r"(a[0]), "r"(a[1]), "r"(a[2]), "r"(a[3]), "r"(b[0]), "r"(b[1]));
}

__device__ __forceinline__ void mma_bf16(float* c, const uint32_t* a, const uint32_t* b) {
    asm volatile(
        "mma.sync.aligned.m16n8k16.row.col.f32.bf16.bf16.f32 "
        "{%0,%1,%2,%3}, {%4,%5,%6,%7}, {%8,%9}, {%0,%1,%2,%3};"
        : "+f"(c[0]), "+f"(c[1]), "+f"(c[2]), "+f"(c[3])
        : "r"(a[0]), "r"(a[1]), "r"(a[2]), "r"(a[3]), "r"(b[0]), "r"(b[1]));
}

__device__ __forceinline__ void ldsm_x4(uint32_t& r0, uint32_t& r1,
                                        uint32_t& r2, uint32_t& r3, uint32_t addr) {
    asm volatile("ldmatrix.sync.aligned.m8n8.x4.shared.b16 {%0,%1,%2,%3}, [%4];"
        : "=r"(r0), "=r"(r1), "=r"(r2), "=r"(r3) : "r"(addr));
}

__device__ __forceinline__ uint32_t smem_u32(const void* p) {
    uint32_t a;
    asm("{ .reg .u64 t; cvta.to.shared.u64 t, %1; cvt.u32.u64 %0, t; }"
        : "=r"(a) : "l"(p));
    return a;
}

__device__ __forceinline__ void cp16(uint32_t dst, const void* src) {
    asm volatile("cp.async.ca.shared.global [%0], [%1], 16;" :: "r"(dst), "l"(src));
}
#define CP_COMMIT() asm volatile("cp.async.commit_group;" ::: "memory")
#define CP_WAIT(n)  asm volatile("cp.async.wait_group %0;" :: "n"(n) : "memory")

// ---------------------------------------------------------------------------
// Weight transpose: z=0,1 -> bf16 (Wq, Wk); z=2,3 -> tf32 fp32 (Wv, Wo)
// ---------------------------------------------------------------------------
__global__ void transpose4(const float* __restrict__ W0, const float* __restrict__ W1,
                           const float* __restrict__ W2, const float* __restrict__ W3,
                           __nv_bfloat16* __restrict__ WTH, float* __restrict__ WT)
{
    __shared__ float t[32][33];
    const int z = blockIdx.z;
    const float* W = (z == 0) ? W0 : (z == 1) ? W1 : (z == 2) ? W2 : W3;
    int bx = blockIdx.x * 32, by = blockIdx.y * 32;
    for (int j = threadIdx.y; j < 32; j += 8)
        t[j][threadIdx.x] = W[(size_t)(by + j) * DM + bx + threadIdx.x];
    __syncthreads();
    if (z < 2) {
        __nv_bfloat16* d = WTH + (size_t)z * DM * DM;
        for (int j = threadIdx.y; j < 32; j += 8)
            d[(size_t)(bx + j) * DM + by + threadIdx.x] =
                __float2bfloat16_rn(t[threadIdx.x][j]);
    } else {
        float* d = WT + (size_t)(z - 2) * DM * DM;
        for (int j = threadIdx.y; j < 32; j += 8)
            d[(size_t)(bx + j) * DM + by + threadIdx.x] = to_tf32(t[threadIdx.x][j]);
    }
}

// ---------------------------------------------------------------------------
// Input prep: z=0,1 -> bf16 (queries, keys); z=2 -> tf32 fp32 (values)
// ---------------------------------------------------------------------------
__global__ __launch_bounds__(256) void prep_inputs(
    const float* __restrict__ q, const float* __restrict__ k,
    const float* __restrict__ v, __nv_bfloat16* __restrict__ INH,
    float* __restrict__ IN)
{
    const int z = blockIdx.z;
    const float* src = (z == 0) ? q : (z == 1) ? k : v;
    const size_t n4 = (size_t)MROWS * DM / 4;
    if (z < 2) {
        __nv_bfloat16* d = INH + (size_t)z * MROWS * DM;
        for (size_t i = blockIdx.x * 256 + threadIdx.x; i < n4; i += (size_t)gridDim.x * 256) {
            float4 x = ((const float4*)src)[i];
            __nv_bfloat162 lo = __float22bfloat162_rn(make_float2(x.x, x.y));
            __nv_bfloat162 hi = __float22bfloat162_rn(make_float2(x.z, x.w));
            uint2 pk;
            pk.x = *(uint32_t*)&lo;
            pk.y = *(uint32_t*)&hi;
            ((uint2*)d)[i] = pk;
        }
    } else {
        for (size_t i = blockIdx.x * 256 + threadIdx.x; i < n4; i += (size_t)gridDim.x * 256) {
            float4 x = ((const float4*)src)[i];
            x.x = to_tf32(x.x); x.y = to_tf32(x.y);
            x.z = to_tf32(x.z); x.w = to_tf32(x.w);
            ((float4*)IN)[i] = x;
        }
    }
}

// ---------------------------------------------------------------------------
// TF32 mma GEMM core, 2-stage cp.async pipeline, fragments via ldmatrix.x4
// (6 loads per k8-step instead of 24 scalar LDS).
// mode: 0 = fp32 +bias; 1 = fp32 tf32-rounded
// ---------------------------------------------------------------------------
#define GBM 128
#define GBN 128
#define GBK 32
#define SSTRIDE 36
#define TILE_FLOATS (GBM * SSTRIDE)
#define STAGE_FLOATS (2 * TILE_FLOATS)
#define SMEM_GEMM (2 * STAGE_FLOATS * 4)

__device__ __forceinline__ void gemm_stage_issue(
    const float* __restrict__ A, const float* __restrict__ BT,
    int bm, int bn, int k0, uint32_t sA_addr, uint32_t sB_addr, int tid)
{
#pragma unroll
    for (int i = 0; i < 4; i++) {
        int idx = tid + i * 256;
        int r = idx >> 3;
        int c4 = idx & 7;
        uint32_t off = (uint32_t)(r * SSTRIDE + c4 * 4) * 4;
        cp16(sA_addr + off, &A[(size_t)(bm + r) * DM + k0 + c4 * 4]);
        cp16(sB_addr + off, &BT[(size_t)(bn + r) * DM + k0 + c4 * 4]);
    }
    CP_COMMIT();
}

__device__ __forceinline__ void gemm_core(
    const float* __restrict__ A, const float* __restrict__ BT,
    const float* __restrict__ bias, float* __restrict__ C,
    int mode, float* dsm)
{
    const uint32_t sbase = smem_u32(dsm);
    const int tid = threadIdx.x;
    const int wid = tid >> 5;
    const int lane = tid & 31;
    const int gID = lane >> 2;
    const int ig  = lane & 3;
    const int lm_m = lane >> 3;   // ldmatrix matrix id
    const int lm_r = lane & 7;    // ldmatrix row within matrix
    const int warp_m = wid >> 2;
    const int warp_n = wid & 3;
    const int bm = blockIdx.y * GBM;
    const int bn = blockIdx.x * GBN;

    float acc[4][4][4];
#pragma unroll
    for (int i = 0; i < 4; i++)
#pragma unroll
        for (int j = 0; j < 4; j++)
#pragma unroll
            for (int v = 0; v < 4; v++) acc[i][j][v] = 0.0f;

    const int kSteps = DM / GBK;

    gemm_stage_issue(A, BT, bm, bn, 0, sbase, sbase + TILE_FLOATS * 4, tid);

    // A-frag ldmatrix: matrices {rows+0/k-lo, rows+8/k-lo, rows+0/k-hi, rows+8/k-hi}
    const uint32_t a_row = (uint32_t)(warp_m * 64 + (lm_m & 1) * 8 + lm_r);
    const uint32_t a_col = (uint32_t)((lm_m >> 1) * 4);
    // B-frag ldmatrix (2 n-tiles per load): row selects tile, col selects k-half
    const uint32_t b_row = (uint32_t)(warp_n * 32 + (lm_m >> 1) * 8 + lm_r);
    const uint32_t b_col = (uint32_t)((lm_m & 1) * 4);

    for (int kt = 0; kt < kSteps; kt++) {
        const int cur = kt & 1;
        if (kt + 1 < kSteps) {
            const int nxt = (kt + 1) & 1;
            gemm_stage_issue(A, BT, bm, bn, (kt + 1) * GBK,
                             sbase + nxt * STAGE_FLOATS * 4,
                             sbase + (nxt * STAGE_FLOATS + TILE_FLOATS) * 4, tid);
            CP_WAIT(1);
        } else {
            CP_WAIT(0);
        }
        __syncthreads();

        const uint32_t sAa = sbase + (uint32_t)(cur * STAGE_FLOATS * 4);
        const uint32_t sBa = sAa + TILE_FLOATS * 4;

#pragma unroll
        for (int kk = 0; kk < GBK; kk += 8) {
            uint32_t afrag[4][4];
#pragma unroll
            for (int mt = 0; mt < 4; mt++) {
                uint32_t addr = sAa + (uint32_t)(
                    ((a_row + mt * 16) * SSTRIDE + kk + a_col) * 4);
                ldsm_x4(afrag[mt][0], afrag[mt][1], afrag[mt][2], afrag[mt][3], addr);
            }
            uint32_t bfrag[4][2];
#pragma unroll
            for (int p = 0; p < 2; p++) {
                uint32_t addr = sBa + (uint32_t)(
                    ((b_row + p * 16) * SSTRIDE + kk + b_col) * 4);
                ldsm_x4(bfrag[2*p][0], bfrag[2*p][1],
                        bfrag[2*p+1][0], bfrag[2*p+1][1], addr);
            }
#pragma unroll
            for (int mt = 0; mt < 4; mt++)
#pragma unroll
                for (int nt = 0; nt < 4; nt++)
                    mma_tf32(acc[mt][nt], afrag[mt], bfrag[nt]);
        }
        __syncthreads();
    }

#pragma unroll
    for (int mt = 0; mt < 4; mt++) {
#pragma unroll
        for (int nt = 0; nt < 4; nt++) {
            int row = bm + warp_m * 64 + mt * 16 + gID;
            int col = bn + warp_n * 32 + nt * 8 + ig * 2;
            float2 v0, v1;
            v0.x = acc[mt][nt][0]; v0.y = acc[mt][nt][1];
            v1.x = acc[mt][nt][2]; v1.y = acc[mt][nt][3];
            if (mode == 0 && bias) {
                float b0 = bias[col], b1 = bias[col + 1];
                v0.x += b0; v0.y += b1;
                v1.x += b0; v1.y += b1;
            }
            if (mode == 1) {
                v0.x = to_tf32(v0.x); v0.y = to_tf32(v0.y);
                v1.x = to_tf32(v1.x); v1.y = to_tf32(v1.y);
            }
            *(float2*)&C[(size_t)row * DM + col] = v0;
            *(float2*)&C[(size_t)(row + 8) * DM + col] = v1;
        }
    }
}

__global__ __launch_bounds__(256, 2) void gemm_v(
    const float* __restrict__ A, const float* __restrict__ BT,
    float* __restrict__ C)
{
    extern __shared__ float dsm[];
    gemm_core(A, BT, nullptr, C, 1, dsm);
}

__global__ __launch_bounds__(256, 2) void gemm_out(
    const float* __restrict__ A, const float* __restrict__ BT,
    const float* __restrict__ bias, float* __restrict__ C)
{
    extern __shared__ float dsm[];
    gemm_core(A, BT, bias, C, 0, dsm);
}

// ---------------------------------------------------------------------------
// BF16 mma GEMM (Q and K projections): unchanged from R11.
// ---------------------------------------------------------------------------
#define HST 28
#define HTILE_U32 (GBM * HST)
#define HSTAGE_U32 (2 * HTILE_U32)
#define SMEM_GEMMH (2 * HSTAGE_U32 * 4)

__device__ __forceinline__ void gemmh_stage_issue(
    const __nv_bfloat16* __restrict__ A, const __nv_bfloat16* __restrict__ BT,
    int bm, int bn, int k0, uint32_t sA_addr, uint32_t sB_addr, int tid)
{
#pragma unroll
    for (int i = 0; i < 2; i++) {
        int idx = tid + i * 256;
        int r = idx >> 2;
        int c = idx & 3;
        uint32_t off = (uint32_t)(r * HST * 4 + c * 16);
        cp16(sA_addr + off, A + (size_t)(bm + r) * DM + k0 + c * 8);
        cp16(sB_addr + off, BT + (size_t)(bn + r) * DM + k0 + c * 8);
    }
    CP_COMMIT();
}

__global__ __launch_bounds__(256, 2) void gemm_bf16qk(
    const __nv_bfloat16* __restrict__ INH, const __nv_bfloat16* __restrict__ WTH,
    __nv_bfloat16* __restrict__ Qo, __nv_bfloat16* __restrict__ Ko)
{
    extern __shared__ uint32_t hsm[];
    const int z = blockIdx.z;
    const __nv_bfloat16* A  = INH + (size_t)z * MROWS * DM;
    const __nv_bfloat16* BT = WTH + (size_t)z * DM * DM;
    __nv_bfloat16* C = z ? Ko : Qo;

    const uint32_t sbase = smem_u32(hsm);
    const int tid = threadIdx.x;
    const int wid = tid >> 5;
    const int lane = tid & 31;
    const int gID = lane >> 2;
    const int ig  = lane & 3;
    const int lm_m = lane >> 3;
    const int lm_r = lane & 7;
    const int warp_m = wid >> 2;
    const int warp_n = wid & 3;
    const int bm = blockIdx.y * GBM;
    const int bn = blockIdx.x * GBN;

    float acc[4][4][4];
#pragma unroll
    for (int i = 0; i < 4; i++)
#pragma unroll
        for (int j = 0; j < 4; j++)
#pragma unroll
            for (int v = 0; v < 4; v++) acc[i][j][v] = 0.0f;

    const int kSteps = DM / GBK;

    gemmh_stage_issue(A, BT, bm, bn, 0, sbase, sbase + HTILE_U32 * 4, tid);

    for (int kt = 0; kt < kSteps; kt++) {
        const int cur = kt & 1;
        if (kt + 1 < kSteps) {
            const int nxt = (kt + 1) & 1;
            gemmh_stage_issue(A, BT, bm, bn, (kt + 1) * GBK,
                              sbase + nxt * HSTAGE_U32 * 4,
                              sbase + (nxt * HSTAGE_U32 + HTILE_U32) * 4, tid);
            CP_WAIT(1);
        } else {
            CP_WAIT(0);
        }
        __syncthreads();

        const uint32_t sAa = sbase + (uint32_t)(cur * HSTAGE_U32 * 4);
        const uint32_t sBa = sAa + HTILE_U32 * 4;

#pragma unroll
        for (int st = 0; st < 2; st++) {
            uint32_t afrag[4][4];
#pragma unroll
            for (int mt = 0; mt < 4; mt++) {
                uint32_t addr = sAa + (uint32_t)(
                    ((warp_m * 64 + mt * 16 + (lm_m & 1) * 8 + lm_r) * HST
                     + st * 8 + (lm_m >> 1) * 4) * 4);
                ldsm_x4(afrag[mt][0], afrag[mt][1], afrag[mt][2], afrag[mt][3], addr);
            }
            uint32_t bfrag[4][2];
#pragma unroll
            for (int p = 0; p < 2; p++) {
                uint32_t addr = sBa + (uint32_t)(
                    ((warp_n * 32 + p * 16 + (lm_m >> 1) * 8 + lm_r) * HST
                     + st * 8 + (lm_m & 1) * 4) * 4);
                ldsm_x4(bfrag[2*p][0], bfrag[2*p][1],
                        bfrag[2*p+1][0], bfrag[2*p+1][1], addr);
            }
#pragma unroll
            for (int mt = 0; mt < 4; mt++)
#pragma unroll
                for (int nt = 0; nt < 4; nt++)
                    mma_bf16(acc[mt][nt], afrag[mt], bfrag[nt]);
        }
        __syncthreads();
    }

    const float esc = z ? 1.0f : QSCALE;
#pragma unroll
    for (int mt = 0; mt < 4; mt++) {
#pragma unroll
        for (int nt = 0; nt < 4; nt++) {
            int row = bm + warp_m * 64 + mt * 16 + gID;
            int col = bn + warp_n * 32 + nt * 8 + ig * 2;
            float2 v0, v1;
            v0.x = acc[mt][nt][0] * esc; v0.y = acc[mt][nt][1] * esc;
            v1.x = acc[mt][nt][2] * esc; v1.y = acc[mt][nt][3] * esc;
            *(__nv_bfloat162*)&C[(size_t)row * DM + col] = __float22bfloat162_rn(v0);
            *(__nv_bfloat162*)&C[(size_t)(row + 8) * DM + col] = __float22bfloat162_rn(v1);
        }
    }
}

// ---------------------------------------------------------------------------
// Flash attention: bf16 QK (K via ldmatrix), tf32 PV (P via ldmatrix, V scalar).
// ---------------------------------------------------------------------------
#define QROWS 128
#define PST 68
#define KST 72
#define VST 72
#define KTILE 64
#define SP_F (QROWS * PST)
#define SK_H (KTILE * KST)
#define SV_F (KTILE * VST)
#define SMEM_ATT (SP_F * 4 + 2 * SV_F * 4 + 2 * SK_H * 2)

__device__ __forceinline__ void attn_stage_issue(
    const __nv_bfloat16* __restrict__ Kh, const float* __restrict__ Vp,
    int b, int h, int kt, uint32_t sK_addr, uint32_t sV_addr, int tid)
{
    const __nv_bfloat16* Kbase = Kh + ((size_t)b * NK + kt * KTILE) * DM + h * HD;
    const float* Vbase = Vp + ((size_t)b * NK + kt * KTILE) * DM + h * HD;
#pragma unroll
    for (int i = 0; i < 2; i++) {
        int idx = tid + i * 256;
        int r = idx >> 3;
        int c16 = idx & 7;
        cp16(sK_addr + (uint32_t)(r * KST * 2 + c16 * 16),
             Kbase + (size_t)r * DM + c16 * 8);
    }
#pragma unroll
    for (int i = 0; i < 4; i++) {
        int idx = tid + i * 256;
        int r = idx >> 4;
        int c4 = idx & 15;
        cp16(sV_addr + (uint32_t)(r * VST + c4 * 4) * 4,
             Vbase + (size_t)r * DM + c4 * 4);
    }
    CP_COMMIT();
}

__global__ __launch_bounds__(256, 2) void attn_mma(
    const __nv_bfloat16* __restrict__ Qh, const __nv_bfloat16* __restrict__ Kh,
    const float* __restrict__ Vp, float* __restrict__ Op)
{
    extern __shared__ float sm[];
    float* sP = sm;
    float* sV = sP + SP_F;
    __nv_bfloat16* sKh = (__nv_bfloat16*)(sV + 2 * SV_F);
    const uint32_t sPa = smem_u32(sP);
    const uint32_t sKa = smem_u32(sKh);
    const uint32_t sVa = smem_u32(sV);

    const int tid = threadIdx.x;
    const int wid = tid >> 5;
    const int lane = tid & 31;
    const int gID = lane >> 2;
    const int ig  = lane & 3;
    const int lm_m = lane >> 3;
    const int lm_r = lane & 7;
    const int qt = blockIdx.x;
    const int h  = blockIdx.y;
    const int b  = blockIdx.z;

    const int r0 = wid * 16 + gID;

    attn_stage_issue(Kh, Vp, b, h, 0, sKa, sVa, tid);

    uint32_t qf[4][4];
    {
        const __nv_bfloat16* Qb =
            Qh + ((size_t)b * NQ + qt * QROWS + r0) * DM + h * HD;
#pragma unroll
        for (int st = 0; st < 4; st++) {
            int kk0 = st * 16;
            qf[st][0] = *(const uint32_t*)&Qb[kk0 + 2 * ig];
            qf[st][1] = *(const uint32_t*)&Qb[8 * DM + kk0 + 2 * ig];
            qf[st][2] = *(const uint32_t*)&Qb[kk0 + 8 + 2 * ig];
            qf[st][3] = *(const uint32_t*)&Qb[8 * DM + kk0 + 8 + 2 * ig];
        }
    }

    const uint32_t lm_rowoff = (uint32_t)((lm_m >> 1) * 8 + lm_r);
    const uint32_t lm_coloff = (uint32_t)((lm_m & 1) * 8);
    // P A-frag ldmatrix offsets (fp32 data: row/k-half pattern)
    const uint32_t p_row = (uint32_t)(wid * 16 + (lm_m & 1) * 8 + lm_r);
    const uint32_t p_col = (uint32_t)((lm_m >> 1) * 4);

    float m0 = -1e30f, m1 = -1e30f, l0 = 0.0f, l1 = 0.0f;
    float oacc[8][4];
#pragma unroll
    for (int nt = 0; nt < 8; nt++)
#pragma unroll
        for (int v = 0; v < 4; v++) oacc[nt][v] = 0.0f;

    const int nTiles = NK / KTILE;
    for (int kt = 0; kt < nTiles; kt++) {
        const int cur = kt & 1;
        CP_WAIT(0);
        __syncthreads();
        if (kt + 1 < nTiles) {
            const int nxt = (kt + 1) & 1;
            attn_stage_issue(Kh, Vp, b, h, kt + 1,
                             sKa + nxt * SK_H * 2, sVa + nxt * SV_F * 4, tid);
        }
        const uint32_t cKa = sKa + (uint32_t)(cur * SK_H * 2);
        const float* cV = sV + cur * SV_F;

        float s[8][4];
#pragma unroll
        for (int nt = 0; nt < 8; nt++)
#pragma unroll
            for (int v = 0; v < 4; v++) s[nt][v] = 0.0f;

#pragma unroll
        for (int st = 0; st < 4; st++) {
#pragma unroll
            for (int p = 0; p < 4; p++) {
                uint32_t addr = cKa + (uint32_t)(
                    ((p * 16 + lm_rowoff) * KST + st * 16 + lm_coloff) * 2);
                uint32_t b0, b1, b2, b3;
                ldsm_x4(b0, b1, b2, b3, addr);
                uint32_t bb0[2] = {b0, b1};
                uint32_t bb1[2] = {b2, b3};
                mma_bf16(s[2*p],     qf[st], bb0);
                mma_bf16(s[2*p + 1], qf[st], bb1);
            }
        }

        float mt0 = -1e30f, mt1 = -1e30f;
#pragma unroll
        for (int nt = 0; nt < 8; nt++) {
            mt0 = fmaxf(mt0, fmaxf(s[nt][0], s[nt][1]));
            mt1 = fmaxf(mt1, fmaxf(s[nt][2], s[nt][3]));
        }
        mt0 = fmaxf(mt0, __shfl_xor_sync(0xffffffffu, mt0, 1));
        mt0 = fmaxf(mt0, __shfl_xor_sync(0xffffffffu, mt0, 2));
        mt1 = fmaxf(mt1, __shfl_xor_sync(0xffffffffu, mt1, 1));
        mt1 = fmaxf(mt1, __shfl_xor_sync(0xffffffffu, mt1, 2));

        float mn0 = fmaxf(m0, mt0), mn1 = fmaxf(m1, mt1);
        float a0 = ex2(m0 - mn0), a1 = ex2(m1 - mn1);
        m0 = mn0; m1 = mn1;

        float rs0 = 0.0f, rs1 = 0.0f;
#pragma unroll
        for (int nt = 0; nt < 8; nt++) {
            float p00 = ex2(s[nt][0] - mn0);
            float p01 = ex2(s[nt][1] - mn0);
            float p10 = ex2(s[nt][2] - mn1);
            float p11 = ex2(s[nt][3] - mn1);
            rs0 += p00 + p01;
            rs1 += p10 + p11;
            int c = nt * 8 + ig * 2;
            float2 q0; q0.x = to_tf32(p00); q0.y = to_tf32(p01);
            *(float2*)&sP[r0 * PST + c] = q0;
            float2 q1; q1.x = to_tf32(p10); q1.y = to_tf32(p11);
            *(float2*)&sP[(r0 + 8) * PST + c] = q1;
        }
        rs0 += __shfl_xor_sync(0xffffffffu, rs0, 1);
        rs0 += __shfl_xor_sync(0xffffffffu, rs0, 2);
        rs1 += __shfl_xor_sync(0xffffffffu, rs1, 1);
        rs1 += __shfl_xor_sync(0xffffffffu, rs1, 2);
        l0 = l0 * a0 + rs0;
        l1 = l1 * a1 + rs1;

#pragma unroll
        for (int nt = 0; nt < 8; nt++) {
            oacc[nt][0] *= a0; oacc[nt][1] *= a0;
            oacc[nt][2] *= a1; oacc[nt][3] *= a1;
        }
        __syncwarp();   // warp-private sP slab

        // ---- oacc += P @ V (tf32; P A-frags via ldmatrix, V scalar) ----
#pragma unroll
        for (int k8 = 0; k8 < 8; k8++) {
            const int kk = k8 * 8;
            uint32_t af[4];
            {
                uint32_t addr = sPa + (uint32_t)((p_row * PST + kk + p_col) * 4);
                ldsm_x4(af[0], af[1], af[2], af[3], addr);
            }
#pragma unroll
            for (int nt = 0; nt < 8; nt++) {
                int n0 = nt * 8 + gID;
                uint32_t bf[2];
                bf[0] = __float_as_uint(cV[(kk + ig) * VST + n0]);
                bf[1] = __float_as_uint(cV[(kk + ig + 4) * VST + n0]);
                mma_tf32(oacc[nt], af, bf);
            }
        }
    }

    float inv0 = 1.0f / l0, inv1 = 1.0f / l1;
    const int grow = qt * QROWS + r0;
#pragma unroll
    for (int nt = 0; nt < 8; nt++) {
        int col = h * HD + nt * 8 + ig * 2;
        float2 o0;
        o0.x = to_tf32(oacc[nt][0] * inv0);
        o0.y = to_tf32(oacc[nt][1] * inv0);
        *(float2*)&Op[((size_t)b * NQ + grow) * DM + col] = o0;
        float2 o1;
        o1.x = to_tf32(oacc[nt][2] * inv1);
        o1.y = to_tf32(oacc[nt][3] * inv1);
        *(float2*)&Op[((size_t)b * NQ + grow + 8) * DM + col] = o1;
    }
}

// ---------------------------------------------------------------------------
// Launch
// ---------------------------------------------------------------------------
extern "C" void kernel_launch(void* const* d_in, const int* in_sizes, int n_in,
                              void* d_out, int out_size)
{
    const float* queries = (const float*)d_in[0];
    const float* keys    = (const float*)d_in[1];
    const float* values  = (const float*)d_in[2];
    const float* Wq      = (const float*)d_in[3];
    const float* Wk      = (const float*)d_in[4];
    const float* Wv      = (const float*)d_in[5];
    const float* Wo      = (const float*)d_in[6];
    const float* bo      = (const float*)d_in[7];
    float* out           = (float*)d_out;

    __nv_bfloat16 *Qh, *Kh, *WTH, *INH;
    float *Vp, *Op, *WT, *IN;
    cudaGetSymbolAddress((void**)&Qh, g_Qh);
    cudaGetSymbolAddress((void**)&Kh, g_Kh);
    cudaGetSymbolAddress((void**)&Vp, g_V);
    cudaGetSymbolAddress((void**)&Op, g_O);
    cudaGetSymbolAddress((void**)&WTH, g_WTH);
    cudaGetSymbolAddress((void**)&WT, g_WT);
    cudaGetSymbolAddress((void**)&INH, g_INH);
    cudaGetSymbolAddress((void**)&IN, g_IN);

    static bool attr_set = false;
    if (!attr_set) {
        cudaFuncSetAttribute(attn_mma,
                             cudaFuncAttributeMaxDynamicSharedMemorySize, SMEM_ATT);
        cudaFuncSetAttribute(gemm_bf16qk,
                             cudaFuncAttributeMaxDynamicSharedMemorySize, SMEM_GEMMH);
        cudaFuncSetAttribute(gemm_v,
                             cudaFuncAttributeMaxDynamicSharedMemorySize, SMEM_GEMM);
        cudaFuncSetAttribute(gemm_out,
                             cudaFuncAttributeMaxDynamicSharedMemorySize, SMEM_GEMM);
        attr_set = true;
    }

    dim3 tgrid(DM / 32, DM / 32, 4), tblk(32, 8);
    transpose4<<<tgrid, tblk>>>(Wq, Wk, Wv, Wo, WTH, WT);

    dim3 pgrid(1024, 1, 3);
    prep_inputs<<<pgrid, 256>>>(queries, keys, values, INH, IN);

    dim3 hgrid(DM / GBN, MROWS / GBM, 2);
    gemm_bf16qk<<<hgrid, 256, SMEM_GEMMH>>>(INH, WTH, Qh, Kh);

    dim3 vgrid(DM / GBN, MROWS / GBM);
    gemm_v<<<vgrid, 256, SMEM_GEMM>>>(IN, WT, Vp);

    dim3 agrid(NQ / QROWS, NH, BATCH);
    attn_mma<<<agrid, 256, SMEM_ATT>>>(Qh, Kh, Vp, Op);

    dim3 ogrid(DM / GBN, MROWS / GBM);
    gemm_out<<<ogrid, 256, SMEM_GEMM>>>(Op, WT + (size_t)DM * DM, bo, out);
}

// round 13
// speedup vs baseline: 6.3120x; 1.2285x over previous
#include <cuda_runtime.h>
#include <cuda_bf16.h>
#include <cuda_fp16.h>
#include <math.h>
#include <stdint.h>

#define BATCH 4
#define NQ 2048
#define NK 2048
#define DM 1024
#define NH 16
#define HD 64
#define MROWS (BATCH * NQ)   // 8192

// Scratch
__device__ __nv_bfloat16 g_Qh[MROWS * DM];
__device__ __nv_bfloat16 g_Kh[MROWS * DM];
__device__ __half g_Vh[MROWS * DM];              // V proj, fp16
__device__ float g_O[MROWS * DM];                // attention out, tf32-rounded
__device__ __nv_bfloat16 g_WTH[2 * DM * DM];     // Wq^T, Wk^T bf16
__device__ float g_WT[2 * DM * DM];              // Wv^T, Wo^T tf32 fp32
__device__ __nv_bfloat16 g_INH[2 * MROWS * DM];  // bf16 queries, keys
__device__ float g_IN[MROWS * DM];               // tf32 values

#define QSCALE (0.03125f * 1.4426950408889634f)   // 1/sqrt(1024) * log2(e)

__device__ __forceinline__ float to_tf32(float x) {
    float r;
    asm("cvt.rna.tf32.f32 %0, %1;" : "=f"(r) : "f"(x));
    return r;
}

__device__ __forceinline__ float ex2(float x) {
    float r;
    asm("ex2.approx.ftz.f32 %0, %1;" : "=f"(r) : "f"(x));
    return r;
}

__device__ __forceinline__ void mma_tf32(float* c, const uint32_t* a, const uint32_t* b) {
    asm volatile(
        "mma.sync.aligned.m16n8k8.row.col.f32.tf32.tf32.f32 "
        "{%0,%1,%2,%3}, {%4,%5,%6,%7}, {%8,%9}, {%0,%1,%2,%3};"
        : "+f"(c[0]), "+f"(c[1]), "+f"(c[2]), "+f"(c[3])
        : "r"(a[0]), "r"(a[1]), "r"(a[2]), "r"(a[3]), "r"(b[0]), "r"(b[1]));
}

__device__ __forceinline__ void mma_bf16(float* c, const uint32_t* a, const uint32_t* b) {
    asm volatile(
        "mma.sync.aligned.m16n8k16.row.col.f32.bf16.bf16.f32 "
        "{%0,%1,%2,%3}, {%4,%5,%6,%7}, {%8,%9}, {%0,%1,%2,%3};"
        : "+f"(c[0]), "+f"(c[1]), "+f"(c[2]), "+f"(c[3])
        : "r"(a[0]), "r"(a[1]), "r"(a[2]), "r"(a[3]), "r"(b[0]), "r"(b[1]));
}

__device__ __forceinline__ void mma_f16(float* c, const uint32_t* a, const uint32_t* b) {
    asm volatile(
        "mma.sync.aligned.m16n8k16.row.col.f32.f16.f16.f32 "
        "{%0,%1,%2,%3}, {%4,%5,%6,%7}, {%8,%9}, {%0,%1,%2,%3};"
        : "+f"(c[0]), "+f"(c[1]), "+f"(c[2]), "+f"(c[3])
        : "r"(a[0]), "r"(a[1]), "r"(a[2]), "r"(a[3]), "r"(b[0]), "r"(b[1]));
}

__device__ __forceinline__ void ldsm_x4(uint32_t& r0, uint32_t& r1,
                                        uint32_t& r2, uint32_t& r3, uint32_t addr) {
    asm volatile("ldmatrix.sync.aligned.m8n8.x4.shared.b16 {%0,%1,%2,%3}, [%4];"
        : "=r"(r0), "=r"(r1), "=r"(r2), "=r"(r3) : "r"(addr));
}

__device__ __forceinline__ void ldsm_x4_trans(uint32_t& r0, uint32_t& r1,
                                              uint32_t& r2, uint32_t& r3, uint32_t addr) {
    asm volatile("ldmatrix.sync.aligned.m8n8.x4.trans.shared.b16 {%0,%1,%2,%3}, [%4];"
        : "=r"(r0), "=r"(r1), "=r"(r2), "=r"(r3) : "r"(addr));
}

__device__ __forceinline__ uint32_t smem_u32(const void* p) {
    uint32_t a;
    asm("{ .reg .u64 t; cvta.to.shared.u64 t, %1; cvt.u32.u64 %0, t; }"
        : "=r"(a) : "l"(p));
    return a;
}

__device__ __forceinline__ void cp16(uint32_t dst, const void* src) {
    asm volatile("cp.async.ca.shared.global [%0], [%1], 16;" :: "r"(dst), "l"(src));
}
#define CP_COMMIT() asm volatile("cp.async.commit_group;" ::: "memory")
#define CP_WAIT(n)  asm volatile("cp.async.wait_group %0;" :: "n"(n) : "memory")

// ---------------------------------------------------------------------------
// Weight transpose: z=0,1 -> bf16 (Wq, Wk); z=2,3 -> tf32 fp32 (Wv, Wo)
// ---------------------------------------------------------------------------
__global__ void transpose4(const float* __restrict__ W0, const float* __restrict__ W1,
                           const float* __restrict__ W2, const float* __restrict__ W3,
                           __nv_bfloat16* __restrict__ WTH, float* __restrict__ WT)
{
    __shared__ float t[32][33];
    const int z = blockIdx.z;
    const float* W = (z == 0) ? W0 : (z == 1) ? W1 : (z == 2) ? W2 : W3;
    int bx = blockIdx.x * 32, by = blockIdx.y * 32;
    for (int j = threadIdx.y; j < 32; j += 8)
        t[j][threadIdx.x] = W[(size_t)(by + j) * DM + bx + threadIdx.x];
    __syncthreads();
    if (z < 2) {
        __nv_bfloat16* d = WTH + (size_t)z * DM * DM;
        for (int j = threadIdx.y; j < 32; j += 8)
            d[(size_t)(bx + j) * DM + by + threadIdx.x] =
                __float2bfloat16_rn(t[threadIdx.x][j]);
    } else {
        float* d = WT + (size_t)(z - 2) * DM * DM;
        for (int j = threadIdx.y; j < 32; j += 8)
            d[(size_t)(bx + j) * DM + by + threadIdx.x] = to_tf32(t[threadIdx.x][j]);
    }
}

// ---------------------------------------------------------------------------
// Input prep: z=0,1 -> bf16 (queries, keys); z=2 -> tf32 fp32 (values)
// ---------------------------------------------------------------------------
__global__ __launch_bounds__(256) void prep_inputs(
    const float* __restrict__ q, const float* __restrict__ k,
    const float* __restrict__ v, __nv_bfloat16* __restrict__ INH,
    float* __restrict__ IN)
{
    const int z = blockIdx.z;
    const float* src = (z == 0) ? q : (z == 1) ? k : v;
    const size_t n4 = (size_t)MROWS * DM / 4;
    if (z < 2) {
        __nv_bfloat16* d = INH + (size_t)z * MROWS * DM;
        for (size_t i = blockIdx.x * 256 + threadIdx.x; i < n4; i += (size_t)gridDim.x * 256) {
            float4 x = ((const float4*)src)[i];
            __nv_bfloat162 lo = __float22bfloat162_rn(make_float2(x.x, x.y));
            __nv_bfloat162 hi = __float22bfloat162_rn(make_float2(x.z, x.w));
            uint2 pk;
            pk.x = *(uint32_t*)&lo;
            pk.y = *(uint32_t*)&hi;
            ((uint2*)d)[i] = pk;
        }
    } else {
        for (size_t i = blockIdx.x * 256 + threadIdx.x; i < n4; i += (size_t)gridDim.x * 256) {
            float4 x = ((const float4*)src)[i];
            x.x = to_tf32(x.x); x.y = to_tf32(x.y);
            x.z = to_tf32(x.z); x.w = to_tf32(x.w);
            ((float4*)IN)[i] = x;
        }
    }
}

// ---------------------------------------------------------------------------
// TF32 mma GEMM core, 2-stage cp.async, ldmatrix fragments.
// mode: 0 = fp32 +bias; 2 = fp16 output
// ---------------------------------------------------------------------------
#define GBM 128
#define GBN 128
#define GBK 32
#define SSTRIDE 36
#define TILE_FLOATS (GBM * SSTRIDE)
#define STAGE_FLOATS (2 * TILE_FLOATS)
#define SMEM_GEMM (2 * STAGE_FLOATS * 4)

__device__ __forceinline__ void gemm_stage_issue(
    const float* __restrict__ A, const float* __restrict__ BT,
    int bm, int bn, int k0, uint32_t sA_addr, uint32_t sB_addr, int tid)
{
#pragma unroll
    for (int i = 0; i < 4; i++) {
        int idx = tid + i * 256;
        int r = idx >> 3;
        int c4 = idx & 7;
        uint32_t off = (uint32_t)(r * SSTRIDE + c4 * 4) * 4;
        cp16(sA_addr + off, &A[(size_t)(bm + r) * DM + k0 + c4 * 4]);
        cp16(sB_addr + off, &BT[(size_t)(bn + r) * DM + k0 + c4 * 4]);
    }
    CP_COMMIT();
}

__device__ __forceinline__ void gemm_core(
    const float* __restrict__ A, const float* __restrict__ BT,
    const float* __restrict__ bias, void* __restrict__ Cv,
    int mode, float* dsm)
{
    const uint32_t sbase = smem_u32(dsm);
    const int tid = threadIdx.x;
    const int wid = tid >> 5;
    const int lane = tid & 31;
    const int gID = lane >> 2;
    const int ig  = lane & 3;
    const int lm_m = lane >> 3;
    const int lm_r = lane & 7;
    const int warp_m = wid >> 2;
    const int warp_n = wid & 3;
    const int bm = blockIdx.y * GBM;
    const int bn = blockIdx.x * GBN;

    float acc[4][4][4];
#pragma unroll
    for (int i = 0; i < 4; i++)
#pragma unroll
        for (int j = 0; j < 4; j++)
#pragma unroll
            for (int v = 0; v < 4; v++) acc[i][j][v] = 0.0f;

    const int kSteps = DM / GBK;

    gemm_stage_issue(A, BT, bm, bn, 0, sbase, sbase + TILE_FLOATS * 4, tid);

    const uint32_t a_row = (uint32_t)(warp_m * 64 + (lm_m & 1) * 8 + lm_r);
    const uint32_t a_col = (uint32_t)((lm_m >> 1) * 4);
    const uint32_t b_row = (uint32_t)(warp_n * 32 + (lm_m >> 1) * 8 + lm_r);
    const uint32_t b_col = (uint32_t)((lm_m & 1) * 4);

    for (int kt = 0; kt < kSteps; kt++) {
        const int cur = kt & 1;
        if (kt + 1 < kSteps) {
            const int nxt = (kt + 1) & 1;
            gemm_stage_issue(A, BT, bm, bn, (kt + 1) * GBK,
                             sbase + nxt * STAGE_FLOATS * 4,
                             sbase + (nxt * STAGE_FLOATS + TILE_FLOATS) * 4, tid);
            CP_WAIT(1);
        } else {
            CP_WAIT(0);
        }
        __syncthreads();

        const uint32_t sAa = sbase + (uint32_t)(cur * STAGE_FLOATS * 4);
        const uint32_t sBa = sAa + TILE_FLOATS * 4;

#pragma unroll
        for (int kk = 0; kk < GBK; kk += 8) {
            uint32_t afrag[4][4];
#pragma unroll
            for (int mt = 0; mt < 4; mt++) {
                uint32_t addr = sAa + (uint32_t)(
                    ((a_row + mt * 16) * SSTRIDE + kk + a_col) * 4);
                ldsm_x4(afrag[mt][0], afrag[mt][1], afrag[mt][2], afrag[mt][3], addr);
            }
            uint32_t bfrag[4][2];
#pragma unroll
            for (int p = 0; p < 2; p++) {
                uint32_t addr = sBa + (uint32_t)(
                    ((b_row + p * 16) * SSTRIDE + kk + b_col) * 4);
                ldsm_x4(bfrag[2*p][0], bfrag[2*p][1],
                        bfrag[2*p+1][0], bfrag[2*p+1][1], addr);
            }
#pragma unroll
            for (int mt = 0; mt < 4; mt++)
#pragma unroll
                for (int nt = 0; nt < 4; nt++)
                    mma_tf32(acc[mt][nt], afrag[mt], bfrag[nt]);
        }
        __syncthreads();
    }

#pragma unroll
    for (int mt = 0; mt < 4; mt++) {
#pragma unroll
        for (int nt = 0; nt < 4; nt++) {
            int row = bm + warp_m * 64 + mt * 16 + gID;
            int col = bn + warp_n * 32 + nt * 8 + ig * 2;
            float2 v0, v1;
            v0.x = acc[mt][nt][0]; v0.y = acc[mt][nt][1];
            v1.x = acc[mt][nt][2]; v1.y = acc[mt][nt][3];
            if (mode == 0) {
                if (bias) {
                    float b0 = bias[col], b1 = bias[col + 1];
                    v0.x += b0; v0.y += b1;
                    v1.x += b0; v1.y += b1;
                }
                float* C = (float*)Cv;
                *(float2*)&C[(size_t)row * DM + col] = v0;
                *(float2*)&C[(size_t)(row + 8) * DM + col] = v1;
            } else {
                __half* C = (__half*)Cv;
                *(__half2*)&C[(size_t)row * DM + col] = __floats2half2_rn(v0.x, v0.y);
                *(__half2*)&C[(size_t)(row + 8) * DM + col] = __floats2half2_rn(v1.x, v1.y);
            }
        }
    }
}

__global__ __launch_bounds__(256, 2) void gemm_v(
    const float* __restrict__ A, const float* __restrict__ BT,
    __half* __restrict__ C)
{
    extern __shared__ float dsm[];
    gemm_core(A, BT, nullptr, C, 2, dsm);
}

__global__ __launch_bounds__(256, 2) void gemm_out(
    const float* __restrict__ A, const float* __restrict__ BT,
    const float* __restrict__ bias, float* __restrict__ C)
{
    extern __shared__ float dsm[];
    gemm_core(A, BT, bias, C, 0, dsm);
}

// ---------------------------------------------------------------------------
// BF16 mma GEMM (Q and K projections): unchanged from R12.
// ---------------------------------------------------------------------------
#define HST 28
#define HTILE_U32 (GBM * HST)
#define HSTAGE_U32 (2 * HTILE_U32)
#define SMEM_GEMMH (2 * HSTAGE_U32 * 4)

__device__ __forceinline__ void gemmh_stage_issue(
    const __nv_bfloat16* __restrict__ A, const __nv_bfloat16* __restrict__ BT,
    int bm, int bn, int k0, uint32_t sA_addr, uint32_t sB_addr, int tid)
{
#pragma unroll
    for (int i = 0; i < 2; i++) {
        int idx = tid + i * 256;
        int r = idx >> 2;
        int c = idx & 3;
        uint32_t off = (uint32_t)(r * HST * 4 + c * 16);
        cp16(sA_addr + off, A + (size_t)(bm + r) * DM + k0 + c * 8);
        cp16(sB_addr + off, BT + (size_t)(bn + r) * DM + k0 + c * 8);
    }
    CP_COMMIT();
}

__global__ __launch_bounds__(256, 2) void gemm_bf16qk(
    const __nv_bfloat16* __restrict__ INH, const __nv_bfloat16* __restrict__ WTH,
    __nv_bfloat16* __restrict__ Qo, __nv_bfloat16* __restrict__ Ko)
{
    extern __shared__ uint32_t hsm[];
    const int z = blockIdx.z;
    const __nv_bfloat16* A  = INH + (size_t)z * MROWS * DM;
    const __nv_bfloat16* BT = WTH + (size_t)z * DM * DM;
    __nv_bfloat16* C = z ? Ko : Qo;

    const uint32_t sbase = smem_u32(hsm);
    const int tid = threadIdx.x;
    const int wid = tid >> 5;
    const int lane = tid & 31;
    const int gID = lane >> 2;
    const int ig  = lane & 3;
    const int lm_m = lane >> 3;
    const int lm_r = lane & 7;
    const int warp_m = wid >> 2;
    const int warp_n = wid & 3;
    const int bm = blockIdx.y * GBM;
    const int bn = blockIdx.x * GBN;

    float acc[4][4][4];
#pragma unroll
    for (int i = 0; i < 4; i++)
#pragma unroll
        for (int j = 0; j < 4; j++)
#pragma unroll
            for (int v = 0; v < 4; v++) acc[i][j][v] = 0.0f;

    const int kSteps = DM / GBK;

    gemmh_stage_issue(A, BT, bm, bn, 0, sbase, sbase + HTILE_U32 * 4, tid);

    for (int kt = 0; kt < kSteps; kt++) {
        const int cur = kt & 1;
        if (kt + 1 < kSteps) {
            const int nxt = (kt + 1) & 1;
            gemmh_stage_issue(A, BT, bm, bn, (kt + 1) * GBK,
                              sbase + nxt * HSTAGE_U32 * 4,
                              sbase + (nxt * HSTAGE_U32 + HTILE_U32) * 4, tid);
            CP_WAIT(1);
        } else {
            CP_WAIT(0);
        }
        __syncthreads();

        const uint32_t sAa = sbase + (uint32_t)(cur * HSTAGE_U32 * 4);
        const uint32_t sBa = sAa + HTILE_U32 * 4;

#pragma unroll
        for (int st = 0; st < 2; st++) {
            uint32_t afrag[4][4];
#pragma unroll
            for (int mt = 0; mt < 4; mt++) {
                uint32_t addr = sAa + (uint32_t)(
                    ((warp_m * 64 + mt * 16 + (lm_m & 1) * 8 + lm_r) * HST
                     + st * 8 + (lm_m >> 1) * 4) * 4);
                ldsm_x4(afrag[mt][0], afrag[mt][1], afrag[mt][2], afrag[mt][3], addr);
            }
            uint32_t bfrag[4][2];
#pragma unroll
            for (int p = 0; p < 2; p++) {
                uint32_t addr = sBa + (uint32_t)(
                    ((warp_n * 32 + p * 16 + (lm_m >> 1) * 8 + lm_r) * HST
                     + st * 8 + (lm_m & 1) * 4) * 4);
                ldsm_x4(bfrag[2*p][0], bfrag[2*p][1],
                        bfrag[2*p+1][0], bfrag[2*p+1][1], addr);
            }
#pragma unroll
            for (int mt = 0; mt < 4; mt++)
#pragma unroll
                for (int nt = 0; nt < 4; nt++)
                    mma_bf16(acc[mt][nt], afrag[mt], bfrag[nt]);
        }
        __syncthreads();
    }

    const float esc = z ? 1.0f : QSCALE;
#pragma unroll
    for (int mt = 0; mt < 4; mt++) {
#pragma unroll
        for (int nt = 0; nt < 4; nt++) {
            int row = bm + warp_m * 64 + mt * 16 + gID;
            int col = bn + warp_n * 32 + nt * 8 + ig * 2;
            float2 v0, v1;
            v0.x = acc[mt][nt][0] * esc; v0.y = acc[mt][nt][1] * esc;
            v1.x = acc[mt][nt][2] * esc; v1.y = acc[mt][nt][3] * esc;
            *(__nv_bfloat162*)&C[(size_t)row * DM + col] = __float22bfloat162_rn(v0);
            *(__nv_bfloat162*)&C[(size_t)(row + 8) * DM + col] = __float22bfloat162_rn(v1);
        }
    }
}

// ---------------------------------------------------------------------------
// Flash attention: bf16 QK + fp16 PV, all fragments via ldmatrix.
// CTA = 128 q-rows, 8 warps; Q in regs; K(bf16)/V(fp16) double-buffered cp.async.
// ---------------------------------------------------------------------------
#define QROWS 128
#define PSTH 72     // P stride (fp16)
#define KST 72      // K stride (bf16)
#define VSTH 72     // V stride (fp16)
#define KTILE 64
#define SP_H (QROWS * PSTH)
#define SK_H (KTILE * KST)
#define SV_H (KTILE * VSTH)
#define SMEM_ATT ((SP_H + 2 * SK_H + 2 * SV_H) * 2)

__device__ __forceinline__ void attn_stage_issue(
    const __nv_bfloat16* __restrict__ Kh, const __half* __restrict__ Vp,
    int b, int h, int kt, uint32_t sK_addr, uint32_t sV_addr, int tid)
{
    const __nv_bfloat16* Kbase = Kh + ((size_t)b * NK + kt * KTILE) * DM + h * HD;
    const __half* Vbase = Vp + ((size_t)b * NK + kt * KTILE) * DM + h * HD;
#pragma unroll
    for (int i = 0; i < 2; i++) {
        int idx = tid + i * 256;
        int r = idx >> 3;       // 0..63
        int c16 = idx & 7;      // 0..7
        cp16(sK_addr + (uint32_t)(r * KST * 2 + c16 * 16),
             Kbase + (size_t)r * DM + c16 * 8);
        cp16(sV_addr + (uint32_t)(r * VSTH * 2 + c16 * 16),
             Vbase + (size_t)r * DM + c16 * 8);
    }
    CP_COMMIT();
}

__global__ __launch_bounds__(256, 2) void attn_mma(
    const __nv_bfloat16* __restrict__ Qh, const __nv_bfloat16* __restrict__ Kh,
    const __half* __restrict__ Vp, float* __restrict__ Op)
{
    extern __shared__ __half smh[];
    __half* sP = smh;                                // [128][PSTH]
    __half* sV = sP + SP_H;                          // 2 x [64][VSTH]
    __nv_bfloat16* sKh = (__nv_bfloat16*)(sV + 2 * SV_H);  // 2 x [64][KST]
    const uint32_t sPa = smem_u32(sP);
    const uint32_t sVa = smem_u32(sV);
    const uint32_t sKa = smem_u32(sKh);

    const int tid = threadIdx.x;
    const int wid = tid >> 5;
    const int lane = tid & 31;
    const int gID = lane >> 2;
    const int ig  = lane & 3;
    const int lm_m = lane >> 3;
    const int lm_r = lane & 7;
    const int qt = blockIdx.x;
    const int h  = blockIdx.y;
    const int b  = blockIdx.z;

    const int r0 = wid * 16 + gID;

    attn_stage_issue(Kh, Vp, b, h, 0, sKa, sVa, tid);

    uint32_t qf[4][4];
    {
        const __nv_bfloat16* Qb =
            Qh + ((size_t)b * NQ + qt * QROWS + r0) * DM + h * HD;
#pragma unroll
        for (int st = 0; st < 4; st++) {
            int kk0 = st * 16;
            qf[st][0] = *(const uint32_t*)&Qb[kk0 + 2 * ig];
            qf[st][1] = *(const uint32_t*)&Qb[8 * DM + kk0 + 2 * ig];
            qf[st][2] = *(const uint32_t*)&Qb[kk0 + 8 + 2 * ig];
            qf[st][3] = *(const uint32_t*)&Qb[8 * DM + kk0 + 8 + 2 * ig];
        }
    }

    // K ldmatrix (non-trans, 2 n-tiles per x4)
    const uint32_t k_rowoff = (uint32_t)((lm_m >> 1) * 8 + lm_r);
    const uint32_t k_coloff = (uint32_t)((lm_m & 1) * 8);
    // P ldmatrix (non-trans A-frag, fp16)
    const uint32_t p_row = (uint32_t)(wid * 16 + (lm_m & 1) * 8 + lm_r);
    const uint32_t p_col = (uint32_t)((lm_m >> 1) * 8);
    // V ldmatrix.trans (B-frags, 2 n-tiles per x4)
    const uint32_t v_rowoff = (uint32_t)((lm_m & 1) * 8 + lm_r);   // k within step
    const uint32_t v_coloff = (uint32_t)((lm_m >> 1) * 8);         // n within pair

    float m0 = -1e30f, m1 = -1e30f, l0 = 0.0f, l1 = 0.0f;
    float oacc[8][4];
#pragma unroll
    for (int nt = 0; nt < 8; nt++)
#pragma unroll
        for (int v = 0; v < 4; v++) oacc[nt][v] = 0.0f;

    const int nTiles = NK / KTILE;
    for (int kt = 0; kt < nTiles; kt++) {
        const int cur = kt & 1;
        CP_WAIT(0);
        __syncthreads();
        if (kt + 1 < nTiles) {
            const int nxt = (kt + 1) & 1;
            attn_stage_issue(Kh, Vp, b, h, kt + 1,
                             sKa + nxt * SK_H * 2, sVa + nxt * SV_H * 2, tid);
        }
        const uint32_t cKa = sKa + (uint32_t)(cur * SK_H * 2);
        const uint32_t cVa = sVa + (uint32_t)(cur * SV_H * 2);

        // ---- S = Q @ K^T (bf16) ----
        float s[8][4];
#pragma unroll
        for (int nt = 0; nt < 8; nt++)
#pragma unroll
            for (int v = 0; v < 4; v++) s[nt][v] = 0.0f;

#pragma unroll
        for (int st = 0; st < 4; st++) {
#pragma unroll
            for (int p = 0; p < 4; p++) {
                uint32_t addr = cKa + (uint32_t)(
                    ((p * 16 + k_rowoff) * KST + st * 16 + k_coloff) * 2);
                uint32_t b0, b1, b2, b3;
                ldsm_x4(b0, b1, b2, b3, addr);
                uint32_t bb0[2] = {b0, b1};
                uint32_t bb1[2] = {b2, b3};
                mma_bf16(s[2*p],     qf[st], bb0);
                mma_bf16(s[2*p + 1], qf[st], bb1);
            }
        }

        // ---- Online softmax ----
        float mt0 = -1e30f, mt1 = -1e30f;
#pragma unroll
        for (int nt = 0; nt < 8; nt++) {
            mt0 = fmaxf(mt0, fmaxf(s[nt][0], s[nt][1]));
            mt1 = fmaxf(mt1, fmaxf(s[nt][2], s[nt][3]));
        }
        mt0 = fmaxf(mt0, __shfl_xor_sync(0xffffffffu, mt0, 1));
        mt0 = fmaxf(mt0, __shfl_xor_sync(0xffffffffu, mt0, 2));
        mt1 = fmaxf(mt1, __shfl_xor_sync(0xffffffffu, mt1, 1));
        mt1 = fmaxf(mt1, __shfl_xor_sync(0xffffffffu, mt1, 2));

        float mn0 = fmaxf(m0, mt0), mn1 = fmaxf(m1, mt1);
        float a0 = ex2(m0 - mn0), a1 = ex2(m1 - mn1);
        m0 = mn0; m1 = mn1;

        float rs0 = 0.0f, rs1 = 0.0f;
#pragma unroll
        for (int nt = 0; nt < 8; nt++) {
            float p00 = ex2(s[nt][0] - mn0);
            float p01 = ex2(s[nt][1] - mn0);
            float p10 = ex2(s[nt][2] - mn1);
            float p11 = ex2(s[nt][3] - mn1);
            rs0 += p00 + p01;
            rs1 += p10 + p11;
            int c = nt * 8 + ig * 2;
            *(__half2*)&sP[r0 * PSTH + c] = __floats2half2_rn(p00, p01);
            *(__half2*)&sP[(r0 + 8) * PSTH + c] = __floats2half2_rn(p10, p11);
        }
        rs0 += __shfl_xor_sync(0xffffffffu, rs0, 1);
        rs0 += __shfl_xor_sync(0xffffffffu, rs0, 2);
        rs1 += __shfl_xor_sync(0xffffffffu, rs1, 1);
        rs1 += __shfl_xor_sync(0xffffffffu, rs1, 2);
        l0 = l0 * a0 + rs0;
        l1 = l1 * a1 + rs1;

#pragma unroll
        for (int nt = 0; nt < 8; nt++) {
            oacc[nt][0] *= a0; oacc[nt][1] *= a0;
            oacc[nt][2] *= a1; oacc[nt][3] *= a1;
        }
        __syncwarp();   // warp-private sP slab

        // ---- oacc += P @ V (fp16 m16n8k16; P ldmatrix, V ldmatrix.trans) ----
#pragma unroll
        for (int st = 0; st < 4; st++) {
            const int k0 = st * 16;
            uint32_t af[4];
            {
                uint32_t addr = sPa + (uint32_t)((p_row * PSTH + k0 + p_col) * 2);
                ldsm_x4(af[0], af[1], af[2], af[3], addr);
            }
#pragma unroll
            for (int p = 0; p < 4; p++) {   // n-pairs: d cols [16p, 16p+16)
                uint32_t addr = cVa + (uint32_t)(
                    ((k0 + v_rowoff) * VSTH + p * 16 + v_coloff) * 2);
                uint32_t b0, b1, b2, b3;
                ldsm_x4_trans(b0, b1, b2, b3, addr);
                uint32_t bb0[2] = {b0, b1};
                uint32_t bb1[2] = {b2, b3};
                mma_f16(oacc[2*p],     af, bb0);
                mma_f16(oacc[2*p + 1], af, bb1);
            }
        }
    }

    // ---- Epilogue ----
    float inv0 = 1.0f / l0, inv1 = 1.0f / l1;
    const int grow = qt * QROWS + r0;
#pragma unroll
    for (int nt = 0; nt < 8; nt++) {
        int col = h * HD + nt * 8 + ig * 2;
        float2 o0;
        o0.x = to_tf32(oacc[nt][0] * inv0);
        o0.y = to_tf32(oacc[nt][1] * inv0);
        *(float2*)&Op[((size_t)b * NQ + grow) * DM + col] = o0;
        float2 o1;
        o1.x = to_tf32(oacc[nt][2] * inv1);
        o1.y = to_tf32(oacc[nt][3] * inv1);
        *(float2*)&Op[((size_t)b * NQ + grow + 8) * DM + col] = o1;
    }
}

// ---------------------------------------------------------------------------
// Launch
// ---------------------------------------------------------------------------
extern "C" void kernel_launch(void* const* d_in, const int* in_sizes, int n_in,
                              void* d_out, int out_size)
{
    const float* queries = (const float*)d_in[0];
    const float* keys    = (const float*)d_in[1];
    const float* values  = (const float*)d_in[2];
    const float* Wq      = (const float*)d_in[3];
    const float* Wk      = (const float*)d_in[4];
    const float* Wv      = (const float*)d_in[5];
    const float* Wo      = (const float*)d_in[6];
    const float* bo      = (const float*)d_in[7];
    float* out           = (float*)d_out;

    __nv_bfloat16 *Qh, *Kh, *WTH, *INH;
    __half *Vh;
    float *Op, *WT, *IN;
    cudaGetSymbolAddress((void**)&Qh, g_Qh);
    cudaGetSymbolAddress((void**)&Kh, g_Kh);
    cudaGetSymbolAddress((void**)&Vh, g_Vh);
    cudaGetSymbolAddress((void**)&Op, g_O);
    cudaGetSymbolAddress((void**)&WTH, g_WTH);
    cudaGetSymbolAddress((void**)&WT, g_WT);
    cudaGetSymbolAddress((void**)&INH, g_INH);
    cudaGetSymbolAddress((void**)&IN, g_IN);

    static bool attr_set = false;
    if (!attr_set) {
        cudaFuncSetAttribute(attn_mma,
                             cudaFuncAttributeMaxDynamicSharedMemorySize, SMEM_ATT);
        cudaFuncSetAttribute(gemm_bf16qk,
                             cudaFuncAttributeMaxDynamicSharedMemorySize, SMEM_GEMMH);
        cudaFuncSetAttribute(gemm_v,
                             cudaFuncAttributeMaxDynamicSharedMemorySize, SMEM_GEMM);
        cudaFuncSetAttribute(gemm_out,
                             cudaFuncAttributeMaxDynamicSharedMemorySize, SMEM_GEMM);
        attr_set = true;
    }

    dim3 tgrid(DM / 32, DM / 32, 4), tblk(32, 8);
    transpose4<<<tgrid, tblk>>>(Wq, Wk, Wv, Wo, WTH, WT);

    dim3 pgrid(1024, 1, 3);
    prep_inputs<<<pgrid, 256>>>(queries, keys, values, INH, IN);

    dim3 hgrid(DM / GBN, MROWS / GBM, 2);
    gemm_bf16qk<<<hgrid, 256, SMEM_GEMMH>>>(INH, WTH, Qh, Kh);

    dim3 vgrid(DM / GBN, MROWS / GBM);
    gemm_v<<<vgrid, 256, SMEM_GEMM>>>(IN, WT, Vh);

    dim3 agrid(NQ / QROWS, NH, BATCH);
    attn_mma<<<agrid, 256, SMEM_ATT>>>(Qh, Kh, Vh, Op);

    dim3 ogrid(DM / GBN, MROWS / GBM);
    gemm_out<<<ogrid, 256, SMEM_GEMM>>>(Op, WT + (size_t)DM * DM, bo, out);
}

// round 14
// speedup vs baseline: 7.2858x; 1.1543x over previous
#include <cuda_runtime.h>
#include <cuda_fp16.h>
#include <math.h>
#include <stdint.h>

#define BATCH 4
#define NQ 2048
#define NK 2048
#define DM 1024
#define NH 16
#define HD 64
#define MROWS (BATCH * NQ)   // 8192

// Scratch (all 16-bit now)
__device__ __half g_Qh[MROWS * DM];          // Q proj, fp16, pre-scaled
__device__ __half g_Kh[MROWS * DM];          // K proj, fp16
__device__ __half g_Vh[MROWS * DM];          // V proj, fp16
__device__ __half g_Oh[MROWS * DM];          // attention out, fp16
__device__ __half g_WTH[4 * DM * DM];        // Wq^T..Wo^T fp16
__device__ __half g_INH[3 * MROWS * DM];     // fp16 queries, keys, values

#define QSCALE (0.03125f * 1.4426950408889634f)   // 1/sqrt(1024) * log2(e)

__device__ __forceinline__ float ex2(float x) {
    float r;
    asm("ex2.approx.ftz.f32 %0, %1;" : "=f"(r) : "f"(x));
    return r;
}

__device__ __forceinline__ void mma_f16(float* c, const uint32_t* a, const uint32_t* b) {
    asm volatile(
        "mma.sync.aligned.m16n8k16.row.col.f32.f16.f16.f32 "
        "{%0,%1,%2,%3}, {%4,%5,%6,%7}, {%8,%9}, {%0,%1,%2,%3};"
        : "+f"(c[0]), "+f"(c[1]), "+f"(c[2]), "+f"(c[3])
        : "r"(a[0]), "r"(a[1]), "r"(a[2]), "r"(a[3]), "r"(b[0]), "r"(b[1]));
}

__device__ __forceinline__ void ldsm_x4(uint32_t& r0, uint32_t& r1,
                                        uint32_t& r2, uint32_t& r3, uint32_t addr) {
    asm volatile("ldmatrix.sync.aligned.m8n8.x4.shared.b16 {%0,%1,%2,%3}, [%4];"
        : "=r"(r0), "=r"(r1), "=r"(r2), "=r"(r3) : "r"(addr));
}

__device__ __forceinline__ void ldsm_x4_trans(uint32_t& r0, uint32_t& r1,
                                              uint32_t& r2, uint32_t& r3, uint32_t addr) {
    asm volatile("ldmatrix.sync.aligned.m8n8.x4.trans.shared.b16 {%0,%1,%2,%3}, [%4];"
        : "=r"(r0), "=r"(r1), "=r"(r2), "=r"(r3) : "r"(addr));
}

__device__ __forceinline__ uint32_t smem_u32(const void* p) {
    uint32_t a;
    asm("{ .reg .u64 t; cvta.to.shared.u64 t, %1; cvt.u32.u64 %0, t; }"
        : "=r"(a) : "l"(p));
    return a;
}

__device__ __forceinline__ void cp16(uint32_t dst, const void* src) {
    asm volatile("cp.async.ca.shared.global [%0], [%1], 16;" :: "r"(dst), "l"(src));
}
#define CP_COMMIT() asm volatile("cp.async.commit_group;" ::: "memory")
#define CP_WAIT(n)  asm volatile("cp.async.wait_group %0;" :: "n"(n) : "memory")

// ---------------------------------------------------------------------------
// Weight transpose: all 4 weights -> fp16 transposed [N][K]
// ---------------------------------------------------------------------------
__global__ void transpose4(const float* __restrict__ W0, const float* __restrict__ W1,
                           const float* __restrict__ W2, const float* __restrict__ W3,
                           __half* __restrict__ WTH)
{
    __shared__ float t[32][33];
    const int z = blockIdx.z;
    const float* W = (z == 0) ? W0 : (z == 1) ? W1 : (z == 2) ? W2 : W3;
    __half* d = WTH + (size_t)z * DM * DM;
    int bx = blockIdx.x * 32, by = blockIdx.y * 32;
    for (int j = threadIdx.y; j < 32; j += 8)
        t[j][threadIdx.x] = W[(size_t)(by + j) * DM + bx + threadIdx.x];
    __syncthreads();
    for (int j = threadIdx.y; j < 32; j += 8)
        d[(size_t)(bx + j) * DM + by + threadIdx.x] = __float2half_rn(t[threadIdx.x][j]);
}

// ---------------------------------------------------------------------------
// Input prep: all 3 activations -> fp16
// ---------------------------------------------------------------------------
__global__ __launch_bounds__(256) void prep_inputs(
    const float* __restrict__ q, const float* __restrict__ k,
    const float* __restrict__ v, __half* __restrict__ INH)
{
    const int z = blockIdx.z;
    const float* src = (z == 0) ? q : (z == 1) ? k : v;
    __half* d = INH + (size_t)z * MROWS * DM;
    const size_t n4 = (size_t)MROWS * DM / 4;
    for (size_t i = blockIdx.x * 256 + threadIdx.x; i < n4; i += (size_t)gridDim.x * 256) {
        float4 x = ((const float4*)src)[i];
        __half2 lo = __floats2half2_rn(x.x, x.y);
        __half2 hi = __floats2half2_rn(x.z, x.w);
        uint2 pk;
        pk.x = *(uint32_t*)&lo;
        pk.y = *(uint32_t*)&hi;
        ((uint2*)d)[i] = pk;
    }
}

// ---------------------------------------------------------------------------
// FP16 mma GEMM: m16n8k16, tile 128x128, BK=32 fp16, 2-stage cp.async,
// ldmatrix fragments. Epilogue mode: 0 = fp16; 1 = fp16 * QSCALE;
// 2 = fp32 + bias.
// ---------------------------------------------------------------------------
#define GBM 128
#define GBN 128
#define GBK 32
#define HST 28                       // uint32 per smem row (112 B)
#define HTILE_U32 (GBM * HST)
#define HSTAGE_U32 (2 * HTILE_U32)
#define SMEM_GEMMH (2 * HSTAGE_U32 * 4)   // 57344 B

__device__ __forceinline__ void gemmh_stage_issue(
    const __half* __restrict__ A, const __half* __restrict__ BT,
    int bm, int bn, int k0, uint32_t sA_addr, uint32_t sB_addr, int tid)
{
#pragma unroll
    for (int i = 0; i < 2; i++) {
        int idx = tid + i * 256;
        int r = idx >> 2;
        int c = idx & 3;
        uint32_t off = (uint32_t)(r * HST * 4 + c * 16);
        cp16(sA_addr + off, A + (size_t)(bm + r) * DM + k0 + c * 8);
        cp16(sB_addr + off, BT + (size_t)(bn + r) * DM + k0 + c * 8);
    }
    CP_COMMIT();
}

__device__ __forceinline__ void gemm16_core(
    const __half* __restrict__ A, const __half* __restrict__ BT,
    const float* __restrict__ bias, void* __restrict__ Cv,
    int mode, uint32_t* hsm)
{
    const uint32_t sbase = smem_u32(hsm);
    const int tid = threadIdx.x;
    const int wid = tid >> 5;
    const int lane = tid & 31;
    const int gID = lane >> 2;
    const int ig  = lane & 3;
    const int lm_m = lane >> 3;
    const int lm_r = lane & 7;
    const int warp_m = wid >> 2;
    const int warp_n = wid & 3;
    const int bm = blockIdx.y * GBM;
    const int bn = blockIdx.x * GBN;

    float acc[4][4][4];
#pragma unroll
    for (int i = 0; i < 4; i++)
#pragma unroll
        for (int j = 0; j < 4; j++)
#pragma unroll
            for (int v = 0; v < 4; v++) acc[i][j][v] = 0.0f;

    const int kSteps = DM / GBK;   // 32

    gemmh_stage_issue(A, BT, bm, bn, 0, sbase, sbase + HTILE_U32 * 4, tid);

    for (int kt = 0; kt < kSteps; kt++) {
        const int cur = kt & 1;
        if (kt + 1 < kSteps) {
            const int nxt = (kt + 1) & 1;
            gemmh_stage_issue(A, BT, bm, bn, (kt + 1) * GBK,
                              sbase + nxt * HSTAGE_U32 * 4,
                              sbase + (nxt * HSTAGE_U32 + HTILE_U32) * 4, tid);
            CP_WAIT(1);
        } else {
            CP_WAIT(0);
        }
        __syncthreads();

        const uint32_t sAa = sbase + (uint32_t)(cur * HSTAGE_U32 * 4);
        const uint32_t sBa = sAa + HTILE_U32 * 4;

#pragma unroll
        for (int st = 0; st < 2; st++) {
            uint32_t afrag[4][4];
#pragma unroll
            for (int mt = 0; mt < 4; mt++) {
                uint32_t addr = sAa + (uint32_t)(
                    ((warp_m * 64 + mt * 16 + (lm_m & 1) * 8 + lm_r) * HST
                     + st * 8 + (lm_m >> 1) * 4) * 4);
                ldsm_x4(afrag[mt][0], afrag[mt][1], afrag[mt][2], afrag[mt][3], addr);
            }
            uint32_t bfrag[4][2];
#pragma unroll
            for (int p = 0; p < 2; p++) {
                uint32_t addr = sBa + (uint32_t)(
                    ((warp_n * 32 + p * 16 + (lm_m >> 1) * 8 + lm_r) * HST
                     + st * 8 + (lm_m & 1) * 4) * 4);
                ldsm_x4(bfrag[2*p][0], bfrag[2*p][1],
                        bfrag[2*p+1][0], bfrag[2*p+1][1], addr);
            }
#pragma unroll
            for (int mt = 0; mt < 4; mt++)
#pragma unroll
                for (int nt = 0; nt < 4; nt++)
                    mma_f16(acc[mt][nt], afrag[mt], bfrag[nt]);
        }
        __syncthreads();
    }

#pragma unroll
    for (int mt = 0; mt < 4; mt++) {
#pragma unroll
        for (int nt = 0; nt < 4; nt++) {
            int row = bm + warp_m * 64 + mt * 16 + gID;
            int col = bn + warp_n * 32 + nt * 8 + ig * 2;
            float2 v0, v1;
            v0.x = acc[mt][nt][0]; v0.y = acc[mt][nt][1];
            v1.x = acc[mt][nt][2]; v1.y = acc[mt][nt][3];
            if (mode == 2) {
                float b0 = bias[col], b1 = bias[col + 1];
                v0.x += b0; v0.y += b1;
                v1.x += b0; v1.y += b1;
                float* C = (float*)Cv;
                *(float2*)&C[(size_t)row * DM + col] = v0;
                *(float2*)&C[(size_t)(row + 8) * DM + col] = v1;
            } else {
                if (mode == 1) {
                    v0.x *= QSCALE; v0.y *= QSCALE;
                    v1.x *= QSCALE; v1.y *= QSCALE;
                }
                __half* C = (__half*)Cv;
                *(__half2*)&C[(size_t)row * DM + col] = __floats2half2_rn(v0.x, v0.y);
                *(__half2*)&C[(size_t)(row + 8) * DM + col] = __floats2half2_rn(v1.x, v1.y);
            }
        }
    }
}

// Q/K/V projections fused (z selects); all fp16 in/out.
__global__ __launch_bounds__(256, 2) void gemm_qkv(
    const __half* __restrict__ INH, const __half* __restrict__ WTH,
    __half* __restrict__ Qo, __half* __restrict__ Ko, __half* __restrict__ Vo)
{
    extern __shared__ uint32_t hsm[];
    const int z = blockIdx.z;
    const __half* A  = INH + (size_t)z * MROWS * DM;
    const __half* BT = WTH + (size_t)z * DM * DM;
    if (z == 0)      gemm16_core(A, BT, nullptr, Qo, 1, hsm);
    else if (z == 1) gemm16_core(A, BT, nullptr, Ko, 0, hsm);
    else             gemm16_core(A, BT, nullptr, Vo, 0, hsm);
}

// Output projection: fp16 A/B, fp32 out + bias.
__global__ __launch_bounds__(256, 2) void gemm_out16(
    const __half* __restrict__ A, const __half* __restrict__ BT,
    const float* __restrict__ bias, float* __restrict__ C)
{
    extern __shared__ uint32_t hsm[];
    gemm16_core(A, BT, bias, C, 2, hsm);
}

// ---------------------------------------------------------------------------
// Flash attention: all-fp16 operands (QK and PV both m16n8k16), fp32 softmax.
// CTA = 128 q-rows, 8 warps; Q in regs; K/V double-buffered cp.async.
// ---------------------------------------------------------------------------
#define QROWS 128
#define PSTH 72
#define KSTH 72
#define VSTH 72
#define KTILE 64
#define SP_H (QROWS * PSTH)
#define SK_H (KTILE * KSTH)
#define SV_H (KTILE * VSTH)
#define SMEM_ATT ((SP_H + 2 * SK_H + 2 * SV_H) * 2)

__device__ __forceinline__ void attn_stage_issue(
    const __half* __restrict__ Kh, const __half* __restrict__ Vp,
    int b, int h, int kt, uint32_t sK_addr, uint32_t sV_addr, int tid)
{
    const __half* Kbase = Kh + ((size_t)b * NK + kt * KTILE) * DM + h * HD;
    const __half* Vbase = Vp + ((size_t)b * NK + kt * KTILE) * DM + h * HD;
#pragma unroll
    for (int i = 0; i < 2; i++) {
        int idx = tid + i * 256;
        int r = idx >> 3;
        int c16 = idx & 7;
        cp16(sK_addr + (uint32_t)(r * KSTH * 2 + c16 * 16),
             Kbase + (size_t)r * DM + c16 * 8);
        cp16(sV_addr + (uint32_t)(r * VSTH * 2 + c16 * 16),
             Vbase + (size_t)r * DM + c16 * 8);
    }
    CP_COMMIT();
}

__global__ __launch_bounds__(256, 2) void attn_mma(
    const __half* __restrict__ Qh, const __half* __restrict__ Kh,
    const __half* __restrict__ Vp, __half* __restrict__ Oh)
{
    extern __shared__ __half smh[];
    __half* sP = smh;                    // [128][PSTH]
    __half* sV = sP + SP_H;              // 2 x [64][VSTH]
    __half* sK = sV + 2 * SV_H;          // 2 x [64][KSTH]
    const uint32_t sPa = smem_u32(sP);
    const uint32_t sVa = smem_u32(sV);
    const uint32_t sKa = smem_u32(sK);

    const int tid = threadIdx.x;
    const int wid = tid >> 5;
    const int lane = tid & 31;
    const int gID = lane >> 2;
    const int ig  = lane & 3;
    const int lm_m = lane >> 3;
    const int lm_r = lane & 7;
    const int qt = blockIdx.x;
    const int h  = blockIdx.y;
    const int b  = blockIdx.z;

    const int r0 = wid * 16 + gID;

    attn_stage_issue(Kh, Vp, b, h, 0, sKa, sVa, tid);

    uint32_t qf[4][4];
    {
        const __half* Qb = Qh + ((size_t)b * NQ + qt * QROWS + r0) * DM + h * HD;
#pragma unroll
        for (int st = 0; st < 4; st++) {
            int kk0 = st * 16;
            qf[st][0] = *(const uint32_t*)&Qb[kk0 + 2 * ig];
            qf[st][1] = *(const uint32_t*)&Qb[8 * DM + kk0 + 2 * ig];
            qf[st][2] = *(const uint32_t*)&Qb[kk0 + 8 + 2 * ig];
            qf[st][3] = *(const uint32_t*)&Qb[8 * DM + kk0 + 8 + 2 * ig];
        }
    }

    const uint32_t k_rowoff = (uint32_t)((lm_m >> 1) * 8 + lm_r);
    const uint32_t k_coloff = (uint32_t)((lm_m & 1) * 8);
    const uint32_t p_row = (uint32_t)(wid * 16 + (lm_m & 1) * 8 + lm_r);
    const uint32_t p_col = (uint32_t)((lm_m >> 1) * 8);
    const uint32_t v_rowoff = (uint32_t)((lm_m & 1) * 8 + lm_r);
    const uint32_t v_coloff = (uint32_t)((lm_m >> 1) * 8);

    float m0 = -1e30f, m1 = -1e30f, l0 = 0.0f, l1 = 0.0f;
    float oacc[8][4];
#pragma unroll
    for (int nt = 0; nt < 8; nt++)
#pragma unroll
        for (int v = 0; v < 4; v++) oacc[nt][v] = 0.0f;

    const int nTiles = NK / KTILE;
    for (int kt = 0; kt < nTiles; kt++) {
        const int cur = kt & 1;
        CP_WAIT(0);
        __syncthreads();
        if (kt + 1 < nTiles) {
            const int nxt = (kt + 1) & 1;
            attn_stage_issue(Kh, Vp, b, h, kt + 1,
                             sKa + nxt * SK_H * 2, sVa + nxt * SV_H * 2, tid);
        }
        const uint32_t cKa = sKa + (uint32_t)(cur * SK_H * 2);
        const uint32_t cVa = sVa + (uint32_t)(cur * SV_H * 2);

        // ---- S = Q @ K^T (fp16) ----
        float s[8][4];
#pragma unroll
        for (int nt = 0; nt < 8; nt++)
#pragma unroll
            for (int v = 0; v < 4; v++) s[nt][v] = 0.0f;

#pragma unroll
        for (int st = 0; st < 4; st++) {
#pragma unroll
            for (int p = 0; p < 4; p++) {
                uint32_t addr = cKa + (uint32_t)(
                    ((p * 16 + k_rowoff) * KSTH + st * 16 + k_coloff) * 2);
                uint32_t b0, b1, b2, b3;
                ldsm_x4(b0, b1, b2, b3, addr);
                uint32_t bb0[2] = {b0, b1};
                uint32_t bb1[2] = {b2, b3};
                mma_f16(s[2*p],     qf[st], bb0);
                mma_f16(s[2*p + 1], qf[st], bb1);
            }
        }

        // ---- Online softmax ----
        float mt0 = -1e30f, mt1 = -1e30f;
#pragma unroll
        for (int nt = 0; nt < 8; nt++) {
            mt0 = fmaxf(mt0, fmaxf(s[nt][0], s[nt][1]));
            mt1 = fmaxf(mt1, fmaxf(s[nt][2], s[nt][3]));
        }
        mt0 = fmaxf(mt0, __shfl_xor_sync(0xffffffffu, mt0, 1));
        mt0 = fmaxf(mt0, __shfl_xor_sync(0xffffffffu, mt0, 2));
        mt1 = fmaxf(mt1, __shfl_xor_sync(0xffffffffu, mt1, 1));
        mt1 = fmaxf(mt1, __shfl_xor_sync(0xffffffffu, mt1, 2));

        float mn0 = fmaxf(m0, mt0), mn1 = fmaxf(m1, mt1);
        float a0 = ex2(m0 - mn0), a1 = ex2(m1 - mn1);
        m0 = mn0; m1 = mn1;

        float rs0 = 0.0f, rs1 = 0.0f;
#pragma unroll
        for (int nt = 0; nt < 8; nt++) {
            float p00 = ex2(s[nt][0] - mn0);
            float p01 = ex2(s[nt][1] - mn0);
            float p10 = ex2(s[nt][2] - mn1);
            float p11 = ex2(s[nt][3] - mn1);
            rs0 += p00 + p01;
            rs1 += p10 + p11;
            int c = nt * 8 + ig * 2;
            *(__half2*)&sP[r0 * PSTH + c] = __floats2half2_rn(p00, p01);
            *(__half2*)&sP[(r0 + 8) * PSTH + c] = __floats2half2_rn(p10, p11);
        }
        rs0 += __shfl_xor_sync(0xffffffffu, rs0, 1);
        rs0 += __shfl_xor_sync(0xffffffffu, rs0, 2);
        rs1 += __shfl_xor_sync(0xffffffffu, rs1, 1);
        rs1 += __shfl_xor_sync(0xffffffffu, rs1, 2);
        l0 = l0 * a0 + rs0;
        l1 = l1 * a1 + rs1;

#pragma unroll
        for (int nt = 0; nt < 8; nt++) {
            oacc[nt][0] *= a0; oacc[nt][1] *= a0;
            oacc[nt][2] *= a1; oacc[nt][3] *= a1;
        }
        __syncwarp();

        // ---- oacc += P @ V (fp16) ----
#pragma unroll
        for (int st = 0; st < 4; st++) {
            const int k0 = st * 16;
            uint32_t af[4];
            {
                uint32_t addr = sPa + (uint32_t)((p_row * PSTH + k0 + p_col) * 2);
                ldsm_x4(af[0], af[1], af[2], af[3], addr);
            }
#pragma unroll
            for (int p = 0; p < 4; p++) {
                uint32_t addr = cVa + (uint32_t)(
                    ((k0 + v_rowoff) * VSTH + p * 16 + v_coloff) * 2);
                uint32_t b0, b1, b2, b3;
                ldsm_x4_trans(b0, b1, b2, b3, addr);
                uint32_t bb0[2] = {b0, b1};
                uint32_t bb1[2] = {b2, b3};
                mma_f16(oacc[2*p],     af, bb0);
                mma_f16(oacc[2*p + 1], af, bb1);
            }
        }
    }

    // ---- Epilogue: normalize, write fp16 O ----
    float inv0 = 1.0f / l0, inv1 = 1.0f / l1;
    const int grow = qt * QROWS + r0;
#pragma unroll
    for (int nt = 0; nt < 8; nt++) {
        int col = h * HD + nt * 8 + ig * 2;
        *(__half2*)&Oh[((size_t)b * NQ + grow) * DM + col] =
            __floats2half2_rn(oacc[nt][0] * inv0, oacc[nt][1] * inv0);
        *(__half2*)&Oh[((size_t)b * NQ + grow + 8) * DM + col] =
            __floats2half2_rn(oacc[nt][2] * inv1, oacc[nt][3] * inv1);
    }
}

// ---------------------------------------------------------------------------
// Launch
// ---------------------------------------------------------------------------
extern "C" void kernel_launch(void* const* d_in, const int* in_sizes, int n_in,
                              void* d_out, int out_size)
{
    const float* queries = (const float*)d_in[0];
    const float* keys    = (const float*)d_in[1];
    const float* values  = (const float*)d_in[2];
    const float* Wq      = (const float*)d_in[3];
    const float* Wk      = (const float*)d_in[4];
    const float* Wv      = (const float*)d_in[5];
    const float* Wo      = (const float*)d_in[6];
    const float* bo      = (const float*)d_in[7];
    float* out           = (float*)d_out;

    __half *Qh, *Kh, *Vh, *Oh, *WTH, *INH;
    cudaGetSymbolAddress((void**)&Qh, g_Qh);
    cudaGetSymbolAddress((void**)&Kh, g_Kh);
    cudaGetSymbolAddress((void**)&Vh, g_Vh);
    cudaGetSymbolAddress((void**)&Oh, g_Oh);
    cudaGetSymbolAddress((void**)&WTH, g_WTH);
    cudaGetSymbolAddress((void**)&INH, g_INH);

    static bool attr_set = false;
    if (!attr_set) {
        cudaFuncSetAttribute(attn_mma,
                             cudaFuncAttributeMaxDynamicSharedMemorySize, SMEM_ATT);
        cudaFuncSetAttribute(gemm_qkv,
                             cudaFuncAttributeMaxDynamicSharedMemorySize, SMEM_GEMMH);
        cudaFuncSetAttribute(gemm_out16,
                             cudaFuncAttributeMaxDynamicSharedMemorySize, SMEM_GEMMH);
        attr_set = true;
    }

    dim3 tgrid(DM / 32, DM / 32, 4), tblk(32, 8);
    transpose4<<<tgrid, tblk>>>(Wq, Wk, Wv, Wo, WTH);

    dim3 pgrid(1024, 1, 3);
    prep_inputs<<<pgrid, 256>>>(queries, keys, values, INH);

    dim3 qgrid(DM / GBN, MROWS / GBM, 3);
    gemm_qkv<<<qgrid, 256, SMEM_GEMMH>>>(INH, WTH, Qh, Kh, Vh);

    dim3 agrid(NQ / QROWS, NH, BATCH);
    attn_mma<<<agrid, 256, SMEM_ATT>>>(Qh, Kh, Vh, Oh);

    dim3 ogrid(DM / GBN, MROWS / GBM);
    gemm_out16<<<ogrid, 256, SMEM_GEMMH>>>(Oh, WTH + 3 * (size_t)DM * DM, bo, out);
}

// round 15
// speedup vs baseline: 7.5626x; 1.0380x over previous
#include <cuda_runtime.h>
#include <cuda_fp16.h>
#include <math.h>
#include <stdint.h>

#define BATCH 4
#define NQ 2048
#define NK 2048
#define DM 1024
#define NH 16
#define HD 64
#define MROWS (BATCH * NQ)   // 8192

// Scratch (all 16-bit)
__device__ __half g_Qh[MROWS * DM];
__device__ __half g_Kh[MROWS * DM];
__device__ __half g_Vh[MROWS * DM];
__device__ __half g_Oh[MROWS * DM];
__device__ __half g_WTH[4 * DM * DM];
__device__ __half g_INH[3 * MROWS * DM];

#define QSCALE (0.03125f * 1.4426950408889634f)   // 1/sqrt(1024) * log2(e)

__device__ __forceinline__ float ex2(float x) {
    float r;
    asm("ex2.approx.ftz.f32 %0, %1;" : "=f"(r) : "f"(x));
    return r;
}

__device__ __forceinline__ void mma_f16(float* c, const uint32_t* a, const uint32_t* b) {
    asm volatile(
        "mma.sync.aligned.m16n8k16.row.col.f32.f16.f16.f32 "
        "{%0,%1,%2,%3}, {%4,%5,%6,%7}, {%8,%9}, {%0,%1,%2,%3};"
        : "+f"(c[0]), "+f"(c[1]), "+f"(c[2]), "+f"(c[3])
        : "r"(a[0]), "r"(a[1]), "r"(a[2]), "r"(a[3]), "r"(b[0]), "r"(b[1]));
}

__device__ __forceinline__ void ldsm_x4(uint32_t& r0, uint32_t& r1,
                                        uint32_t& r2, uint32_t& r3, uint32_t addr) {
    asm volatile("ldmatrix.sync.aligned.m8n8.x4.shared.b16 {%0,%1,%2,%3}, [%4];"
        : "=r"(r0), "=r"(r1), "=r"(r2), "=r"(r3) : "r"(addr));
}

__device__ __forceinline__ void ldsm_x4_trans(uint32_t& r0, uint32_t& r1,
                                              uint32_t& r2, uint32_t& r3, uint32_t addr) {
    asm volatile("ldmatrix.sync.aligned.m8n8.x4.trans.shared.b16 {%0,%1,%2,%3}, [%4];"
        : "=r"(r0), "=r"(r1), "=r"(r2), "=r"(r3) : "r"(addr));
}

__device__ __forceinline__ uint32_t smem_u32(const void* p) {
    uint32_t a;
    asm("{ .reg .u64 t; cvta.to.shared.u64 t, %1; cvt.u32.u64 %0, t; }"
        : "=r"(a) : "l"(p));
    return a;
}

__device__ __forceinline__ void cp16(uint32_t dst, const void* src) {
    asm volatile("cp.async.ca.shared.global [%0], [%1], 16;" :: "r"(dst), "l"(src));
}
#define CP_COMMIT() asm volatile("cp.async.commit_group;" ::: "memory")
#define CP_WAIT(n)  asm volatile("cp.async.wait_group %0;" :: "n"(n) : "memory")

// ---------------------------------------------------------------------------
// Weight transpose: all 4 weights -> fp16 transposed [N][K]
// ---------------------------------------------------------------------------
__global__ void transpose4(const float* __restrict__ W0, const float* __restrict__ W1,
                           const float* __restrict__ W2, const float* __restrict__ W3,
                           __half* __restrict__ WTH)
{
    __shared__ float t[32][33];
    const int z = blockIdx.z;
    const float* W = (z == 0) ? W0 : (z == 1) ? W1 : (z == 2) ? W2 : W3;
    __half* d = WTH + (size_t)z * DM * DM;
    int bx = blockIdx.x * 32, by = blockIdx.y * 32;
    for (int j = threadIdx.y; j < 32; j += 8)
        t[j][threadIdx.x] = W[(size_t)(by + j) * DM + bx + threadIdx.x];
    __syncthreads();
    for (int j = threadIdx.y; j < 32; j += 8)
        d[(size_t)(bx + j) * DM + by + threadIdx.x] = __float2half_rn(t[threadIdx.x][j]);
}

// ---------------------------------------------------------------------------
// Input prep: all 3 activations -> fp16
// ---------------------------------------------------------------------------
__global__ __launch_bounds__(256) void prep_inputs(
    const float* __restrict__ q, const float* __restrict__ k,
    const float* __restrict__ v, __half* __restrict__ INH)
{
    const int z = blockIdx.z;
    const float* src = (z == 0) ? q : (z == 1) ? k : v;
    __half* d = INH + (size_t)z * MROWS * DM;
    const size_t n4 = (size_t)MROWS * DM / 4;
    for (size_t i = blockIdx.x * 256 + threadIdx.x; i < n4; i += (size_t)gridDim.x * 256) {
        float4 x = ((const float4*)src)[i];
        __half2 lo = __floats2half2_rn(x.x, x.y);
        __half2 hi = __floats2half2_rn(x.z, x.w);
        uint2 pk;
        pk.x = *(uint32_t*)&lo;
        pk.y = *(uint32_t*)&hi;
        ((uint2*)d)[i] = pk;
    }
}

// ---------------------------------------------------------------------------
// FP16 mma GEMM (unchanged from R14): m16n8k16, 128x128, BK=32, cp.async x2,
// ldmatrix. mode: 0 = fp16; 1 = fp16 * QSCALE; 2 = fp32 + bias.
// ---------------------------------------------------------------------------
#define GBM 128
#define GBN 128
#define GBK 32
#define HST 28
#define HTILE_U32 (GBM * HST)
#define HSTAGE_U32 (2 * HTILE_U32)
#define SMEM_GEMMH (2 * HSTAGE_U32 * 4)

__device__ __forceinline__ void gemmh_stage_issue(
    const __half* __restrict__ A, const __half* __restrict__ BT,
    int bm, int bn, int k0, uint32_t sA_addr, uint32_t sB_addr, int tid)
{
#pragma unroll
    for (int i = 0; i < 2; i++) {
        int idx = tid + i * 256;
        int r = idx >> 2;
        int c = idx & 3;
        uint32_t off = (uint32_t)(r * HST * 4 + c * 16);
        cp16(sA_addr + off, A + (size_t)(bm + r) * DM + k0 + c * 8);
        cp16(sB_addr + off, BT + (size_t)(bn + r) * DM + k0 + c * 8);
    }
    CP_COMMIT();
}

__device__ __forceinline__ void gemm16_core(
    const __half* __restrict__ A, const __half* __restrict__ BT,
    const float* __restrict__ bias, void* __restrict__ Cv,
    int mode, uint32_t* hsm)
{
    const uint32_t sbase = smem_u32(hsm);
    const int tid = threadIdx.x;
    const int wid = tid >> 5;
    const int lane = tid & 31;
    const int gID = lane >> 2;
    const int ig  = lane & 3;
    const int lm_m = lane >> 3;
    const int lm_r = lane & 7;
    const int warp_m = wid >> 2;
    const int warp_n = wid & 3;
    const int bm = blockIdx.y * GBM;
    const int bn = blockIdx.x * GBN;

    float acc[4][4][4];
#pragma unroll
    for (int i = 0; i < 4; i++)
#pragma unroll
        for (int j = 0; j < 4; j++)
#pragma unroll
            for (int v = 0; v < 4; v++) acc[i][j][v] = 0.0f;

    const int kSteps = DM / GBK;

    gemmh_stage_issue(A, BT, bm, bn, 0, sbase, sbase + HTILE_U32 * 4, tid);

    for (int kt = 0; kt < kSteps; kt++) {
        const int cur = kt & 1;
        if (kt + 1 < kSteps) {
            const int nxt = (kt + 1) & 1;
            gemmh_stage_issue(A, BT, bm, bn, (kt + 1) * GBK,
                              sbase + nxt * HSTAGE_U32 * 4,
                              sbase + (nxt * HSTAGE_U32 + HTILE_U32) * 4, tid);
            CP_WAIT(1);
        } else {
            CP_WAIT(0);
        }
        __syncthreads();

        const uint32_t sAa = sbase + (uint32_t)(cur * HSTAGE_U32 * 4);
        const uint32_t sBa = sAa + HTILE_U32 * 4;

#pragma unroll
        for (int st = 0; st < 2; st++) {
            uint32_t afrag[4][4];
#pragma unroll
            for (int mt = 0; mt < 4; mt++) {
                uint32_t addr = sAa + (uint32_t)(
                    ((warp_m * 64 + mt * 16 + (lm_m & 1) * 8 + lm_r) * HST
                     + st * 8 + (lm_m >> 1) * 4) * 4);
                ldsm_x4(afrag[mt][0], afrag[mt][1], afrag[mt][2], afrag[mt][3], addr);
            }
            uint32_t bfrag[4][2];
#pragma unroll
            for (int p = 0; p < 2; p++) {
                uint32_t addr = sBa + (uint32_t)(
                    ((warp_n * 32 + p * 16 + (lm_m >> 1) * 8 + lm_r) * HST
                     + st * 8 + (lm_m & 1) * 4) * 4);
                ldsm_x4(bfrag[2*p][0], bfrag[2*p][1],
                        bfrag[2*p+1][0], bfrag[2*p+1][1], addr);
            }
#pragma unroll
            for (int mt = 0; mt < 4; mt++)
#pragma unroll
                for (int nt = 0; nt < 4; nt++)
                    mma_f16(acc[mt][nt], afrag[mt], bfrag[nt]);
        }
        __syncthreads();
    }

#pragma unroll
    for (int mt = 0; mt < 4; mt++) {
#pragma unroll
        for (int nt = 0; nt < 4; nt++) {
            int row = bm + warp_m * 64 + mt * 16 + gID;
            int col = bn + warp_n * 32 + nt * 8 + ig * 2;
            float2 v0, v1;
            v0.x = acc[mt][nt][0]; v0.y = acc[mt][nt][1];
            v1.x = acc[mt][nt][2]; v1.y = acc[mt][nt][3];
            if (mode == 2) {
                float b0 = bias[col], b1 = bias[col + 1];
                v0.x += b0; v0.y += b1;
                v1.x += b0; v1.y += b1;
                float* C = (float*)Cv;
                *(float2*)&C[(size_t)row * DM + col] = v0;
                *(float2*)&C[(size_t)(row + 8) * DM + col] = v1;
            } else {
                if (mode == 1) {
                    v0.x *= QSCALE; v0.y *= QSCALE;
                    v1.x *= QSCALE; v1.y *= QSCALE;
                }
                __half* C = (__half*)Cv;
                *(__half2*)&C[(size_t)row * DM + col] = __floats2half2_rn(v0.x, v0.y);
                *(__half2*)&C[(size_t)(row + 8) * DM + col] = __floats2half2_rn(v1.x, v1.y);
            }
        }
    }
}

__global__ __launch_bounds__(256, 2) void gemm_qkv(
    const __half* __restrict__ INH, const __half* __restrict__ WTH,
    __half* __restrict__ Qo, __half* __restrict__ Ko, __half* __restrict__ Vo)
{
    extern __shared__ uint32_t hsm[];
    const int z = blockIdx.z;
    const __half* A  = INH + (size_t)z * MROWS * DM;
    const __half* BT = WTH + (size_t)z * DM * DM;
    if (z == 0)      gemm16_core(A, BT, nullptr, Qo, 1, hsm);
    else if (z == 1) gemm16_core(A, BT, nullptr, Ko, 0, hsm);
    else             gemm16_core(A, BT, nullptr, Vo, 0, hsm);
}

__global__ __launch_bounds__(256, 2) void gemm_out16(
    const __half* __restrict__ A, const __half* __restrict__ BT,
    const float* __restrict__ bias, float* __restrict__ C)
{
    extern __shared__ uint32_t hsm[];
    gemm16_core(A, BT, bias, C, 2, hsm);
}

// ---------------------------------------------------------------------------
// Flash attention rev 5: all-fp16 MMA; P kept in REGISTERS (FA2 layout reuse
// — S accumulator quad layout == PV A-fragment layout). No sP smem at all.
// ---------------------------------------------------------------------------
#define QROWS 128
#define KSTH 72
#define VSTH 72
#define KTILE 64
#define SK_H (KTILE * KSTH)
#define SV_H (KTILE * VSTH)
#define SMEM_ATT ((2 * SK_H + 2 * SV_H) * 2)   // 36864 B

__device__ __forceinline__ void attn_stage_issue(
    const __half* __restrict__ Kh, const __half* __restrict__ Vp,
    int b, int h, int kt, uint32_t sK_addr, uint32_t sV_addr, int tid)
{
    const __half* Kbase = Kh + ((size_t)b * NK + kt * KTILE) * DM + h * HD;
    const __half* Vbase = Vp + ((size_t)b * NK + kt * KTILE) * DM + h * HD;
#pragma unroll
    for (int i = 0; i < 2; i++) {
        int idx = tid + i * 256;
        int r = idx >> 3;
        int c16 = idx & 7;
        cp16(sK_addr + (uint32_t)(r * KSTH * 2 + c16 * 16),
             Kbase + (size_t)r * DM + c16 * 8);
        cp16(sV_addr + (uint32_t)(r * VSTH * 2 + c16 * 16),
             Vbase + (size_t)r * DM + c16 * 8);
    }
    CP_COMMIT();
}

__global__ __launch_bounds__(256, 2) void attn_mma(
    const __half* __restrict__ Qh, const __half* __restrict__ Kh,
    const __half* __restrict__ Vp, __half* __restrict__ Oh)
{
    extern __shared__ __half smh[];
    __half* sV = smh;                    // 2 x [64][VSTH]
    __half* sK = sV + 2 * SV_H;          // 2 x [64][KSTH]
    const uint32_t sVa = smem_u32(sV);
    const uint32_t sKa = smem_u32(sK);

    const int tid = threadIdx.x;
    const int wid = tid >> 5;
    const int lane = tid & 31;
    const int gID = lane >> 2;
    const int ig  = lane & 3;
    const int lm_m = lane >> 3;
    const int lm_r = lane & 7;
    const int qt = blockIdx.x;
    const int h  = blockIdx.y;
    const int b  = blockIdx.z;

    const int r0 = wid * 16 + gID;

    attn_stage_issue(Kh, Vp, b, h, 0, sKa, sVa, tid);

    uint32_t qf[4][4];
    {
        const __half* Qb = Qh + ((size_t)b * NQ + qt * QROWS + r0) * DM + h * HD;
#pragma unroll
        for (int st = 0; st < 4; st++) {
            int kk0 = st * 16;
            qf[st][0] = *(const uint32_t*)&Qb[kk0 + 2 * ig];
            qf[st][1] = *(const uint32_t*)&Qb[8 * DM + kk0 + 2 * ig];
            qf[st][2] = *(const uint32_t*)&Qb[kk0 + 8 + 2 * ig];
            qf[st][3] = *(const uint32_t*)&Qb[8 * DM + kk0 + 8 + 2 * ig];
        }
    }

    const uint32_t k_rowoff = (uint32_t)((lm_m >> 1) * 8 + lm_r);
    const uint32_t k_coloff = (uint32_t)((lm_m & 1) * 8);
    const uint32_t v_rowoff = (uint32_t)((lm_m & 1) * 8 + lm_r);
    const uint32_t v_coloff = (uint32_t)((lm_m >> 1) * 8);

    float m0 = -1e30f, m1 = -1e30f, l0 = 0.0f, l1 = 0.0f;
    float oacc[8][4];
#pragma unroll
    for (int nt = 0; nt < 8; nt++)
#pragma unroll
        for (int v = 0; v < 4; v++) oacc[nt][v] = 0.0f;

    const int nTiles = NK / KTILE;
    for (int kt = 0; kt < nTiles; kt++) {
        const int cur = kt & 1;
        CP_WAIT(0);
        __syncthreads();
        if (kt + 1 < nTiles) {
            const int nxt = (kt + 1) & 1;
            attn_stage_issue(Kh, Vp, b, h, kt + 1,
                             sKa + nxt * SK_H * 2, sVa + nxt * SV_H * 2, tid);
        }
        const uint32_t cKa = sKa + (uint32_t)(cur * SK_H * 2);
        const uint32_t cVa = sVa + (uint32_t)(cur * SV_H * 2);

        // ---- S = Q @ K^T (fp16) ----
        float s[8][4];
#pragma unroll
        for (int nt = 0; nt < 8; nt++)
#pragma unroll
            for (int v = 0; v < 4; v++) s[nt][v] = 0.0f;

#pragma unroll
        for (int st = 0; st < 4; st++) {
#pragma unroll
            for (int p = 0; p < 4; p++) {
                uint32_t addr = cKa + (uint32_t)(
                    ((p * 16 + k_rowoff) * KSTH + st * 16 + k_coloff) * 2);
                uint32_t b0, b1, b2, b3;
                ldsm_x4(b0, b1, b2, b3, addr);
                uint32_t bb0[2] = {b0, b1};
                uint32_t bb1[2] = {b2, b3};
                mma_f16(s[2*p],     qf[st], bb0);
                mma_f16(s[2*p + 1], qf[st], bb1);
            }
        }

        // ---- Online softmax; P packed straight into A-fragment registers ----
        float mt0 = -1e30f, mt1 = -1e30f;
#pragma unroll
        for (int nt = 0; nt < 8; nt++) {
            mt0 = fmaxf(mt0, fmaxf(s[nt][0], s[nt][1]));
            mt1 = fmaxf(mt1, fmaxf(s[nt][2], s[nt][3]));
        }
        mt0 = fmaxf(mt0, __shfl_xor_sync(0xffffffffu, mt0, 1));
        mt0 = fmaxf(mt0, __shfl_xor_sync(0xffffffffu, mt0, 2));
        mt1 = fmaxf(mt1, __shfl_xor_sync(0xffffffffu, mt1, 1));
        mt1 = fmaxf(mt1, __shfl_xor_sync(0xffffffffu, mt1, 2));

        float mn0 = fmaxf(m0, mt0), mn1 = fmaxf(m1, mt1);
        float a0 = ex2(m0 - mn0), a1 = ex2(m1 - mn1);
        m0 = mn0; m1 = mn1;

        uint32_t pf[8][2];   // pf[nt][0] = rows r0 pair, pf[nt][1] = rows r0+8 pair
        float rs0 = 0.0f, rs1 = 0.0f;
#pragma unroll
        for (int nt = 0; nt < 8; nt++) {
            float p00 = ex2(s[nt][0] - mn0);
            float p01 = ex2(s[nt][1] - mn0);
            float p10 = ex2(s[nt][2] - mn1);
            float p11 = ex2(s[nt][3] - mn1);
            rs0 += p00 + p01;
            rs1 += p10 + p11;
            __half2 h0 = __floats2half2_rn(p00, p01);
            __half2 h1 = __floats2half2_rn(p10, p11);
            pf[nt][0] = *(uint32_t*)&h0;
            pf[nt][1] = *(uint32_t*)&h1;
        }
        rs0 += __shfl_xor_sync(0xffffffffu, rs0, 1);
        rs0 += __shfl_xor_sync(0xffffffffu, rs0, 2);
        rs1 += __shfl_xor_sync(0xffffffffu, rs1, 1);
        rs1 += __shfl_xor_sync(0xffffffffu, rs1, 2);
        l0 = l0 * a0 + rs0;
        l1 = l1 * a1 + rs1;

#pragma unroll
        for (int nt = 0; nt < 8; nt++) {
            oacc[nt][0] *= a0; oacc[nt][1] *= a0;
            oacc[nt][2] *= a1; oacc[nt][3] *= a1;
        }

        // ---- oacc += P @ V (fp16; A-frags from registers, V via ldmatrix.trans) ----
#pragma unroll
        for (int st = 0; st < 4; st++) {
            const int k0 = st * 16;
            uint32_t af[4];
            af[0] = pf[2*st][0];
            af[1] = pf[2*st][1];
            af[2] = pf[2*st + 1][0];
            af[3] = pf[2*st + 1][1];
#pragma unroll
            for (int p = 0; p < 4; p++) {
                uint32_t addr = cVa + (uint32_t)(
                    ((k0 + v_rowoff) * VSTH + p * 16 + v_coloff) * 2);
                uint32_t b0, b1, b2, b3;
                ldsm_x4_trans(b0, b1, b2, b3, addr);
                uint32_t bb0[2] = {b0, b1};
                uint32_t bb1[2] = {b2, b3};
                mma_f16(oacc[2*p],     af, bb0);
                mma_f16(oacc[2*p + 1], af, bb1);
            }
        }
    }

    // ---- Epilogue ----
    float inv0 = 1.0f / l0, inv1 = 1.0f / l1;
    const int grow = qt * QROWS + r0;
#pragma unroll
    for (int nt = 0; nt < 8; nt++) {
        int col = h * HD + nt * 8 + ig * 2;
        *(__half2*)&Oh[((size_t)b * NQ + grow) * DM + col] =
            __floats2half2_rn(oacc[nt][0] * inv0, oacc[nt][1] * inv0);
        *(__half2*)&Oh[((size_t)b * NQ + grow + 8) * DM + col] =
            __floats2half2_rn(oacc[nt][2] * inv1, oacc[nt][3] * inv1);
    }
}

// ---------------------------------------------------------------------------
// Launch
// ---------------------------------------------------------------------------
extern "C" void kernel_launch(void* const* d_in, const int* in_sizes, int n_in,
                              void* d_out, int out_size)
{
    const float* queries = (const float*)d_in[0];
    const float* keys    = (const float*)d_in[1];
    const float* values  = (const float*)d_in[2];
    const float* Wq      = (const float*)d_in[3];
    const float* Wk      = (const float*)d_in[4];
    const float* Wv      = (const float*)d_in[5];
    const float* Wo      = (const float*)d_in[6];
    const float* bo      = (const float*)d_in[7];
    float* out           = (float*)d_out;

    __half *Qh, *Kh, *Vh, *Oh, *WTH, *INH;
    cudaGetSymbolAddress((void**)&Qh, g_Qh);
    cudaGetSymbolAddress((void**)&Kh, g_Kh);
    cudaGetSymbolAddress((void**)&Vh, g_Vh);
    cudaGetSymbolAddress((void**)&Oh, g_Oh);
    cudaGetSymbolAddress((void**)&WTH, g_WTH);
    cudaGetSymbolAddress((void**)&INH, g_INH);

    static bool attr_set = false;
    if (!attr_set) {
        cudaFuncSetAttribute(attn_mma,
                             cudaFuncAttributeMaxDynamicSharedMemorySize, SMEM_ATT);
        cudaFuncSetAttribute(gemm_qkv,
                             cudaFuncAttributeMaxDynamicSharedMemorySize, SMEM_GEMMH);
        cudaFuncSetAttribute(gemm_out16,
                             cudaFuncAttributeMaxDynamicSharedMemorySize, SMEM_GEMMH);
        attr_set = true;
    }

    dim3 tgrid(DM / 32, DM / 32, 4), tblk(32, 8);
    transpose4<<<tgrid, tblk>>>(Wq, Wk, Wv, Wo, WTH);

    dim3 pgrid(1024, 1, 3);
    prep_inputs<<<pgrid, 256>>>(queries, keys, values, INH);

    dim3 qgrid(DM / GBN, MROWS / GBM, 3);
    gemm_qkv<<<qgrid, 256, SMEM_GEMMH>>>(INH, WTH, Qh, Kh, Vh);

    dim3 agrid(NQ / QROWS, NH, BATCH);
    attn_mma<<<agrid, 256, SMEM_ATT>>>(Qh, Kh, Vh, Oh);

    dim3 ogrid(DM / GBN, MROWS / GBM);
    gemm_out16<<<ogrid, 256, SMEM_GEMMH>>>(Oh, WTH + 3 * (size_t)DM * DM, bo, out);
}

// round 16
// speedup vs baseline: 8.2703x; 1.0936x over previous
#include <cuda_runtime.h>
#include <cuda_fp16.h>
#include <math.h>
#include <stdint.h>

#define BATCH 4
#define NQ 2048
#define NK 2048
#define DM 1024
#define NH 16
#define HD 64
#define MROWS (BATCH * NQ)   // 8192

// Scratch (all 16-bit)
__device__ __half g_Qh[MROWS * DM];
__device__ __half g_Kh[MROWS * DM];
__device__ __half g_Vh[MROWS * DM];
__device__ __half g_Oh[MROWS * DM];
__device__ __half g_WTH[4 * DM * DM];
__device__ __half g_INH[3 * MROWS * DM];

#define QSCALE (0.03125f * 1.4426950408889634f)   // 1/sqrt(1024) * log2(e)

__device__ __forceinline__ float ex2(float x) {
    float r;
    asm("ex2.approx.ftz.f32 %0, %1;" : "=f"(r) : "f"(x));
    return r;
}

__device__ __forceinline__ void mma_f16(float* c, const uint32_t* a, const uint32_t* b) {
    asm volatile(
        "mma.sync.aligned.m16n8k16.row.col.f32.f16.f16.f32 "
        "{%0,%1,%2,%3}, {%4,%5,%6,%7}, {%8,%9}, {%0,%1,%2,%3};"
        : "+f"(c[0]), "+f"(c[1]), "+f"(c[2]), "+f"(c[3])
        : "r"(a[0]), "r"(a[1]), "r"(a[2]), "r"(a[3]), "r"(b[0]), "r"(b[1]));
}

__device__ __forceinline__ void ldsm_x4(uint32_t& r0, uint32_t& r1,
                                        uint32_t& r2, uint32_t& r3, uint32_t addr) {
    asm volatile("ldmatrix.sync.aligned.m8n8.x4.shared.b16 {%0,%1,%2,%3}, [%4];"
        : "=r"(r0), "=r"(r1), "=r"(r2), "=r"(r3) : "r"(addr));
}

__device__ __forceinline__ void ldsm_x4_trans(uint32_t& r0, uint32_t& r1,
                                              uint32_t& r2, uint32_t& r3, uint32_t addr) {
    asm volatile("ldmatrix.sync.aligned.m8n8.x4.trans.shared.b16 {%0,%1,%2,%3}, [%4];"
        : "=r"(r0), "=r"(r1), "=r"(r2), "=r"(r3) : "r"(addr));
}

__device__ __forceinline__ uint32_t smem_u32(const void* p) {
    uint32_t a;
    asm("{ .reg .u64 t; cvta.to.shared.u64 t, %1; cvt.u32.u64 %0, t; }"
        : "=r"(a) : "l"(p));
    return a;
}

__device__ __forceinline__ void cp16(uint32_t dst, const void* src) {
    asm volatile("cp.async.ca.shared.global [%0], [%1], 16;" :: "r"(dst), "l"(src));
}
#define CP_COMMIT() asm volatile("cp.async.commit_group;" ::: "memory")
#define CP_WAIT(n)  asm volatile("cp.async.wait_group %0;" :: "n"(n) : "memory")

// ---------------------------------------------------------------------------
// Weight transpose: all 4 weights -> fp16 transposed [N][K]
// ---------------------------------------------------------------------------
__global__ void transpose4(const float* __restrict__ W0, const float* __restrict__ W1,
                           const float* __restrict__ W2, const float* __restrict__ W3,
                           __half* __restrict__ WTH)
{
    __shared__ float t[32][33];
    const int z = blockIdx.z;
    const float* W = (z == 0) ? W0 : (z == 1) ? W1 : (z == 2) ? W2 : W3;
    __half* d = WTH + (size_t)z * DM * DM;
    int bx = blockIdx.x * 32, by = blockIdx.y * 32;
    for (int j = threadIdx.y; j < 32; j += 8)
        t[j][threadIdx.x] = W[(size_t)(by + j) * DM + bx + threadIdx.x];
    __syncthreads();
    for (int j = threadIdx.y; j < 32; j += 8)
        d[(size_t)(bx + j) * DM + by + threadIdx.x] = __float2half_rn(t[threadIdx.x][j]);
}

// ---------------------------------------------------------------------------
// Input prep: all 3 activations -> fp16
// ---------------------------------------------------------------------------
__global__ __launch_bounds__(256) void prep_inputs(
    const float* __restrict__ q, const float* __restrict__ k,
    const float* __restrict__ v, __half* __restrict__ INH)
{
    const int z = blockIdx.z;
    const float* src = (z == 0) ? q : (z == 1) ? k : v;
    __half* d = INH + (size_t)z * MROWS * DM;
    const size_t n4 = (size_t)MROWS * DM / 4;
    for (size_t i = blockIdx.x * 256 + threadIdx.x; i < n4; i += (size_t)gridDim.x * 256) {
        float4 x = ((const float4*)src)[i];
        __half2 lo = __floats2half2_rn(x.x, x.y);
        __half2 hi = __floats2half2_rn(x.z, x.w);
        uint2 pk;
        pk.x = *(uint32_t*)&lo;
        pk.y = *(uint32_t*)&hi;
        ((uint2*)d)[i] = pk;
    }
}

// ---------------------------------------------------------------------------
// FP16 mma GEMM: m16n8k16, tile 128x128, BK=64 fp16 (4 k16-steps per buffer),
// 2-stage cp.async, ldmatrix fragments.
// mode: 0 = fp16; 1 = fp16 * QSCALE; 2 = fp32 + bias.
// ---------------------------------------------------------------------------
#define GBM 128
#define GBN 128
#define GBK 64
#define HST 36                       // uint32 per smem row (144 B; 128 B data + pad)
#define HTILE_U32 (GBM * HST)        // 4608
#define HSTAGE_U32 (2 * HTILE_U32)   // 9216
#define SMEM_GEMMH (2 * HSTAGE_U32 * 4)   // 73728 B

__device__ __forceinline__ void gemmh_stage_issue(
    const __half* __restrict__ A, const __half* __restrict__ BT,
    int bm, int bn, int k0, uint32_t sA_addr, uint32_t sB_addr, int tid)
{
#pragma unroll
    for (int i = 0; i < 4; i++) {
        int idx = tid + i * 256;
        int r = idx >> 3;       // 0..127
        int c = idx & 7;        // 0..7 (16B chunks of 128B row)
        uint32_t off = (uint32_t)(r * HST * 4 + c * 16);
        cp16(sA_addr + off, A + (size_t)(bm + r) * DM + k0 + c * 8);
        cp16(sB_addr + off, BT + (size_t)(bn + r) * DM + k0 + c * 8);
    }
    CP_COMMIT();
}

__device__ __forceinline__ void gemm16_core(
    const __half* __restrict__ A, const __half* __restrict__ BT,
    const float* __restrict__ bias, void* __restrict__ Cv,
    int mode, uint32_t* hsm)
{
    const uint32_t sbase = smem_u32(hsm);
    const int tid = threadIdx.x;
    const int wid = tid >> 5;
    const int lane = tid & 31;
    const int gID = lane >> 2;
    const int ig  = lane & 3;
    const int lm_m = lane >> 3;
    const int lm_r = lane & 7;
    const int warp_m = wid >> 2;
    const int warp_n = wid & 3;
    const int bm = blockIdx.y * GBM;
    const int bn = blockIdx.x * GBN;

    float acc[4][4][4];
#pragma unroll
    for (int i = 0; i < 4; i++)
#pragma unroll
        for (int j = 0; j < 4; j++)
#pragma unroll
            for (int v = 0; v < 4; v++) acc[i][j][v] = 0.0f;

    const int kSteps = DM / GBK;   // 16

    gemmh_stage_issue(A, BT, bm, bn, 0, sbase, sbase + HTILE_U32 * 4, tid);

    for (int kt = 0; kt < kSteps; kt++) {
        const int cur = kt & 1;
        if (kt + 1 < kSteps) {
            const int nxt = (kt + 1) & 1;
            gemmh_stage_issue(A, BT, bm, bn, (kt + 1) * GBK,
                              sbase + nxt * HSTAGE_U32 * 4,
                              sbase + (nxt * HSTAGE_U32 + HTILE_U32) * 4, tid);
            CP_WAIT(1);
        } else {
            CP_WAIT(0);
        }
        __syncthreads();

        const uint32_t sAa = sbase + (uint32_t)(cur * HSTAGE_U32 * 4);
        const uint32_t sBa = sAa + HTILE_U32 * 4;

#pragma unroll
        for (int st = 0; st < 4; st++) {   // 4 k16-steps per buffer
            uint32_t afrag[4][4];
#pragma unroll
            for (int mt = 0; mt < 4; mt++) {
                uint32_t addr = sAa + (uint32_t)(
                    ((warp_m * 64 + mt * 16 + (lm_m & 1) * 8 + lm_r) * HST
                     + st * 8 + (lm_m >> 1) * 4) * 4);
                ldsm_x4(afrag[mt][0], afrag[mt][1], afrag[mt][2], afrag[mt][3], addr);
            }
            uint32_t bfrag[4][2];
#pragma unroll
            for (int p = 0; p < 2; p++) {
                uint32_t addr = sBa + (uint32_t)(
                    ((warp_n * 32 + p * 16 + (lm_m >> 1) * 8 + lm_r) * HST
                     + st * 8 + (lm_m & 1) * 4) * 4);
                ldsm_x4(bfrag[2*p][0], bfrag[2*p][1],
                        bfrag[2*p+1][0], bfrag[2*p+1][1], addr);
            }
#pragma unroll
            for (int mt = 0; mt < 4; mt++)
#pragma unroll
                for (int nt = 0; nt < 4; nt++)
                    mma_f16(acc[mt][nt], afrag[mt], bfrag[nt]);
        }
        __syncthreads();
    }

#pragma unroll
    for (int mt = 0; mt < 4; mt++) {
#pragma unroll
        for (int nt = 0; nt < 4; nt++) {
            int row = bm + warp_m * 64 + mt * 16 + gID;
            int col = bn + warp_n * 32 + nt * 8 + ig * 2;
            float2 v0, v1;
            v0.x = acc[mt][nt][0]; v0.y = acc[mt][nt][1];
            v1.x = acc[mt][nt][2]; v1.y = acc[mt][nt][3];
            if (mode == 2) {
                float b0 = bias[col], b1 = bias[col + 1];
                v0.x += b0; v0.y += b1;
                v1.x += b0; v1.y += b1;
                float* C = (float*)Cv;
                *(float2*)&C[(size_t)row * DM + col] = v0;
                *(float2*)&C[(size_t)(row + 8) * DM + col] = v1;
            } else {
                if (mode == 1) {
                    v0.x *= QSCALE; v0.y *= QSCALE;
                    v1.x *= QSCALE; v1.y *= QSCALE;
                }
                __half* C = (__half*)Cv;
                *(__half2*)&C[(size_t)row * DM + col] = __floats2half2_rn(v0.x, v0.y);
                *(__half2*)&C[(size_t)(row + 8) * DM + col] = __floats2half2_rn(v1.x, v1.y);
            }
        }
    }
}

__global__ __launch_bounds__(256, 2) void gemm_qkv(
    const __half* __restrict__ INH, const __half* __restrict__ WTH,
    __half* __restrict__ Qo, __half* __restrict__ Ko, __half* __restrict__ Vo)
{
    extern __shared__ uint32_t hsm[];
    const int z = blockIdx.z;
    const __half* A  = INH + (size_t)z * MROWS * DM;
    const __half* BT = WTH + (size_t)z * DM * DM;
    if (z == 0)      gemm16_core(A, BT, nullptr, Qo, 1, hsm);
    else if (z == 1) gemm16_core(A, BT, nullptr, Ko, 0, hsm);
    else             gemm16_core(A, BT, nullptr, Vo, 0, hsm);
}

__global__ __launch_bounds__(256, 2) void gemm_out16(
    const __half* __restrict__ A, const __half* __restrict__ BT,
    const float* __restrict__ bias, float* __restrict__ C)
{
    extern __shared__ uint32_t hsm[];
    gemm16_core(A, BT, bias, C, 2, hsm);
}

// ---------------------------------------------------------------------------
// Flash attention (unchanged from R15): all-fp16 MMA; P in registers.
// ---------------------------------------------------------------------------
#define QROWS 128
#define KSTH 72
#define VSTH 72
#define KTILE 64
#define SK_H (KTILE * KSTH)
#define SV_H (KTILE * VSTH)
#define SMEM_ATT ((2 * SK_H + 2 * SV_H) * 2)   // 36864 B

__device__ __forceinline__ void attn_stage_issue(
    const __half* __restrict__ Kh, const __half* __restrict__ Vp,
    int b, int h, int kt, uint32_t sK_addr, uint32_t sV_addr, int tid)
{
    const __half* Kbase = Kh + ((size_t)b * NK + kt * KTILE) * DM + h * HD;
    const __half* Vbase = Vp + ((size_t)b * NK + kt * KTILE) * DM + h * HD;
#pragma unroll
    for (int i = 0; i < 2; i++) {
        int idx = tid + i * 256;
        int r = idx >> 3;
        int c16 = idx & 7;
        cp16(sK_addr + (uint32_t)(r * KSTH * 2 + c16 * 16),
             Kbase + (size_t)r * DM + c16 * 8);
        cp16(sV_addr + (uint32_t)(r * VSTH * 2 + c16 * 16),
             Vbase + (size_t)r * DM + c16 * 8);
    }
    CP_COMMIT();
}

__global__ __launch_bounds__(256, 2) void attn_mma(
    const __half* __restrict__ Qh, const __half* __restrict__ Kh,
    const __half* __restrict__ Vp, __half* __restrict__ Oh)
{
    extern __shared__ __half smh[];
    __half* sV = smh;
    __half* sK = sV + 2 * SV_H;
    const uint32_t sVa = smem_u32(sV);
    const uint32_t sKa = smem_u32(sK);

    const int tid = threadIdx.x;
    const int wid = tid >> 5;
    const int lane = tid & 31;
    const int gID = lane >> 2;
    const int ig  = lane & 3;
    const int lm_m = lane >> 3;
    const int lm_r = lane & 7;
    const int qt = blockIdx.x;
    const int h  = blockIdx.y;
    const int b  = blockIdx.z;

    const int r0 = wid * 16 + gID;

    attn_stage_issue(Kh, Vp, b, h, 0, sKa, sVa, tid);

    uint32_t qf[4][4];
    {
        const __half* Qb = Qh + ((size_t)b * NQ + qt * QROWS + r0) * DM + h * HD;
#pragma unroll
        for (int st = 0; st < 4; st++) {
            int kk0 = st * 16;
            qf[st][0] = *(const uint32_t*)&Qb[kk0 + 2 * ig];
            qf[st][1] = *(const uint32_t*)&Qb[8 * DM + kk0 + 2 * ig];
            qf[st][2] = *(const uint32_t*)&Qb[kk0 + 8 + 2 * ig];
            qf[st][3] = *(const uint32_t*)&Qb[8 * DM + kk0 + 8 + 2 * ig];
        }
    }

    const uint32_t k_rowoff = (uint32_t)((lm_m >> 1) * 8 + lm_r);
    const uint32_t k_coloff = (uint32_t)((lm_m & 1) * 8);
    const uint32_t v_rowoff = (uint32_t)((lm_m & 1) * 8 + lm_r);
    const uint32_t v_coloff = (uint32_t)((lm_m >> 1) * 8);

    float m0 = -1e30f, m1 = -1e30f, l0 = 0.0f, l1 = 0.0f;
    float oacc[8][4];
#pragma unroll
    for (int nt = 0; nt < 8; nt++)
#pragma unroll
        for (int v = 0; v < 4; v++) oacc[nt][v] = 0.0f;

    const int nTiles = NK / KTILE;
    for (int kt = 0; kt < nTiles; kt++) {
        const int cur = kt & 1;
        CP_WAIT(0);
        __syncthreads();
        if (kt + 1 < nTiles) {
            const int nxt = (kt + 1) & 1;
            attn_stage_issue(Kh, Vp, b, h, kt + 1,
                             sKa + nxt * SK_H * 2, sVa + nxt * SV_H * 2, tid);
        }
        const uint32_t cKa = sKa + (uint32_t)(cur * SK_H * 2);
        const uint32_t cVa = sVa + (uint32_t)(cur * SV_H * 2);

        float s[8][4];
#pragma unroll
        for (int nt = 0; nt < 8; nt++)
#pragma unroll
            for (int v = 0; v < 4; v++) s[nt][v] = 0.0f;

#pragma unroll
        for (int st = 0; st < 4; st++) {
#pragma unroll
            for (int p = 0; p < 4; p++) {
                uint32_t addr = cKa + (uint32_t)(
                    ((p * 16 + k_rowoff) * KSTH + st * 16 + k_coloff) * 2);
                uint32_t b0, b1, b2, b3;
                ldsm_x4(b0, b1, b2, b3, addr);
                uint32_t bb0[2] = {b0, b1};
                uint32_t bb1[2] = {b2, b3};
                mma_f16(s[2*p],     qf[st], bb0);
                mma_f16(s[2*p + 1], qf[st], bb1);
            }
        }

        float mt0 = -1e30f, mt1 = -1e30f;
#pragma unroll
        for (int nt = 0; nt < 8; nt++) {
            mt0 = fmaxf(mt0, fmaxf(s[nt][0], s[nt][1]));
            mt1 = fmaxf(mt1, fmaxf(s[nt][2], s[nt][3]));
        }
        mt0 = fmaxf(mt0, __shfl_xor_sync(0xffffffffu, mt0, 1));
        mt0 = fmaxf(mt0, __shfl_xor_sync(0xffffffffu, mt0, 2));
        mt1 = fmaxf(mt1, __shfl_xor_sync(0xffffffffu, mt1, 1));
        mt1 = fmaxf(mt1, __shfl_xor_sync(0xffffffffu, mt1, 2));

        float mn0 = fmaxf(m0, mt0), mn1 = fmaxf(m1, mt1);
        float a0 = ex2(m0 - mn0), a1 = ex2(m1 - mn1);
        m0 = mn0; m1 = mn1;

        uint32_t pf[8][2];
        float rs0 = 0.0f, rs1 = 0.0f;
#pragma unroll
        for (int nt = 0; nt < 8; nt++) {
            float p00 = ex2(s[nt][0] - mn0);
            float p01 = ex2(s[nt][1] - mn0);
            float p10 = ex2(s[nt][2] - mn1);
            float p11 = ex2(s[nt][3] - mn1);
            rs0 += p00 + p01;
            rs1 += p10 + p11;
            __half2 h0 = __floats2half2_rn(p00, p01);
            __half2 h1 = __floats2half2_rn(p10, p11);
            pf[nt][0] = *(uint32_t*)&h0;
            pf[nt][1] = *(uint32_t*)&h1;
        }
        rs0 += __shfl_xor_sync(0xffffffffu, rs0, 1);
        rs0 += __shfl_xor_sync(0xffffffffu, rs0, 2);
        rs1 += __shfl_xor_sync(0xffffffffu, rs1, 1);
        rs1 += __shfl_xor_sync(0xffffffffu, rs1, 2);
        l0 = l0 * a0 + rs0;
        l1 = l1 * a1 + rs1;

#pragma unroll
        for (int nt = 0; nt < 8; nt++) {
            oacc[nt][0] *= a0; oacc[nt][1] *= a0;
            oacc[nt][2] *= a1; oacc[nt][3] *= a1;
        }

#pragma unroll
        for (int st = 0; st < 4; st++) {
            const int k0 = st * 16;
            uint32_t af[4];
            af[0] = pf[2*st][0];
            af[1] = pf[2*st][1];
            af[2] = pf[2*st + 1][0];
            af[3] = pf[2*st + 1][1];
#pragma unroll
            for (int p = 0; p < 4; p++) {
                uint32_t addr = cVa + (uint32_t)(
                    ((k0 + v_rowoff) * VSTH + p * 16 + v_coloff) * 2);
                uint32_t b0, b1, b2, b3;
                ldsm_x4_trans(b0, b1, b2, b3, addr);
                uint32_t bb0[2] = {b0, b1};
                uint32_t bb1[2] = {b2, b3};
                mma_f16(oacc[2*p],     af, bb0);
                mma_f16(oacc[2*p + 1], af, bb1);
            }
        }
    }

    float inv0 = 1.0f / l0, inv1 = 1.0f / l1;
    const int grow = qt * QROWS + r0;
#pragma unroll
    for (int nt = 0; nt < 8; nt++) {
        int col = h * HD + nt * 8 + ig * 2;
        *(__half2*)&Oh[((size_t)b * NQ + grow) * DM + col] =
            __floats2half2_rn(oacc[nt][0] * inv0, oacc[nt][1] * inv0);
        *(__half2*)&Oh[((size_t)b * NQ + grow + 8) * DM + col] =
            __floats2half2_rn(oacc[nt][2] * inv1, oacc[nt][3] * inv1);
    }
}

// ---------------------------------------------------------------------------
// Launch
// ---------------------------------------------------------------------------
extern "C" void kernel_launch(void* const* d_in, const int* in_sizes, int n_in,
                              void* d_out, int out_size)
{
    const float* queries = (const float*)d_in[0];
    const float* keys    = (const float*)d_in[1];
    const float* values  = (const float*)d_in[2];
    const float* Wq      = (const float*)d_in[3];
    const float* Wk      = (const float*)d_in[4];
    const float* Wv      = (const float*)d_in[5];
    const float* Wo      = (const float*)d_in[6];
    const float* bo      = (const float*)d_in[7];
    float* out           = (float*)d_out;

    __half *Qh, *Kh, *Vh, *Oh, *WTH, *INH;
    cudaGetSymbolAddress((void**)&Qh, g_Qh);
    cudaGetSymbolAddress((void**)&Kh, g_Kh);
    cudaGetSymbolAddress((void**)&Vh, g_Vh);
    cudaGetSymbolAddress((void**)&Oh, g_Oh);
    cudaGetSymbolAddress((void**)&WTH, g_WTH);
    cudaGetSymbolAddress((void**)&INH, g_INH);

    static bool attr_set = false;
    if (!attr_set) {
        cudaFuncSetAttribute(attn_mma,
                             cudaFuncAttributeMaxDynamicSharedMemorySize, SMEM_ATT);
        cudaFuncSetAttribute(gemm_qkv,
                             cudaFuncAttributeMaxDynamicSharedMemorySize, SMEM_GEMMH);
        cudaFuncSetAttribute(gemm_out16,
                             cudaFuncAttributeMaxDynamicSharedMemorySize, SMEM_GEMMH);
        attr_set = true;
    }

    dim3 tgrid(DM / 32, DM / 32, 4), tblk(32, 8);
    transpose4<<<tgrid, tblk>>>(Wq, Wk, Wv, Wo, WTH);

    dim3 pgrid(1024, 1, 3);
    prep_inputs<<<pgrid, 256>>>(queries, keys, values, INH);

    dim3 qgrid(DM / GBN, MROWS / GBM, 3);
    gemm_qkv<<<qgrid, 256, SMEM_GEMMH>>>(INH, WTH, Qh, Kh, Vh);

    dim3 agrid(NQ / QROWS, NH, BATCH);
    attn_mma<<<agrid, 256, SMEM_ATT>>>(Qh, Kh, Vh, Oh);

    dim3 ogrid(DM / GBN, MROWS / GBM);
    gemm_out16<<<ogrid, 256, SMEM_GEMMH>>>(Oh, WTH + 3 * (size_t)DM * DM, bo, out);
}